// round 7
// baseline (speedup 1.0000x reference)
#include <cuda_runtime.h>
#include <math.h>
#include <stdint.h>

#define H 256
#define RREL 5
#define NSEG 6            // 5 relations + self-loop
#define M0_CONST 50000
#define M1_CONST 10000
#define E0_MAX 800000

// ---------------- scratch (device globals: allocation-free) ----------------
__device__ float g_A0[(size_t)NSEG * M0_CONST * H];
__device__ float g_A1[(size_t)NSEG * M1_CONST * H];
__device__ float g_H0[(size_t)M0_CONST * H];
__device__ float g_H1[(size_t)M1_CONST * H];
__device__ float g_Mh[(size_t)M1_CONST * H];
__device__ float g_Wt[(size_t)13 * H * H];    // [N,K] transposed, tf32-rounded
__device__ int   g_cnt[M0_CONST * RREL + 8];  // keyed by dst*5+rel
__device__ int   g_off[M0_CONST * RREL + 8];
__device__ int   g_cur[M0_CONST * RREL + 8];
__device__ int   g_eidx[E0_MAX];
__device__ float g_sum[H];
__device__ float g_sumsq[H];
__device__ float g_scale[H];
__device__ float g_shift[H];

// ---------------- helpers ----------------
__device__ __forceinline__ uint32_t f2tf32(float v) {
    uint32_t t;
    asm("cvt.rna.tf32.f32 %0, %1;" : "=r"(t) : "f"(v));
    return t;
}
__device__ __forceinline__ float rtf(float v) { return __uint_as_float(f2tf32(v)); }

__device__ __forceinline__ void cp16(uint32_t dst, const float* src, int sz) {
    asm volatile("cp.async.cg.shared.global [%0], [%1], 16, %2;"
                 :: "r"(dst), "l"(src), "r"(sz));
}

// ---------------- CSR build (keyed by dst*5 + rel) ----------------
__global__ void hist_kernel(const int* __restrict__ dst, const int* __restrict__ et,
                            int E, int* __restrict__ cnt) {
    int e = blockIdx.x * 256 + threadIdx.x;
    if (e < E) atomicAdd(&cnt[dst[e] * RREL + et[e]], 1);
}

__global__ void scan_kernel(const int* __restrict__ cnt, int* __restrict__ off,
                            int* __restrict__ cur, int n) {
    __shared__ int part[1024];
    int t = threadIdx.x;
    int chunk = (n + 1023) >> 10;
    int a = t * chunk;
    int b = min(a + chunk, n);
    int s = 0;
    for (int i = a; i < b; i++) s += cnt[i];
    part[t] = s;
    __syncthreads();
    for (int d = 1; d < 1024; d <<= 1) {
        int v = (t >= d) ? part[t - d] : 0;
        __syncthreads();
        part[t] += v;
        __syncthreads();
    }
    int run = (t == 0) ? 0 : part[t - 1];
    for (int i = a; i < b; i++) { off[i] = run; cur[i] = run; run += cnt[i]; }
    if (b == n) off[n] = run;
}

__global__ void scatter_kernel(const int* __restrict__ src, const int* __restrict__ dst,
                               const int* __restrict__ et, int E,
                               int* __restrict__ cur, int* __restrict__ eidx) {
    int e = blockIdx.x * 256 + threadIdx.x;
    if (e < E) {
        int p = atomicAdd(&cur[dst[e] * RREL + et[e]], 1);
        eidx[p] = src[e];
    }
}

// One block (256 thr) per dst node. Edge list is relation-sorted, so each
// relation is one predication-free accumulation run. Writes 6 relation rows
// (self-loop = relation 5), tf32-rounded. Re-zeros cnt for the next replay.
__global__ void gather_kernel(const float* __restrict__ x, const int* __restrict__ eidx,
                              const int* __restrict__ off, int* __restrict__ cnt,
                              float* __restrict__ A, int ndst) {
    int d = blockIdx.x;
    int t = threadIdx.x;
    size_t base = (size_t)d * H + t;
    size_t seg = (size_t)ndst * H;
#pragma unroll
    for (int r = 0; r < RREL; r++) {
        int beg = off[d * RREL + r], end = off[d * RREL + r + 1];
        float a = 0.f;
        for (int i = beg; i < end; i++)
            a += x[(size_t)eidx[i] * H + t];
        A[base + (size_t)r * seg] = rtf(a);
    }
    A[base + 5 * seg] = rtf(x[base]);
    if (t < RREL) cnt[d * RREL + t] = 0;
}

// ---------------- weight transpose (one-shot per launch, tf32-rounded) ----
__global__ void transpose_weights(const float* W0, const float* Wl0,
                                  const float* W1, const float* Wl1,
                                  const float* Wm1) {
    __shared__ float t[32][33];
    int m = blockIdx.x;
    const float* src = (m < 5)   ? W0 + (size_t)m * H * H
                     : (m == 5)  ? Wl0
                     : (m < 11)  ? W1 + (size_t)(m - 6) * H * H
                     : (m == 11) ? Wl1 : Wm1;
    float* dst = g_Wt + (size_t)m * H * H;
    int bx = blockIdx.y * 32, by = blockIdx.z * 32;
    int x = threadIdx.x, y = threadIdx.y;
#pragma unroll
    for (int i = 0; i < 32; i += 8)
        t[y + i][x] = src[(size_t)(by + y + i) * H + bx + x];
    __syncthreads();
#pragma unroll
    for (int i = 0; i < 32; i += 8)
        dst[(size_t)(bx + y + i) * H + by + x] = rtf(t[x][y + i]);
}

// ---------------- tf32 tensor GEMM: cp.async + ldmatrix + fused BN stats ---
struct TGArgs {
    const float* A; long aseg;   // segment stride in floats
    const float* W;              // base of nseg [256,256] transposed matrices
    int nseg; int M;
    const float* bias;
    float* C;
    int do_stats;                // accumulate column sum/sumsq into g_sum/g_sumsq
};

#define PAD 36
#define ABYTES (128 * PAD * 4)    // 18432 bytes per tile buffer
#define TG_SMEM (4 * ABYTES)      // A0,A1,B0,B1 = 73728

__global__ void __launch_bounds__(256, 2) gemm_tc(TGArgs g) {
    extern __shared__ float smf[];
    uint32_t sbase;
    asm("{ .reg .u64 t; cvta.to.shared.u64 t, %1; cvt.u32.u64 %0, t; }"
        : "=r"(sbase) : "l"(smf));
    int tid = threadIdx.x;
    int warp = tid >> 5, lane = tid & 31;
    int wm = warp & 3, wn = warp >> 2;
    int m0 = blockIdx.x * 128, n0 = blockIdx.y * 128;
    int lrow = tid >> 1, lkh = (tid & 1) * 16;
    int arow_g = m0 + lrow;
    int asz = (arow_g < g.M) ? 16 : 0;
    int arow_c = (arow_g < g.M) ? arow_g : 0;

    float acc[2][8][4];
#pragma unroll
    for (int i = 0; i < 2; i++)
#pragma unroll
        for (int j = 0; j < 8; j++)
#pragma unroll
            for (int k = 0; k < 4; k++) acc[i][j][k] = 0.f;

    int nk = g.nseg * 8;

#define ISSUE(s_, b_)                                                          \
    {                                                                          \
        int seg_ = (s_) >> 3, koff_ = ((s_) & 7) * 32;                         \
        const float* as_ = g.A + (size_t)seg_ * g.aseg +                       \
                           (size_t)arow_c * H + koff_ + lkh;                   \
        uint32_t ad_ = sbase + (b_) * ABYTES + (lrow * PAD + lkh) * 4;         \
        cp16(ad_, as_, asz);                                                   \
        cp16(ad_ + 16, as_ + 4, asz);                                          \
        cp16(ad_ + 32, as_ + 8, asz);                                          \
        cp16(ad_ + 48, as_ + 12, asz);                                         \
        const float* bs_ = g.W + (size_t)seg_ * (H * H) +                      \
                           (size_t)(n0 + lrow) * H + koff_ + lkh;              \
        uint32_t bd_ = sbase + 2 * ABYTES + (b_) * ABYTES +                    \
                       (lrow * PAD + lkh) * 4;                                 \
        cp16(bd_, bs_, 16);                                                    \
        cp16(bd_ + 16, bs_ + 4, 16);                                           \
        cp16(bd_ + 32, bs_ + 8, 16);                                           \
        cp16(bd_ + 48, bs_ + 12, 16);                                          \
        asm volatile("cp.async.commit_group;");                                \
    }

    ISSUE(0, 0);

    int rowl = lane & 15;
    int khalf = (lane >> 4) * 4;

    for (int s = 0; s < nk; s++) {
        int buf = s & 1;
        if (s + 1 < nk) {
            ISSUE(s + 1, buf ^ 1);
            asm volatile("cp.async.wait_group 1;");
        } else {
            asm volatile("cp.async.wait_group 0;");
        }
        __syncthreads();

        uint32_t ab = sbase + buf * ABYTES;
        uint32_t bb = sbase + 2 * ABYTES + buf * ABYTES;
#pragma unroll
        for (int ks = 0; ks < 4; ks++) {
            int q = ks * 8 + khalf;
            uint32_t a[2][4], b[4][4];
#pragma unroll
            for (int im = 0; im < 2; im++) {
                uint32_t ad = ab + ((wm * 32 + im * 16 + rowl) * PAD + q) * 4;
                asm volatile(
                    "ldmatrix.sync.aligned.m8n8.x4.shared.b16 {%0,%1,%2,%3}, [%4];"
                    : "=r"(a[im][0]), "=r"(a[im][1]), "=r"(a[im][2]), "=r"(a[im][3])
                    : "r"(ad));
            }
#pragma unroll
            for (int i2 = 0; i2 < 4; i2++) {
                uint32_t bd = bb + ((wn * 64 + i2 * 16 + rowl) * PAD + q) * 4;
                asm volatile(
                    "ldmatrix.sync.aligned.m8n8.x4.shared.b16 {%0,%1,%2,%3}, [%4];"
                    : "=r"(b[i2][0]), "=r"(b[i2][1]), "=r"(b[i2][2]), "=r"(b[i2][3])
                    : "r"(bd));
            }
#pragma unroll
            for (int im = 0; im < 2; im++)
#pragma unroll
                for (int in_ = 0; in_ < 8; in_++) {
                    int i2 = in_ >> 1, p = in_ & 1;
                    asm volatile(
                        "mma.sync.aligned.m16n8k8.row.col.f32.tf32.tf32.f32 "
                        "{%0,%1,%2,%3}, {%4,%5,%6,%7}, {%8,%9}, {%0,%1,%2,%3};\n"
                        : "+f"(acc[im][in_][0]), "+f"(acc[im][in_][1]),
                          "+f"(acc[im][in_][2]), "+f"(acc[im][in_][3])
                        : "r"(a[im][0]), "r"(a[im][1]), "r"(a[im][2]), "r"(a[im][3]),
                          "r"(b[i2][p]), "r"(b[i2][2 + p]));
                }
        }
        __syncthreads();
    }

    // ---- epilogue: bias + store + fused BN column stats ----
    int lr = lane >> 2, lc = lane & 3;
#pragma unroll
    for (int in_ = 0; in_ < 8; in_++) {
        int col0 = n0 + wn * 64 + in_ * 8 + lc * 2;
        float bia0 = g.bias[col0];
        float bia1 = g.bias[col0 + 1];
        float s0 = 0.f, q0 = 0.f, s1 = 0.f, q1 = 0.f;
#pragma unroll
        for (int im = 0; im < 2; im++) {
            int row0 = m0 + wm * 32 + im * 16 + lr;
            if (row0 < g.M) {
                float v0 = acc[im][in_][0] + bia0;
                float v1 = acc[im][in_][1] + bia1;
                *(float2*)(g.C + (size_t)row0 * H + col0) = make_float2(v0, v1);
                s0 += v0; q0 += v0 * v0; s1 += v1; q1 += v1 * v1;
            }
            if (row0 + 8 < g.M) {
                float v2 = acc[im][in_][2] + bia0;
                float v3 = acc[im][in_][3] + bia1;
                *(float2*)(g.C + (size_t)(row0 + 8) * H + col0) = make_float2(v2, v3);
                s0 += v2; q0 += v2 * v2; s1 += v3; q1 += v3 * v3;
            }
        }
        if (g.do_stats) {
            atomicAdd(&g_sum[col0], s0);
            atomicAdd(&g_sumsq[col0], q0);
            atomicAdd(&g_sum[col0 + 1], s1);
            atomicAdd(&g_sumsq[col0 + 1], q1);
        }
    }
}

// ---------------- SIMT GEMM (final 256x153 only) ----------------
struct GemmArgs {
    const float* A;
    const float* W;
    int M, N;
    const float* bias;
    float* C;
};

__global__ void gemm_kernel(GemmArgs g) {
    __shared__ float As[16][65];
    __shared__ float Bs[16][64];

    int tid = threadIdx.x;
    int m0 = blockIdx.x * 64;
    int n0 = blockIdx.y * 64;
    int tm = tid >> 4;
    int tn = tid & 15;

    int lrow = tid >> 2;
    int lk4 = (tid & 3) << 2;
    int lkb = tid >> 4;
    int ln4 = (tid & 15) << 2;

    float acc[4][4];
#pragma unroll
    for (int i = 0; i < 4; i++)
#pragma unroll
        for (int j = 0; j < 4; j++) acc[i][j] = 0.f;

    for (int k0 = 0; k0 < H; k0 += 16) {
        float4 av = make_float4(0.f, 0.f, 0.f, 0.f);
        if (m0 + lrow < g.M)
            av = *(const float4*)(g.A + (size_t)(m0 + lrow) * H + k0 + lk4);
        As[lk4 + 0][lrow] = av.x;
        As[lk4 + 1][lrow] = av.y;
        As[lk4 + 2][lrow] = av.z;
        As[lk4 + 3][lrow] = av.w;
        const float* wp = g.W + (size_t)(k0 + lkb) * g.N + n0 + ln4;
        float4 bv;
        bv.x = (n0 + ln4 + 0 < g.N) ? wp[0] : 0.f;
        bv.y = (n0 + ln4 + 1 < g.N) ? wp[1] : 0.f;
        bv.z = (n0 + ln4 + 2 < g.N) ? wp[2] : 0.f;
        bv.w = (n0 + ln4 + 3 < g.N) ? wp[3] : 0.f;
        *(float4*)&Bs[lkb][ln4] = bv;
        __syncthreads();
#pragma unroll
        for (int kk = 0; kk < 16; kk++) {
            float a0 = As[kk][tm * 4 + 0];
            float a1 = As[kk][tm * 4 + 1];
            float a2 = As[kk][tm * 4 + 2];
            float a3 = As[kk][tm * 4 + 3];
            float4 b = *(const float4*)&Bs[kk][tn * 4];
            acc[0][0] += a0 * b.x; acc[0][1] += a0 * b.y; acc[0][2] += a0 * b.z; acc[0][3] += a0 * b.w;
            acc[1][0] += a1 * b.x; acc[1][1] += a1 * b.y; acc[1][2] += a1 * b.z; acc[1][3] += a1 * b.w;
            acc[2][0] += a2 * b.x; acc[2][1] += a2 * b.y; acc[2][2] += a2 * b.z; acc[2][3] += a2 * b.w;
            acc[3][0] += a3 * b.x; acc[3][1] += a3 * b.y; acc[3][2] += a3 * b.z; acc[3][3] += a3 * b.w;
        }
        __syncthreads();
    }

#pragma unroll
    for (int i = 0; i < 4; i++) {
        int m = m0 + tm * 4 + i;
        if (m >= g.M) continue;
#pragma unroll
        for (int j = 0; j < 4; j++) {
            int n = n0 + tn * 4 + j;
            if (n < g.N) g.C[(size_t)m * g.N + n] = acc[i][j] + g.bias[n];
        }
    }
}

// ---------------- BN kernels ----------------
__global__ void zero_stats_kernel() {
    g_sum[threadIdx.x] = 0.f;
    g_sumsq[threadIdx.x] = 0.f;
}

__global__ void bn_finalize_kernel(const float* __restrict__ gamma,
                                   const float* __restrict__ beta, float invM) {
    int col = threadIdx.x;
    float mean = g_sum[col] * invM;
    float var = g_sumsq[col] * invM - mean * mean;
    float sc = gamma[col] * rsqrtf(var + 1e-5f);
    g_scale[col] = sc;
    g_shift[col] = beta[col] - mean * sc;
}

// act 0 = ELU, 1 = ReLU; rnd -> round output to tf32 (for tensor-GEMM consumers)
__global__ void bn_apply_kernel(float* __restrict__ h, int M, int act, int rnd) {
    long i = (long)blockIdx.x * blockDim.x + threadIdx.x;
    if (i >= (long)M * H) return;
    int col = (int)(i & (H - 1));
    float v = h[i] * g_scale[col] + g_shift[col];
    if (act == 0)
        v = (v > 0.f) ? v : expm1f(v);
    else
        v = (v > 0.f) ? v : 0.f;
    if (rnd) v = rtf(v);
    h[i] = v;
}

// ---------------- host orchestration ----------------
static inline int cdiv(long a, long b) { return (int)((a + b - 1) / b); }

extern "C" void kernel_launch(void* const* d_in, const int* in_sizes, int n_in,
                              void* d_out, int out_size) {
    const float* x   = (const float*)d_in[0];
    const int* src0  = (const int*)d_in[1];
    const int* dst0  = (const int*)d_in[2];
    const int* et0   = (const int*)d_in[3];
    const int* src1  = (const int*)d_in[4];
    const int* dst1  = (const int*)d_in[5];
    const int* et1   = (const int*)d_in[6];
    const float* W0  = (const float*)d_in[9];
    const float* Wl0 = (const float*)d_in[10];
    const float* b0  = (const float*)d_in[11];
    const float* g0  = (const float*)d_in[12];
    const float* be0 = (const float*)d_in[13];
    const float* W1  = (const float*)d_in[14];
    const float* Wl1 = (const float*)d_in[15];
    const float* b1  = (const float*)d_in[16];
    const float* g1  = (const float*)d_in[17];
    const float* be1 = (const float*)d_in[18];
    const float* Wm1 = (const float*)d_in[19];
    const float* bm1 = (const float*)d_in[20];
    const float* gm  = (const float*)d_in[21];
    const float* bem = (const float*)d_in[22];
    const float* Wm2 = (const float*)d_in[23];
    const float* bm2 = (const float*)d_in[24];
    float* out = (float*)d_out;

    const int E0 = in_sizes[1];
    const int E1 = in_sizes[4];
    const int COUT = 153;
    const int M1 = out_size / COUT;   // 10000
    const int M0 = M0_CONST;          // 50000

    float *A0, *A1, *H0, *H1, *Mh, *Wt;
    int *cnt, *off, *cur, *eidx;
    cudaGetSymbolAddress((void**)&A0, g_A0);
    cudaGetSymbolAddress((void**)&A1, g_A1);
    cudaGetSymbolAddress((void**)&H0, g_H0);
    cudaGetSymbolAddress((void**)&H1, g_H1);
    cudaGetSymbolAddress((void**)&Mh, g_Mh);
    cudaGetSymbolAddress((void**)&Wt, g_Wt);
    cudaGetSymbolAddress((void**)&cnt, g_cnt);
    cudaGetSymbolAddress((void**)&off, g_off);
    cudaGetSymbolAddress((void**)&cur, g_cur);
    cudaGetSymbolAddress((void**)&eidx, g_eidx);

    cudaFuncSetAttribute(gemm_tc,
                         cudaFuncAttributeMaxDynamicSharedMemorySize, TG_SMEM);

    // ---- layer 0: CSR (dst,rel)-keyed + gather + GEMM w/ fused stats ----
    hist_kernel<<<cdiv(E0, 256), 256>>>(dst0, et0, E0, cnt);                // 0
    scan_kernel<<<1, 1024>>>(cnt, off, cur, M0 * RREL);                     // 1
    scatter_kernel<<<cdiv(E0, 256), 256>>>(src0, dst0, et0, E0, cur, eidx); // 2
    gather_kernel<<<M0, 256>>>(x, eidx, off, cnt, A0, M0);                  // 3 <- profiled
    transpose_weights<<<dim3(13, 8, 8), dim3(32, 8)>>>(W0, Wl0, W1, Wl1, Wm1);
    zero_stats_kernel<<<1, H>>>();

    TGArgs ga;
    ga.A = A0;  ga.aseg = (long)M0 * H;
    ga.W = Wt;  ga.nseg = NSEG;  ga.M = M0;  ga.bias = b0;  ga.C = H0;
    ga.do_stats = 1;
    gemm_tc<<<dim3(cdiv(M0, 128), 2), 256, TG_SMEM>>>(ga);

    bn_finalize_kernel<<<1, H>>>(g0, be0, 1.0f / M0);
    bn_apply_kernel<<<cdiv((long)M0 * H, 256), 256>>>(H0, M0, 0, 1);

    // ---- layer 1 ----
    hist_kernel<<<cdiv(E1, 256), 256>>>(dst1, et1, E1, cnt);
    scan_kernel<<<1, 1024>>>(cnt, off, cur, M1 * RREL);
    scatter_kernel<<<cdiv(E1, 256), 256>>>(src1, dst1, et1, E1, cur, eidx);
    gather_kernel<<<M1, 256>>>(H0, eidx, off, cnt, A1, M1);
    zero_stats_kernel<<<1, H>>>();

    ga.A = A1;  ga.aseg = (long)M1 * H;
    ga.W = Wt + (size_t)6 * H * H;
    ga.nseg = NSEG;  ga.M = M1;  ga.bias = b1;  ga.C = H1;
    ga.do_stats = 1;
    gemm_tc<<<dim3(cdiv(M1, 128), 2), 256, TG_SMEM>>>(ga);

    bn_finalize_kernel<<<1, H>>>(g1, be1, 1.0f / M1);
    bn_apply_kernel<<<cdiv((long)M1 * H, 256), 256>>>(H1, M1, 0, 1);

    // ---- MLP head ----
    zero_stats_kernel<<<1, H>>>();
    ga.A = H1;  ga.aseg = 0;
    ga.W = Wt + (size_t)12 * H * H;
    ga.nseg = 1;  ga.M = M1;  ga.bias = bm1;  ga.C = Mh;
    ga.do_stats = 1;
    gemm_tc<<<dim3(cdiv(M1, 128), 2), 256, TG_SMEM>>>(ga);

    bn_finalize_kernel<<<1, H>>>(gm, bem, 1.0f / M1);
    bn_apply_kernel<<<cdiv((long)M1 * H, 256), 256>>>(Mh, M1, 1, 0);

    GemmArgs gf;
    gf.A = Mh;  gf.W = Wm2;
    gf.M = M1;  gf.N = COUT;  gf.bias = bm2;  gf.C = out;
    gemm_kernel<<<dim3(cdiv(M1, 64), cdiv(COUT, 64)), 256>>>(gf);
}

// round 8
// speedup vs baseline: 1.6806x; 1.6806x over previous
#include <cuda_runtime.h>
#include <math.h>
#include <stdint.h>

#define H 256
#define RREL 5
#define NSEG 6            // 5 relations + self-loop
#define M0_CONST 50000
#define M1_CONST 10000
#define E0_MAX 800000

// ---------------- scratch (device globals: allocation-free) ----------------
__device__ float g_A0[(size_t)NSEG * M0_CONST * H];
__device__ float g_A1[(size_t)NSEG * M1_CONST * H];
__device__ float g_H0[(size_t)M0_CONST * H];
__device__ float g_H1[(size_t)M1_CONST * H];
__device__ float g_Mh[(size_t)M1_CONST * H];
__device__ float g_Wt[(size_t)13 * H * H];    // [N,K] transposed, tf32-rounded
__device__ int   g_cnt[M0_CONST + 4];
__device__ int   g_off[M0_CONST + 4];
__device__ int   g_cur[M0_CONST + 4];
__device__ int   g_eidx[E0_MAX];
__device__ float g_sum[H];
__device__ float g_sumsq[H];
__device__ float g_scale[H];
__device__ float g_shift[H];

// ---------------- helpers ----------------
__device__ __forceinline__ uint32_t f2tf32(float v) {
    uint32_t t;
    asm("cvt.rna.tf32.f32 %0, %1;" : "=r"(t) : "f"(v));
    return t;
}
__device__ __forceinline__ float rtf(float v) { return __uint_as_float(f2tf32(v)); }

__device__ __forceinline__ void cp16(uint32_t dst, const float* src, int sz) {
    asm volatile("cp.async.cg.shared.global [%0], [%1], 16, %2;"
                 :: "r"(dst), "l"(src), "r"(sz));
}

// ---------------- CSR build (dst-keyed, relation packed into eidx) --------
__global__ void hist_kernel(const int* __restrict__ dst, int E, int* __restrict__ cnt) {
    int e = blockIdx.x * 256 + threadIdx.x;
    if (e < E) atomicAdd(&cnt[dst[e]], 1);
}

__global__ void scan_kernel(const int* __restrict__ cnt, int* __restrict__ off,
                            int* __restrict__ cur, int n) {
    __shared__ int part[1024];
    int t = threadIdx.x;
    int chunk = (n + 1023) >> 10;
    int a = t * chunk;
    int b = min(a + chunk, n);
    int s = 0;
    for (int i = a; i < b; i++) s += cnt[i];
    part[t] = s;
    __syncthreads();
    for (int d = 1; d < 1024; d <<= 1) {
        int v = (t >= d) ? part[t - d] : 0;
        __syncthreads();
        part[t] += v;
        __syncthreads();
    }
    int run = (t == 0) ? 0 : part[t - 1];
    for (int i = a; i < b; i++) { off[i] = run; cur[i] = run; run += cnt[i]; }
    if (b == n) off[n] = run;
}

__global__ void scatter_kernel(const int* __restrict__ src, const int* __restrict__ dst,
                               const int* __restrict__ et, int E,
                               int* __restrict__ cur, int* __restrict__ eidx) {
    int e = blockIdx.x * 256 + threadIdx.x;
    if (e < E) {
        int p = atomicAdd(&cur[dst[e]], 1);
        eidx[p] = (et[e] << 24) | src[e];
    }
}

// One block (64 thr) per dst node; thread t owns channels [4t, 4t+4).
// 5 float4 accumulators with predicated adds; one independent LDG.128 per
// edge per thread keeps MLP high. Writes 6 relation rows (self-loop = 5),
// tf32-rounded. Re-zeros cnt for the next graph replay.
__global__ void gather_kernel(const float* __restrict__ x, const int* __restrict__ eidx,
                              const int* __restrict__ off, int* __restrict__ cnt,
                              float* __restrict__ A, int ndst) {
    int d = blockIdx.x;
    int t = threadIdx.x;          // 0..63
    int c = t * 4;
    int beg = off[d], end = off[d + 1];
    float4 a0 = make_float4(0.f, 0.f, 0.f, 0.f);
    float4 a1 = a0, a2 = a0, a3 = a0, a4 = a0;
    for (int i = beg; i < end; i++) {
        int pk = eidx[i];
        float4 v = *(const float4*)(x + (size_t)(pk & 0xFFFFFF) * H + c);
        int r = pk >> 24;
        if (r == 0) { a0.x += v.x; a0.y += v.y; a0.z += v.z; a0.w += v.w; }
        if (r == 1) { a1.x += v.x; a1.y += v.y; a1.z += v.z; a1.w += v.w; }
        if (r == 2) { a2.x += v.x; a2.y += v.y; a2.z += v.z; a2.w += v.w; }
        if (r == 3) { a3.x += v.x; a3.y += v.y; a3.z += v.z; a3.w += v.w; }
        if (r == 4) { a4.x += v.x; a4.y += v.y; a4.z += v.z; a4.w += v.w; }
    }
    size_t base = (size_t)d * H + c;
    size_t seg = (size_t)ndst * H;
#define RSTORE(k, av)                                                          \
    {                                                                          \
        float4 o;                                                              \
        o.x = rtf((av).x); o.y = rtf((av).y);                                  \
        o.z = rtf((av).z); o.w = rtf((av).w);                                  \
        *(float4*)(A + base + (size_t)(k) * seg) = o;                          \
    }
    RSTORE(0, a0); RSTORE(1, a1); RSTORE(2, a2); RSTORE(3, a3); RSTORE(4, a4);
    float4 sv = *(const float4*)(x + base);
    RSTORE(5, sv);
    if (t == 0) cnt[d] = 0;
}

// ---------------- weight transpose (one-shot per launch, tf32-rounded) ----
__global__ void transpose_weights(const float* W0, const float* Wl0,
                                  const float* W1, const float* Wl1,
                                  const float* Wm1) {
    __shared__ float t[32][33];
    int m = blockIdx.x;
    const float* src = (m < 5)   ? W0 + (size_t)m * H * H
                     : (m == 5)  ? Wl0
                     : (m < 11)  ? W1 + (size_t)(m - 6) * H * H
                     : (m == 11) ? Wl1 : Wm1;
    float* dst = g_Wt + (size_t)m * H * H;
    int bx = blockIdx.y * 32, by = blockIdx.z * 32;
    int x = threadIdx.x, y = threadIdx.y;
#pragma unroll
    for (int i = 0; i < 32; i += 8)
        t[y + i][x] = src[(size_t)(by + y + i) * H + bx + x];
    __syncthreads();
#pragma unroll
    for (int i = 0; i < 32; i += 8)
        dst[(size_t)(bx + y + i) * H + by + x] = rtf(t[x][y + i]);
}

// ---------------- tf32 tensor GEMM: cp.async + ldmatrix ----------------
struct TGArgs {
    const float* A; long aseg;   // segment stride in floats
    const float* W;              // base of nseg [256,256] transposed matrices
    int nseg; int M;
    const float* bias;
    float* C;
};

#define PAD 36
#define ABYTES (128 * PAD * 4)    // 18432 bytes per tile buffer
#define TG_SMEM (4 * ABYTES)      // A0,A1,B0,B1 = 73728

__global__ void __launch_bounds__(256, 2) gemm_tc(TGArgs g) {
    extern __shared__ float smf[];
    uint32_t sbase;
    asm("{ .reg .u64 t; cvta.to.shared.u64 t, %1; cvt.u32.u64 %0, t; }"
        : "=r"(sbase) : "l"(smf));
    int tid = threadIdx.x;
    int warp = tid >> 5, lane = tid & 31;
    int wm = warp & 3, wn = warp >> 2;
    int m0 = blockIdx.x * 128, n0 = blockIdx.y * 128;
    int lrow = tid >> 1, lkh = (tid & 1) * 16;
    int arow_g = m0 + lrow;
    int asz = (arow_g < g.M) ? 16 : 0;
    int arow_c = (arow_g < g.M) ? arow_g : 0;

    float acc[2][8][4];
#pragma unroll
    for (int i = 0; i < 2; i++)
#pragma unroll
        for (int j = 0; j < 8; j++)
#pragma unroll
            for (int k = 0; k < 4; k++) acc[i][j][k] = 0.f;

    int nk = g.nseg * 8;

#define ISSUE(s_, b_)                                                          \
    {                                                                          \
        int seg_ = (s_) >> 3, koff_ = ((s_) & 7) * 32;                         \
        const float* as_ = g.A + (size_t)seg_ * g.aseg +                       \
                           (size_t)arow_c * H + koff_ + lkh;                   \
        uint32_t ad_ = sbase + (b_) * ABYTES + (lrow * PAD + lkh) * 4;         \
        cp16(ad_, as_, asz);                                                   \
        cp16(ad_ + 16, as_ + 4, asz);                                          \
        cp16(ad_ + 32, as_ + 8, asz);                                          \
        cp16(ad_ + 48, as_ + 12, asz);                                         \
        const float* bs_ = g.W + (size_t)seg_ * (H * H) +                      \
                           (size_t)(n0 + lrow) * H + koff_ + lkh;              \
        uint32_t bd_ = sbase + 2 * ABYTES + (b_) * ABYTES +                    \
                       (lrow * PAD + lkh) * 4;                                 \
        cp16(bd_, bs_, 16);                                                    \
        cp16(bd_ + 16, bs_ + 4, 16);                                           \
        cp16(bd_ + 32, bs_ + 8, 16);                                           \
        cp16(bd_ + 48, bs_ + 12, 16);                                          \
        asm volatile("cp.async.commit_group;");                                \
    }

    ISSUE(0, 0);

    int rowl = lane & 15;
    int khalf = (lane >> 4) * 4;

    for (int s = 0; s < nk; s++) {
        int buf = s & 1;
        if (s + 1 < nk) {
            ISSUE(s + 1, buf ^ 1);
            asm volatile("cp.async.wait_group 1;");
        } else {
            asm volatile("cp.async.wait_group 0;");
        }
        __syncthreads();

        uint32_t ab = sbase + buf * ABYTES;
        uint32_t bb = sbase + 2 * ABYTES + buf * ABYTES;
#pragma unroll
        for (int ks = 0; ks < 4; ks++) {
            int q = ks * 8 + khalf;
            uint32_t a[2][4], b[4][4];
#pragma unroll
            for (int im = 0; im < 2; im++) {
                uint32_t ad = ab + ((wm * 32 + im * 16 + rowl) * PAD + q) * 4;
                asm volatile(
                    "ldmatrix.sync.aligned.m8n8.x4.shared.b16 {%0,%1,%2,%3}, [%4];"
                    : "=r"(a[im][0]), "=r"(a[im][1]), "=r"(a[im][2]), "=r"(a[im][3])
                    : "r"(ad));
            }
#pragma unroll
            for (int i2 = 0; i2 < 4; i2++) {
                uint32_t bd = bb + ((wn * 64 + i2 * 16 + rowl) * PAD + q) * 4;
                asm volatile(
                    "ldmatrix.sync.aligned.m8n8.x4.shared.b16 {%0,%1,%2,%3}, [%4];"
                    : "=r"(b[i2][0]), "=r"(b[i2][1]), "=r"(b[i2][2]), "=r"(b[i2][3])
                    : "r"(bd));
            }
#pragma unroll
            for (int im = 0; im < 2; im++)
#pragma unroll
                for (int in_ = 0; in_ < 8; in_++) {
                    int i2 = in_ >> 1, p = in_ & 1;
                    asm volatile(
                        "mma.sync.aligned.m16n8k8.row.col.f32.tf32.tf32.f32 "
                        "{%0,%1,%2,%3}, {%4,%5,%6,%7}, {%8,%9}, {%0,%1,%2,%3};\n"
                        : "+f"(acc[im][in_][0]), "+f"(acc[im][in_][1]),
                          "+f"(acc[im][in_][2]), "+f"(acc[im][in_][3])
                        : "r"(a[im][0]), "r"(a[im][1]), "r"(a[im][2]), "r"(a[im][3]),
                          "r"(b[i2][p]), "r"(b[i2][2 + p]));
                }
        }
        __syncthreads();
    }

    // ---- epilogue: bias + store ----
    int lr = lane >> 2, lc = lane & 3;
#pragma unroll
    for (int im = 0; im < 2; im++) {
        int row0 = m0 + wm * 32 + im * 16 + lr;
#pragma unroll
        for (int in_ = 0; in_ < 8; in_++) {
            int col0 = n0 + wn * 64 + in_ * 8 + lc * 2;
            float bia0 = g.bias[col0];
            float bia1 = g.bias[col0 + 1];
            if (row0 < g.M) {
                float2 v = make_float2(acc[im][in_][0] + bia0,
                                       acc[im][in_][1] + bia1);
                *(float2*)(g.C + (size_t)row0 * H + col0) = v;
            }
            if (row0 + 8 < g.M) {
                float2 v = make_float2(acc[im][in_][2] + bia0,
                                       acc[im][in_][3] + bia1);
                *(float2*)(g.C + (size_t)(row0 + 8) * H + col0) = v;
            }
        }
    }
}

// ---------------- SIMT GEMM (final 256x153 only) ----------------
struct GemmArgs {
    const float* A;
    const float* W;
    int M, N;
    const float* bias;
    float* C;
};

__global__ void gemm_kernel(GemmArgs g) {
    __shared__ float As[16][65];
    __shared__ float Bs[16][64];

    int tid = threadIdx.x;
    int m0 = blockIdx.x * 64;
    int n0 = blockIdx.y * 64;
    int tm = tid >> 4;
    int tn = tid & 15;

    int lrow = tid >> 2;
    int lk4 = (tid & 3) << 2;
    int lkb = tid >> 4;
    int ln4 = (tid & 15) << 2;

    float acc[4][4];
#pragma unroll
    for (int i = 0; i < 4; i++)
#pragma unroll
        for (int j = 0; j < 4; j++) acc[i][j] = 0.f;

    for (int k0 = 0; k0 < H; k0 += 16) {
        float4 av = make_float4(0.f, 0.f, 0.f, 0.f);
        if (m0 + lrow < g.M)
            av = *(const float4*)(g.A + (size_t)(m0 + lrow) * H + k0 + lk4);
        As[lk4 + 0][lrow] = av.x;
        As[lk4 + 1][lrow] = av.y;
        As[lk4 + 2][lrow] = av.z;
        As[lk4 + 3][lrow] = av.w;
        const float* wp = g.W + (size_t)(k0 + lkb) * g.N + n0 + ln4;
        float4 bv;
        bv.x = (n0 + ln4 + 0 < g.N) ? wp[0] : 0.f;
        bv.y = (n0 + ln4 + 1 < g.N) ? wp[1] : 0.f;
        bv.z = (n0 + ln4 + 2 < g.N) ? wp[2] : 0.f;
        bv.w = (n0 + ln4 + 3 < g.N) ? wp[3] : 0.f;
        *(float4*)&Bs[lkb][ln4] = bv;
        __syncthreads();
#pragma unroll
        for (int kk = 0; kk < 16; kk++) {
            float a0 = As[kk][tm * 4 + 0];
            float a1 = As[kk][tm * 4 + 1];
            float a2 = As[kk][tm * 4 + 2];
            float a3 = As[kk][tm * 4 + 3];
            float4 b = *(const float4*)&Bs[kk][tn * 4];
            acc[0][0] += a0 * b.x; acc[0][1] += a0 * b.y; acc[0][2] += a0 * b.z; acc[0][3] += a0 * b.w;
            acc[1][0] += a1 * b.x; acc[1][1] += a1 * b.y; acc[1][2] += a1 * b.z; acc[1][3] += a1 * b.w;
            acc[2][0] += a2 * b.x; acc[2][1] += a2 * b.y; acc[2][2] += a2 * b.z; acc[2][3] += a2 * b.w;
            acc[3][0] += a3 * b.x; acc[3][1] += a3 * b.y; acc[3][2] += a3 * b.z; acc[3][3] += a3 * b.w;
        }
        __syncthreads();
    }

#pragma unroll
    for (int i = 0; i < 4; i++) {
        int m = m0 + tm * 4 + i;
        if (m >= g.M) continue;
#pragma unroll
        for (int j = 0; j < 4; j++) {
            int n = n0 + tn * 4 + j;
            if (n < g.N) g.C[(size_t)m * g.N + n] = acc[i][j] + g.bias[n];
        }
    }
}

// ---------------- BN kernels ----------------
__global__ void zero_stats_kernel() {
    g_sum[threadIdx.x] = 0.f;
    g_sumsq[threadIdx.x] = 0.f;
}

__global__ void bn_stats_kernel(const float* __restrict__ h, int M) {
    int col = threadIdx.x;
    int r0 = blockIdx.x * 128;
    int rend = min(r0 + 128, M);
    float s = 0.f, s2 = 0.f;
    for (int r = r0; r < rend; r++) {
        float v = h[(size_t)r * H + col];
        s += v;
        s2 += v * v;
    }
    atomicAdd(&g_sum[col], s);
    atomicAdd(&g_sumsq[col], s2);
}

__global__ void bn_finalize_kernel(const float* __restrict__ gamma,
                                   const float* __restrict__ beta, float invM) {
    int col = threadIdx.x;
    float mean = g_sum[col] * invM;
    float var = g_sumsq[col] * invM - mean * mean;
    float sc = gamma[col] * rsqrtf(var + 1e-5f);
    g_scale[col] = sc;
    g_shift[col] = beta[col] - mean * sc;
}

// act 0 = ELU, 1 = ReLU; rnd -> round output to tf32 (for tensor-GEMM consumers)
__global__ void bn_apply_kernel(float* __restrict__ h, int M, int act, int rnd) {
    long i = (long)blockIdx.x * blockDim.x + threadIdx.x;
    if (i >= (long)M * H) return;
    int col = (int)(i & (H - 1));
    float v = h[i] * g_scale[col] + g_shift[col];
    if (act == 0)
        v = (v > 0.f) ? v : expm1f(v);
    else
        v = (v > 0.f) ? v : 0.f;
    if (rnd) v = rtf(v);
    h[i] = v;
}

// ---------------- host orchestration ----------------
static inline int cdiv(long a, long b) { return (int)((a + b - 1) / b); }

extern "C" void kernel_launch(void* const* d_in, const int* in_sizes, int n_in,
                              void* d_out, int out_size) {
    const float* x   = (const float*)d_in[0];
    const int* src0  = (const int*)d_in[1];
    const int* dst0  = (const int*)d_in[2];
    const int* et0   = (const int*)d_in[3];
    const int* src1  = (const int*)d_in[4];
    const int* dst1  = (const int*)d_in[5];
    const int* et1   = (const int*)d_in[6];
    const float* W0  = (const float*)d_in[9];
    const float* Wl0 = (const float*)d_in[10];
    const float* b0  = (const float*)d_in[11];
    const float* g0  = (const float*)d_in[12];
    const float* be0 = (const float*)d_in[13];
    const float* W1  = (const float*)d_in[14];
    const float* Wl1 = (const float*)d_in[15];
    const float* b1  = (const float*)d_in[16];
    const float* g1  = (const float*)d_in[17];
    const float* be1 = (const float*)d_in[18];
    const float* Wm1 = (const float*)d_in[19];
    const float* bm1 = (const float*)d_in[20];
    const float* gm  = (const float*)d_in[21];
    const float* bem = (const float*)d_in[22];
    const float* Wm2 = (const float*)d_in[23];
    const float* bm2 = (const float*)d_in[24];
    float* out = (float*)d_out;

    const int E0 = in_sizes[1];
    const int E1 = in_sizes[4];
    const int COUT = 153;
    const int M1 = out_size / COUT;   // 10000
    const int M0 = M0_CONST;          // 50000

    float *A0, *A1, *H0, *H1, *Mh, *Wt;
    int *cnt, *off, *cur, *eidx;
    cudaGetSymbolAddress((void**)&A0, g_A0);
    cudaGetSymbolAddress((void**)&A1, g_A1);
    cudaGetSymbolAddress((void**)&H0, g_H0);
    cudaGetSymbolAddress((void**)&H1, g_H1);
    cudaGetSymbolAddress((void**)&Mh, g_Mh);
    cudaGetSymbolAddress((void**)&Wt, g_Wt);
    cudaGetSymbolAddress((void**)&cnt, g_cnt);
    cudaGetSymbolAddress((void**)&off, g_off);
    cudaGetSymbolAddress((void**)&cur, g_cur);
    cudaGetSymbolAddress((void**)&eidx, g_eidx);

    cudaFuncSetAttribute(gemm_tc,
                         cudaFuncAttributeMaxDynamicSharedMemorySize, TG_SMEM);

    // ---- layer 0: CSR (dst-keyed) + float4 gather + GEMM ----
    hist_kernel<<<cdiv(E0, 256), 256>>>(dst0, E0, cnt);                     // 0
    scan_kernel<<<1, 1024>>>(cnt, off, cur, M0);                            // 1
    scatter_kernel<<<cdiv(E0, 256), 256>>>(src0, dst0, et0, E0, cur, eidx); // 2
    gather_kernel<<<M0, 64>>>(x, eidx, off, cnt, A0, M0);                   // 3 <- profiled
    transpose_weights<<<dim3(13, 8, 8), dim3(32, 8)>>>(W0, Wl0, W1, Wl1, Wm1);

    TGArgs ga;
    ga.A = A0;  ga.aseg = (long)M0 * H;
    ga.W = Wt;  ga.nseg = NSEG;  ga.M = M0;  ga.bias = b0;  ga.C = H0;
    gemm_tc<<<dim3(cdiv(M0, 128), 2), 256, TG_SMEM>>>(ga);

    zero_stats_kernel<<<1, H>>>();
    bn_stats_kernel<<<cdiv(M0, 128), H>>>(H0, M0);
    bn_finalize_kernel<<<1, H>>>(g0, be0, 1.0f / M0);
    bn_apply_kernel<<<cdiv((long)M0 * H, 256), 256>>>(H0, M0, 0, 1);

    // ---- layer 1 ----
    hist_kernel<<<cdiv(E1, 256), 256>>>(dst1, E1, cnt);
    scan_kernel<<<1, 1024>>>(cnt, off, cur, M1);
    scatter_kernel<<<cdiv(E1, 256), 256>>>(src1, dst1, et1, E1, cur, eidx);
    gather_kernel<<<M1, 64>>>(H0, eidx, off, cnt, A1, M1);

    ga.A = A1;  ga.aseg = (long)M1 * H;
    ga.W = Wt + (size_t)6 * H * H;
    ga.nseg = NSEG;  ga.M = M1;  ga.bias = b1;  ga.C = H1;
    gemm_tc<<<dim3(cdiv(M1, 128), 2), 256, TG_SMEM>>>(ga);

    zero_stats_kernel<<<1, H>>>();
    bn_stats_kernel<<<cdiv(M1, 128), H>>>(H1, M1);
    bn_finalize_kernel<<<1, H>>>(g1, be1, 1.0f / M1);
    bn_apply_kernel<<<cdiv((long)M1 * H, 256), 256>>>(H1, M1, 0, 1);

    // ---- MLP head ----
    ga.A = H1;  ga.aseg = 0;
    ga.W = Wt + (size_t)12 * H * H;
    ga.nseg = 1;  ga.M = M1;  ga.bias = bm1;  ga.C = Mh;
    gemm_tc<<<dim3(cdiv(M1, 128), 2), 256, TG_SMEM>>>(ga);

    zero_stats_kernel<<<1, H>>>();
    bn_stats_kernel<<<cdiv(M1, 128), H>>>(Mh, M1);
    bn_finalize_kernel<<<1, H>>>(gm, bem, 1.0f / M1);
    bn_apply_kernel<<<cdiv((long)M1 * H, 256), 256>>>(Mh, M1, 1, 0);

    GemmArgs gf;
    gf.A = Mh;  gf.W = Wm2;
    gf.M = M1;  gf.N = COUT;  gf.bias = bm2;  gf.C = out;
    gemm_kernel<<<dim3(cdiv(M1, 64), cdiv(COUT, 64)), 256>>>(gf);
}

// round 9
// speedup vs baseline: 1.8476x; 1.0994x over previous
#include <cuda_runtime.h>
#include <math.h>
#include <stdint.h>

#define H 256
#define RREL 5
#define NSEG 6            // 5 relations + self-loop
#define M0_CONST 50000
#define M1_CONST 10000
#define E0_MAX 800000
#define LDA 260           // padded row stride (floats); 1040B: 16B-aligned, bank-shift 16B/row

// ---------------- scratch (device globals: allocation-free) ----------------
// +128 rows of slack everywhere: bulk copies read full 128-row m-tiles.
__device__ float g_A0[((size_t)NSEG * M0_CONST + 128) * LDA];
__device__ float g_A1[((size_t)NSEG * M1_CONST + 128) * LDA];
__device__ float g_H0[((size_t)M0_CONST + 128) * LDA];
__device__ float g_H1[((size_t)M1_CONST + 128) * LDA];
__device__ float g_Mh[((size_t)M1_CONST + 128) * LDA];
__device__ float g_Wt[(size_t)13 * 256 * LDA];   // [mat][n][k] transposed, tf32-rounded
__device__ int   g_cnt[M0_CONST + 4];
__device__ int   g_off[M0_CONST + 4];
__device__ int   g_cur[M0_CONST + 4];
__device__ int   g_eidx[E0_MAX];
__device__ float g_sum[H];
__device__ float g_sumsq[H];
__device__ float g_scale[H];
__device__ float g_shift[H];

// ---------------- helpers ----------------
__device__ __forceinline__ uint32_t f2tf32(float v) {
    uint32_t t;
    asm("cvt.rna.tf32.f32 %0, %1;" : "=r"(t) : "f"(v));
    return t;
}
__device__ __forceinline__ float rtf(float v) { return __uint_as_float(f2tf32(v)); }

__device__ __forceinline__ uint32_t smem_u32(const void* p) {
    uint32_t a;
    asm("{ .reg .u64 t; cvta.to.shared.u64 t, %1; cvt.u32.u64 %0, t; }"
        : "=r"(a) : "l"(p));
    return a;
}

#define MBAR_INIT(addr, cnt)                                                   \
    asm volatile("mbarrier.init.shared.b64 [%0], %1;" :: "r"(addr), "r"(cnt) : "memory")

#define MBAR_EXPECT(addr, bytes)                                               \
    asm volatile("mbarrier.arrive.expect_tx.shared.b64 _, [%0], %1;"           \
                 :: "r"(addr), "r"(bytes) : "memory")

#define BULK_G2S(dst, src, bytes, mbar)                                        \
    asm volatile(                                                              \
        "cp.async.bulk.shared::cluster.global.mbarrier::complete_tx::bytes "   \
        "[%0], [%1], %2, [%3];"                                                \
        :: "r"(dst), "l"(src), "r"(bytes), "r"(mbar) : "memory")

__device__ __forceinline__ void mbar_wait(uint32_t mbar, uint32_t parity) {
    uint32_t done;
    asm volatile(
        "{\n\t.reg .pred p;\n\t"
        "mbarrier.try_wait.parity.acquire.cta.shared::cta.b64 p, [%1], %2;\n\t"
        "selp.b32 %0, 1, 0, p;\n\t}"
        : "=r"(done) : "r"(mbar), "r"(parity) : "memory");
    if (!done) {
        asm volatile(
            "{\n\t.reg .pred P1;\n\t"
            "W_%=:\n\t"
            "mbarrier.try_wait.parity.acquire.cta.shared::cta.b64 P1, [%0], %1, 0x989680;\n\t"
            "@P1 bra.uni D_%=;\n\t"
            "bra.uni W_%=;\n\t"
            "D_%=:\n\t}"
            :: "r"(mbar), "r"(parity) : "memory");
    }
}

// ---------------- CSR build (dst-keyed, relation packed into eidx) --------
__global__ void hist_kernel(const int* __restrict__ dst, int E, int* __restrict__ cnt) {
    int e = blockIdx.x * 256 + threadIdx.x;
    if (e < E) atomicAdd(&cnt[dst[e]], 1);
}

__global__ void scan_kernel(const int* __restrict__ cnt, int* __restrict__ off,
                            int* __restrict__ cur, int n) {
    __shared__ int part[1024];
    int t = threadIdx.x;
    int chunk = (n + 1023) >> 10;
    int a = t * chunk;
    int b = min(a + chunk, n);
    int s = 0;
    for (int i = a; i < b; i++) s += cnt[i];
    part[t] = s;
    __syncthreads();
    for (int d = 1; d < 1024; d <<= 1) {
        int v = (t >= d) ? part[t - d] : 0;
        __syncthreads();
        part[t] += v;
        __syncthreads();
    }
    int run = (t == 0) ? 0 : part[t - 1];
    for (int i = a; i < b; i++) { off[i] = run; cur[i] = run; run += cnt[i]; }
    if (b == n) off[n] = run;
}

__global__ void scatter_kernel(const int* __restrict__ src, const int* __restrict__ dst,
                               const int* __restrict__ et, int E,
                               int* __restrict__ cur, int* __restrict__ eidx) {
    int e = blockIdx.x * 256 + threadIdx.x;
    if (e < E) {
        int p = atomicAdd(&cur[dst[e]], 1);
        eidx[p] = (et[e] << 24) | src[e];
    }
}

// One block (64 thr) per dst node; thread t owns channels [4t, 4t+4).
// Reads x rows with stride src_lda, writes padded A rows (stride LDA).
__global__ void gather_kernel(const float* __restrict__ x, const int* __restrict__ eidx,
                              const int* __restrict__ off, int* __restrict__ cnt,
                              float* __restrict__ A, int ndst, int src_lda) {
    int d = blockIdx.x;
    int t = threadIdx.x;          // 0..63
    int c = t * 4;
    int beg = off[d], end = off[d + 1];
    float4 a0 = make_float4(0.f, 0.f, 0.f, 0.f);
    float4 a1 = a0, a2 = a0, a3 = a0, a4 = a0;
    for (int i = beg; i < end; i++) {
        int pk = eidx[i];
        float4 v = *(const float4*)(x + (size_t)(pk & 0xFFFFFF) * src_lda + c);
        int r = pk >> 24;
        if (r == 0) { a0.x += v.x; a0.y += v.y; a0.z += v.z; a0.w += v.w; }
        if (r == 1) { a1.x += v.x; a1.y += v.y; a1.z += v.z; a1.w += v.w; }
        if (r == 2) { a2.x += v.x; a2.y += v.y; a2.z += v.z; a2.w += v.w; }
        if (r == 3) { a3.x += v.x; a3.y += v.y; a3.z += v.z; a3.w += v.w; }
        if (r == 4) { a4.x += v.x; a4.y += v.y; a4.z += v.z; a4.w += v.w; }
    }
    size_t base = (size_t)d * LDA + c;
    size_t seg = (size_t)ndst * LDA;
#define RSTORE(k, av)                                                          \
    {                                                                          \
        float4 o;                                                              \
        o.x = rtf((av).x); o.y = rtf((av).y);                                  \
        o.z = rtf((av).z); o.w = rtf((av).w);                                  \
        *(float4*)(A + base + (size_t)(k) * seg) = o;                          \
    }
    RSTORE(0, a0); RSTORE(1, a1); RSTORE(2, a2); RSTORE(3, a3); RSTORE(4, a4);
    float4 sv = *(const float4*)(x + (size_t)d * src_lda + c);
    RSTORE(5, sv);
    if (t == 0) cnt[d] = 0;
}

// ---------------- weight transpose (one-shot per launch, tf32-rounded) ----
__global__ void transpose_weights(const float* W0, const float* Wl0,
                                  const float* W1, const float* Wl1,
                                  const float* Wm1) {
    __shared__ float t[32][33];
    int m = blockIdx.x;
    const float* src = (m < 5)   ? W0 + (size_t)m * H * H
                     : (m == 5)  ? Wl0
                     : (m < 11)  ? W1 + (size_t)(m - 6) * H * H
                     : (m == 11) ? Wl1 : Wm1;
    float* dst = g_Wt + (size_t)m * 256 * LDA;
    int bx = blockIdx.y * 32, by = blockIdx.z * 32;
    int x = threadIdx.x, y = threadIdx.y;
#pragma unroll
    for (int i = 0; i < 32; i += 8)
        t[y + i][x] = src[(size_t)(by + y + i) * H + bx + x];
    __syncthreads();
#pragma unroll
    for (int i = 0; i < 32; i += 8)
        dst[(size_t)(bx + y + i) * LDA + by + x] = rtf(t[x][y + i]);
}

// ---------------- tf32 tensor GEMM via cp.async.bulk ----------------
// C[M,256] = sum_s A_s[M,256] @ Wt_s^T + bias.  CTA 128m x 128n; seg-outer
// (B panel 130KB resident); m-chunks 32 x fullK double-buffered via bulk+mbarrier.
struct TGArgs {
    const float* A; long aseg;   // segment stride in floats
    const float* W;              // base of nseg padded [256][LDA] matrices
    int nseg; int M;
    const float* bias;
    float* C;                    // padded (LDA)
};

#define CH_ROWS 32
#define CH_BYTES (CH_ROWS * LDA * 4)     // 33280
#define B_BYTES (128 * LDA * 4)          // 133120
#define SM_A0 1024
#define SM_A1 (1024 + CH_BYTES)
#define SM_B  (1024 + 2 * CH_BYTES)
#define SM_TOTAL (1024 + 2 * CH_BYTES + B_BYTES)   // 200704

__device__ __forceinline__ void mma_chunk(uint32_t ab, uint32_t bb,
                                          int wm2, int wn4, int rowl, int khalf,
                                          float (*acc)[4]) {
#pragma unroll 4
    for (int kq = 0; kq < 32; kq++) {
        int q = kq * 8 + khalf;
        uint32_t a[4];
        uint32_t ad = ab + (((wm2 * 16 + rowl) * LDA + q) << 2);
        asm volatile(
            "ldmatrix.sync.aligned.m8n8.x4.shared.b16 {%0,%1,%2,%3}, [%4];"
            : "=r"(a[0]), "=r"(a[1]), "=r"(a[2]), "=r"(a[3]) : "r"(ad));
        uint32_t b[2][4];
#pragma unroll
        for (int i2 = 0; i2 < 2; i2++) {
            uint32_t bd = bb + (((wn4 * 32 + i2 * 16 + rowl) * LDA + q) << 2);
            asm volatile(
                "ldmatrix.sync.aligned.m8n8.x4.shared.b16 {%0,%1,%2,%3}, [%4];"
                : "=r"(b[i2][0]), "=r"(b[i2][1]), "=r"(b[i2][2]), "=r"(b[i2][3])
                : "r"(bd));
        }
#pragma unroll
        for (int in_ = 0; in_ < 4; in_++) {
            int i2 = in_ >> 1, p = in_ & 1;
            asm volatile(
                "mma.sync.aligned.m16n8k8.row.col.f32.tf32.tf32.f32 "
                "{%0,%1,%2,%3}, {%4,%5,%6,%7}, {%8,%9}, {%0,%1,%2,%3};\n"
                : "+f"(acc[in_][0]), "+f"(acc[in_][1]),
                  "+f"(acc[in_][2]), "+f"(acc[in_][3])
                : "r"(a[0]), "r"(a[1]), "r"(a[2]), "r"(a[3]),
                  "r"(b[i2][p]), "r"(b[i2][2 + p]));
        }
    }
}

__global__ void __launch_bounds__(256, 1) gemm_bulk(TGArgs g) {
    extern __shared__ char sm[];
    uint32_t sb = smem_u32(sm);
    int tid = threadIdx.x, warp = tid >> 5, lane = tid & 31;
    int wm2 = warp & 1;           // m half within 32-row chunk
    int wn4 = warp >> 1;          // n quarter (32 cols)
    int m0 = blockIdx.x * 128, n0 = blockIdx.y * 128;
    int rowl = lane & 15, khalf = (lane >> 4) * 4;
    int lr = lane >> 2, lc = lane & 3;

    if (tid == 0) {
        MBAR_INIT(sb + 0, 1);    // B
        MBAR_INIT(sb + 8, 1);    // A buf0
        MBAR_INIT(sb + 16, 1);   // A buf1
    }
    __syncthreads();

    float acc[4][4][4];           // [chunk][n8-tile][reg]
#pragma unroll
    for (int c = 0; c < 4; c++)
#pragma unroll
        for (int j = 0; j < 4; j++)
#pragma unroll
            for (int k = 0; k < 4; k++) acc[c][j][k] = 0.f;

    int pB = 0, p0 = 0, p1 = 0;
    for (int seg = 0; seg < g.nseg; seg++) {
        const float* asrc = g.A + (size_t)seg * g.aseg + (size_t)m0 * LDA;
        __syncthreads();          // previous seg's B + A buffers fully consumed
        if (tid == 0) {
            const float* bsrc = g.W + ((size_t)seg * 256 + n0) * LDA;
            MBAR_EXPECT(sb + 0, B_BYTES);
            BULK_G2S(sb + SM_B, bsrc, B_BYTES, sb + 0);
            MBAR_EXPECT(sb + 8, CH_BYTES);
            BULK_G2S(sb + SM_A0, asrc, CH_BYTES, sb + 8);
            MBAR_EXPECT(sb + 16, CH_BYTES);
            BULK_G2S(sb + SM_A1, asrc + CH_ROWS * LDA, CH_BYTES, sb + 16);
        }
        mbar_wait(sb + 0, pB); pB ^= 1;
        // chunk 0 (buf0)
        mbar_wait(sb + 8, p0); p0 ^= 1;
        mma_chunk(sb + SM_A0, sb + SM_B, wm2, wn4, rowl, khalf, acc[0]);
        __syncthreads();          // all warps done reading buf0
        if (tid == 0) {
            MBAR_EXPECT(sb + 8, CH_BYTES);
            BULK_G2S(sb + SM_A0, asrc + 2 * CH_ROWS * LDA, CH_BYTES, sb + 8);
        }
        // chunk 1 (buf1)
        mbar_wait(sb + 16, p1); p1 ^= 1;
        mma_chunk(sb + SM_A1, sb + SM_B, wm2, wn4, rowl, khalf, acc[1]);
        __syncthreads();          // all warps done reading buf1
        if (tid == 0) {
            MBAR_EXPECT(sb + 16, CH_BYTES);
            BULK_G2S(sb + SM_A1, asrc + 3 * CH_ROWS * LDA, CH_BYTES, sb + 16);
        }
        // chunk 2 (buf0)
        mbar_wait(sb + 8, p0); p0 ^= 1;
        mma_chunk(sb + SM_A0, sb + SM_B, wm2, wn4, rowl, khalf, acc[2]);
        // chunk 3 (buf1)
        mbar_wait(sb + 16, p1); p1 ^= 1;
        mma_chunk(sb + SM_A1, sb + SM_B, wm2, wn4, rowl, khalf, acc[3]);
    }

    // ---- epilogue: bias + store (padded C) ----
#pragma unroll
    for (int ci = 0; ci < 4; ci++) {
        int mrow = m0 + ci * 32 + wm2 * 16 + lr;
#pragma unroll
        for (int in_ = 0; in_ < 4; in_++) {
            int col = n0 + wn4 * 32 + in_ * 8 + lc * 2;
            float bia0 = g.bias[col];
            float bia1 = g.bias[col + 1];
            if (mrow < g.M) {
                float2 v = make_float2(acc[ci][in_][0] + bia0,
                                       acc[ci][in_][1] + bia1);
                *(float2*)(g.C + (size_t)mrow * LDA + col) = v;
            }
            if (mrow + 8 < g.M) {
                float2 v = make_float2(acc[ci][in_][2] + bia0,
                                       acc[ci][in_][3] + bia1);
                *(float2*)(g.C + (size_t)(mrow + 8) * LDA + col) = v;
            }
        }
    }
}

// ---------------- SIMT GEMM (final 256x153 only; A padded, W raw) ---------
struct GemmArgs {
    const float* A;   // lda = LDA
    const float* W;   // [256][N] row-major
    int M, N;
    const float* bias;
    float* C;         // [M][N] dense
};

__global__ void gemm_kernel(GemmArgs g) {
    __shared__ float As[16][65];
    __shared__ float Bs[16][64];

    int tid = threadIdx.x;
    int m0 = blockIdx.x * 64;
    int n0 = blockIdx.y * 64;
    int tm = tid >> 4;
    int tn = tid & 15;

    int lrow = tid >> 2;
    int lk4 = (tid & 3) << 2;
    int lkb = tid >> 4;
    int ln4 = (tid & 15) << 2;

    float acc[4][4];
#pragma unroll
    for (int i = 0; i < 4; i++)
#pragma unroll
        for (int j = 0; j < 4; j++) acc[i][j] = 0.f;

    for (int k0 = 0; k0 < H; k0 += 16) {
        float4 av = make_float4(0.f, 0.f, 0.f, 0.f);
        if (m0 + lrow < g.M)
            av = *(const float4*)(g.A + (size_t)(m0 + lrow) * LDA + k0 + lk4);
        As[lk4 + 0][lrow] = av.x;
        As[lk4 + 1][lrow] = av.y;
        As[lk4 + 2][lrow] = av.z;
        As[lk4 + 3][lrow] = av.w;
        const float* wp = g.W + (size_t)(k0 + lkb) * g.N + n0 + ln4;
        float4 bv;
        bv.x = (n0 + ln4 + 0 < g.N) ? wp[0] : 0.f;
        bv.y = (n0 + ln4 + 1 < g.N) ? wp[1] : 0.f;
        bv.z = (n0 + ln4 + 2 < g.N) ? wp[2] : 0.f;
        bv.w = (n0 + ln4 + 3 < g.N) ? wp[3] : 0.f;
        *(float4*)&Bs[lkb][ln4] = bv;
        __syncthreads();
#pragma unroll
        for (int kk = 0; kk < 16; kk++) {
            float a0 = As[kk][tm * 4 + 0];
            float a1 = As[kk][tm * 4 + 1];
            float a2 = As[kk][tm * 4 + 2];
            float a3 = As[kk][tm * 4 + 3];
            float4 b = *(const float4*)&Bs[kk][tn * 4];
            acc[0][0] += a0 * b.x; acc[0][1] += a0 * b.y; acc[0][2] += a0 * b.z; acc[0][3] += a0 * b.w;
            acc[1][0] += a1 * b.x; acc[1][1] += a1 * b.y; acc[1][2] += a1 * b.z; acc[1][3] += a1 * b.w;
            acc[2][0] += a2 * b.x; acc[2][1] += a2 * b.y; acc[2][2] += a2 * b.z; acc[2][3] += a2 * b.w;
            acc[3][0] += a3 * b.x; acc[3][1] += a3 * b.y; acc[3][2] += a3 * b.z; acc[3][3] += a3 * b.w;
        }
        __syncthreads();
    }

#pragma unroll
    for (int i = 0; i < 4; i++) {
        int m = m0 + tm * 4 + i;
        if (m >= g.M) continue;
#pragma unroll
        for (int j = 0; j < 4; j++) {
            int n = n0 + tn * 4 + j;
            if (n < g.N) g.C[(size_t)m * g.N + n] = acc[i][j] + g.bias[n];
        }
    }
}

// ---------------- BN kernels (padded rows) ----------------
__global__ void zero_stats_kernel() {
    g_sum[threadIdx.x] = 0.f;
    g_sumsq[threadIdx.x] = 0.f;
}

__global__ void bn_stats_kernel(const float* __restrict__ h, int M) {
    int col = threadIdx.x;
    int r0 = blockIdx.x * 128;
    int rend = min(r0 + 128, M);
    float s = 0.f, s2 = 0.f;
    for (int r = r0; r < rend; r++) {
        float v = h[(size_t)r * LDA + col];
        s += v;
        s2 += v * v;
    }
    atomicAdd(&g_sum[col], s);
    atomicAdd(&g_sumsq[col], s2);
}

__global__ void bn_finalize_kernel(const float* __restrict__ gamma,
                                   const float* __restrict__ beta, float invM) {
    int col = threadIdx.x;
    float mean = g_sum[col] * invM;
    float var = g_sumsq[col] * invM - mean * mean;
    float sc = gamma[col] * rsqrtf(var + 1e-5f);
    g_scale[col] = sc;
    g_shift[col] = beta[col] - mean * sc;
}

// act 0 = ELU, 1 = ReLU; rnd -> round to tf32 for tensor-GEMM consumers
__global__ void bn_apply_kernel(float* __restrict__ h, int M, int act, int rnd) {
    long i = (long)blockIdx.x * blockDim.x + threadIdx.x;
    if (i >= (long)M * H) return;
    int col = (int)(i & (H - 1));
    long row = i >> 8;
    float v = h[row * LDA + col] * g_scale[col] + g_shift[col];
    if (act == 0)
        v = (v > 0.f) ? v : expm1f(v);
    else
        v = (v > 0.f) ? v : 0.f;
    if (rnd) v = rtf(v);
    h[row * LDA + col] = v;
}

// ---------------- host orchestration ----------------
static inline int cdiv(long a, long b) { return (int)((a + b - 1) / b); }

extern "C" void kernel_launch(void* const* d_in, const int* in_sizes, int n_in,
                              void* d_out, int out_size) {
    const float* x   = (const float*)d_in[0];
    const int* src0  = (const int*)d_in[1];
    const int* dst0  = (const int*)d_in[2];
    const int* et0   = (const int*)d_in[3];
    const int* src1  = (const int*)d_in[4];
    const int* dst1  = (const int*)d_in[5];
    const int* et1   = (const int*)d_in[6];
    const float* W0  = (const float*)d_in[9];
    const float* Wl0 = (const float*)d_in[10];
    const float* b0  = (const float*)d_in[11];
    const float* g0  = (const float*)d_in[12];
    const float* be0 = (const float*)d_in[13];
    const float* W1  = (const float*)d_in[14];
    const float* Wl1 = (const float*)d_in[15];
    const float* b1  = (const float*)d_in[16];
    const float* g1  = (const float*)d_in[17];
    const float* be1 = (const float*)d_in[18];
    const float* Wm1 = (const float*)d_in[19];
    const float* bm1 = (const float*)d_in[20];
    const float* gm  = (const float*)d_in[21];
    const float* bem = (const float*)d_in[22];
    const float* Wm2 = (const float*)d_in[23];
    const float* bm2 = (const float*)d_in[24];
    float* out = (float*)d_out;

    const int E0 = in_sizes[1];
    const int E1 = in_sizes[4];
    const int COUT = 153;
    const int M1 = out_size / COUT;   // 10000
    const int M0 = M0_CONST;          // 50000

    float *A0, *A1, *H0, *H1, *Mh, *Wt;
    int *cnt, *off, *cur, *eidx;
    cudaGetSymbolAddress((void**)&A0, g_A0);
    cudaGetSymbolAddress((void**)&A1, g_A1);
    cudaGetSymbolAddress((void**)&H0, g_H0);
    cudaGetSymbolAddress((void**)&H1, g_H1);
    cudaGetSymbolAddress((void**)&Mh, g_Mh);
    cudaGetSymbolAddress((void**)&Wt, g_Wt);
    cudaGetSymbolAddress((void**)&cnt, g_cnt);
    cudaGetSymbolAddress((void**)&off, g_off);
    cudaGetSymbolAddress((void**)&cur, g_cur);
    cudaGetSymbolAddress((void**)&eidx, g_eidx);

    cudaFuncSetAttribute(gemm_bulk,
                         cudaFuncAttributeMaxDynamicSharedMemorySize, SM_TOTAL);

    // ---- layer 0: CSR + gather (profiled slot 3) + bulk GEMM ----
    hist_kernel<<<cdiv(E0, 256), 256>>>(dst0, E0, cnt);                     // 0
    scan_kernel<<<1, 1024>>>(cnt, off, cur, M0);                            // 1
    scatter_kernel<<<cdiv(E0, 256), 256>>>(src0, dst0, et0, E0, cur, eidx); // 2
    gather_kernel<<<M0, 64>>>(x, eidx, off, cnt, A0, M0, H);                // 3 <- profiled
    transpose_weights<<<dim3(13, 8, 8), dim3(32, 8)>>>(W0, Wl0, W1, Wl1, Wm1);

    TGArgs ga;
    ga.A = A0;  ga.aseg = (long)M0 * LDA;
    ga.W = Wt;  ga.nseg = NSEG;  ga.M = M0;  ga.bias = b0;  ga.C = H0;
    gemm_bulk<<<dim3(cdiv(M0, 128), 2), 256, SM_TOTAL>>>(ga);

    zero_stats_kernel<<<1, H>>>();
    bn_stats_kernel<<<cdiv(M0, 128), H>>>(H0, M0);
    bn_finalize_kernel<<<1, H>>>(g0, be0, 1.0f / M0);
    bn_apply_kernel<<<cdiv((long)M0 * H, 256), 256>>>(H0, M0, 0, 1);

    // ---- layer 1 ----
    hist_kernel<<<cdiv(E1, 256), 256>>>(dst1, E1, cnt);
    scan_kernel<<<1, 1024>>>(cnt, off, cur, M1);
    scatter_kernel<<<cdiv(E1, 256), 256>>>(src1, dst1, et1, E1, cur, eidx);
    gather_kernel<<<M1, 64>>>(H0, eidx, off, cnt, A1, M1, LDA);

    ga.A = A1;  ga.aseg = (long)M1 * LDA;
    ga.W = Wt + (size_t)6 * 256 * LDA;
    ga.nseg = NSEG;  ga.M = M1;  ga.bias = b1;  ga.C = H1;
    gemm_bulk<<<dim3(cdiv(M1, 128), 2), 256, SM_TOTAL>>>(ga);

    zero_stats_kernel<<<1, H>>>();
    bn_stats_kernel<<<cdiv(M1, 128), H>>>(H1, M1);
    bn_finalize_kernel<<<1, H>>>(g1, be1, 1.0f / M1);
    bn_apply_kernel<<<cdiv((long)M1 * H, 256), 256>>>(H1, M1, 0, 1);

    // ---- MLP head ----
    ga.A = H1;  ga.aseg = 0;
    ga.W = Wt + (size_t)12 * 256 * LDA;
    ga.nseg = 1;  ga.M = M1;  ga.bias = bm1;  ga.C = Mh;
    gemm_bulk<<<dim3(cdiv(M1, 128), 2), 256, SM_TOTAL>>>(ga);

    zero_stats_kernel<<<1, H>>>();
    bn_stats_kernel<<<cdiv(M1, 128), H>>>(Mh, M1);
    bn_finalize_kernel<<<1, H>>>(gm, bem, 1.0f / M1);
    bn_apply_kernel<<<cdiv((long)M1 * H, 256), 256>>>(Mh, M1, 1, 0);

    GemmArgs gf;
    gf.A = Mh;  gf.W = Wm2;
    gf.M = M1;  gf.N = COUT;  gf.bias = bm2;  gf.C = out;
    gemm_kernel<<<dim3(cdiv(M1, 64), cdiv(COUT, 64)), 256>>>(gf);
}

// round 10
// speedup vs baseline: 1.9424x; 1.0513x over previous
#include <cuda_runtime.h>
#include <math.h>
#include <stdint.h>

#define H 256
#define RREL 5
#define NSEG 6            // 5 relations + self-loop
#define M0_CONST 50000
#define M1_CONST 10000
#define E0_MAX 800000
#define LDA 260           // padded row stride (floats); 1040B: 16B-aligned, conflict-free ldmatrix

// ---------------- scratch (device globals: allocation-free) ----------------
__device__ float g_A0[((size_t)NSEG * M0_CONST + 128) * LDA];
__device__ float g_A1[((size_t)NSEG * M1_CONST + 128) * LDA];
__device__ float g_H0[((size_t)M0_CONST + 128) * LDA];
__device__ float g_H1[((size_t)M1_CONST + 128) * LDA];
__device__ float g_Mh[((size_t)M1_CONST + 128) * LDA];
__device__ float g_Wt[(size_t)13 * 256 * LDA];   // [mat][n][k] transposed, tf32-rounded
__device__ int   g_cnt[M0_CONST + 4];
__device__ int   g_off[M0_CONST + 4];
__device__ int   g_cur[M0_CONST + 4];
__device__ int   g_eidx[E0_MAX];
__device__ float g_sum[H];
__device__ float g_sumsq[H];
__device__ float g_scale[H];
__device__ float g_shift[H];

// ---------------- helpers ----------------
__device__ __forceinline__ uint32_t f2tf32(float v) {
    uint32_t t;
    asm("cvt.rna.tf32.f32 %0, %1;" : "=r"(t) : "f"(v));
    return t;
}
__device__ __forceinline__ float rtf(float v) { return __uint_as_float(f2tf32(v)); }

__device__ __forceinline__ uint32_t smem_u32(const void* p) {
    uint32_t a;
    asm("{ .reg .u64 t; cvta.to.shared.u64 t, %1; cvt.u32.u64 %0, t; }"
        : "=r"(a) : "l"(p));
    return a;
}

#define MBAR_INIT(addr, cnt)                                                   \
    asm volatile("mbarrier.init.shared.b64 [%0], %1;" :: "r"(addr), "r"(cnt) : "memory")

#define MBAR_EXPECT(addr, bytes)                                               \
    asm volatile("mbarrier.arrive.expect_tx.shared.b64 _, [%0], %1;"           \
                 :: "r"(addr), "r"(bytes) : "memory")

#define BULK_G2S(dst, src, bytes, mbar)                                        \
    asm volatile(                                                              \
        "cp.async.bulk.shared::cluster.global.mbarrier::complete_tx::bytes "   \
        "[%0], [%1], %2, [%3];"                                                \
        :: "r"(dst), "l"(src), "r"(bytes), "r"(mbar) : "memory")

__device__ __forceinline__ void mbar_wait(uint32_t mbar, uint32_t parity) {
    uint32_t done;
    asm volatile(
        "{\n\t.reg .pred p;\n\t"
        "mbarrier.try_wait.parity.acquire.cta.shared::cta.b64 p, [%1], %2;\n\t"
        "selp.b32 %0, 1, 0, p;\n\t}"
        : "=r"(done) : "r"(mbar), "r"(parity) : "memory");
    if (!done) {
        asm volatile(
            "{\n\t.reg .pred P1;\n\t"
            "W_%=:\n\t"
            "mbarrier.try_wait.parity.acquire.cta.shared::cta.b64 P1, [%0], %1, 0x989680;\n\t"
            "@P1 bra.uni D_%=;\n\t"
            "bra.uni W_%=;\n\t"
            "D_%=:\n\t}"
            :: "r"(mbar), "r"(parity) : "memory");
    }
}

// ---------------- CSR build (dst-keyed, relation packed into eidx) --------
__global__ void hist_kernel(const int* __restrict__ dst, int E, int* __restrict__ cnt) {
    int e = blockIdx.x * 256 + threadIdx.x;
    if (e < E) atomicAdd(&cnt[dst[e]], 1);
}

__global__ void scan_kernel(const int* __restrict__ cnt, int* __restrict__ off,
                            int* __restrict__ cur, int n) {
    __shared__ int part[1024];
    int t = threadIdx.x;
    int chunk = (n + 1023) >> 10;
    int a = t * chunk;
    int b = min(a + chunk, n);
    int s = 0;
#pragma unroll 4
    for (int i = a; i < b; i++) s += cnt[i];
    part[t] = s;
    __syncthreads();
    for (int d = 1; d < 1024; d <<= 1) {
        int v = (t >= d) ? part[t - d] : 0;
        __syncthreads();
        part[t] += v;
        __syncthreads();
    }
    int run = (t == 0) ? 0 : part[t - 1];
    for (int i = a; i < b; i++) { off[i] = run; cur[i] = run; run += cnt[i]; }
    if (b == n) off[n] = run;
}

__global__ void scatter_kernel(const int* __restrict__ src, const int* __restrict__ dst,
                               const int* __restrict__ et, int E,
                               int* __restrict__ cur, int* __restrict__ eidx) {
    int e = blockIdx.x * 256 + threadIdx.x;
    if (e < E) {
        int p = atomicAdd(&cur[dst[e]], 1);
        eidx[p] = (et[e] << 24) | src[e];
    }
}

// One block (64 thr) per dst node; thread t owns channels [4t, 4t+4).
// Edge loop unrolled x2 for memory-level parallelism.
__global__ void gather_kernel(const float* __restrict__ x, const int* __restrict__ eidx,
                              const int* __restrict__ off, int* __restrict__ cnt,
                              float* __restrict__ A, int ndst, int src_lda) {
    int d = blockIdx.x;
    int t = threadIdx.x;          // 0..63
    int c = t * 4;
    int beg = off[d], end = off[d + 1];
    float4 a0 = make_float4(0.f, 0.f, 0.f, 0.f);
    float4 a1 = a0, a2 = a0, a3 = a0, a4 = a0;
#define ACCUM(pk_, v_)                                                         \
    {                                                                          \
        int r_ = (pk_) >> 24;                                                  \
        if (r_ == 0) { a0.x += (v_).x; a0.y += (v_).y; a0.z += (v_).z; a0.w += (v_).w; } \
        if (r_ == 1) { a1.x += (v_).x; a1.y += (v_).y; a1.z += (v_).z; a1.w += (v_).w; } \
        if (r_ == 2) { a2.x += (v_).x; a2.y += (v_).y; a2.z += (v_).z; a2.w += (v_).w; } \
        if (r_ == 3) { a3.x += (v_).x; a3.y += (v_).y; a3.z += (v_).z; a3.w += (v_).w; } \
        if (r_ == 4) { a4.x += (v_).x; a4.y += (v_).y; a4.z += (v_).z; a4.w += (v_).w; } \
    }
    int i = beg;
    for (; i + 1 < end; i += 2) {
        int pk0 = eidx[i];
        int pk1 = eidx[i + 1];
        float4 v0 = *(const float4*)(x + (size_t)(pk0 & 0xFFFFFF) * src_lda + c);
        float4 v1 = *(const float4*)(x + (size_t)(pk1 & 0xFFFFFF) * src_lda + c);
        ACCUM(pk0, v0);
        ACCUM(pk1, v1);
    }
    if (i < end) {
        int pk0 = eidx[i];
        float4 v0 = *(const float4*)(x + (size_t)(pk0 & 0xFFFFFF) * src_lda + c);
        ACCUM(pk0, v0);
    }
    size_t base = (size_t)d * LDA + c;
    size_t seg = (size_t)ndst * LDA;
#define RSTORE(k, av)                                                          \
    {                                                                          \
        float4 o;                                                              \
        o.x = rtf((av).x); o.y = rtf((av).y);                                  \
        o.z = rtf((av).z); o.w = rtf((av).w);                                  \
        *(float4*)(A + base + (size_t)(k) * seg) = o;                          \
    }
    RSTORE(0, a0); RSTORE(1, a1); RSTORE(2, a2); RSTORE(3, a3); RSTORE(4, a4);
    float4 sv = *(const float4*)(x + (size_t)d * src_lda + c);
    RSTORE(5, sv);
    if (t == 0) cnt[d] = 0;
}

// ---------------- weight transpose (one-shot per launch, tf32-rounded) ----
__global__ void transpose_weights(const float* W0, const float* Wl0,
                                  const float* W1, const float* Wl1,
                                  const float* Wm1) {
    __shared__ float t[32][33];
    int m = blockIdx.x;
    const float* src = (m < 5)   ? W0 + (size_t)m * H * H
                     : (m == 5)  ? Wl0
                     : (m < 11)  ? W1 + (size_t)(m - 6) * H * H
                     : (m == 11) ? Wl1 : Wm1;
    float* dst = g_Wt + (size_t)m * 256 * LDA;
    int bx = blockIdx.y * 32, by = blockIdx.z * 32;
    int x = threadIdx.x, y = threadIdx.y;
#pragma unroll
    for (int i = 0; i < 32; i += 8)
        t[y + i][x] = src[(size_t)(by + y + i) * H + bx + x];
    __syncthreads();
#pragma unroll
    for (int i = 0; i < 32; i += 8)
        dst[(size_t)(bx + y + i) * LDA + by + x] = rtf(t[x][y + i]);
}

// ---------------- tf32 tensor GEMM via cp.async.bulk, pipelined ----------
// C[M,256] = sum_s A_s[M,256] @ Wt_s^T + bias.  CTA 128m x 128n; seg-outer.
// B panel loaded as 4 x 32-row chunks with per-chunk mbarriers (warp wn4
// waits only its own chunk); A chunks double-buffered with cross-segment
// prefetch so seg-boundary bubbles shrink to one chunk arrival.
struct TGArgs {
    const float* A; long aseg;   // segment stride in floats
    const float* W;              // base of nseg padded [256][LDA] matrices
    int nseg; int M;
    const float* bias;
    float* C;                    // padded (LDA)
};

#define CH_ROWS 32
#define CH_BYTES (CH_ROWS * LDA * 4)     // 33280
#define B_BYTES (128 * LDA * 4)          // 133120
#define SM_A0 1024
#define SM_A1 (1024 + CH_BYTES)
#define SM_B  (1024 + 2 * CH_BYTES)
#define SM_TOTAL (1024 + 2 * CH_BYTES + B_BYTES)   // 200704
// mbarriers: A0 @ sb+0, A1 @ sb+8, B chunk c @ sb+16+8c

__device__ __forceinline__ void mma_chunk(uint32_t ab, uint32_t bb,
                                          int wm2, int wn4, int rowl, int khalf,
                                          float (*acc)[4]) {
#pragma unroll 4
    for (int kq = 0; kq < 32; kq++) {
        int q = kq * 8 + khalf;
        uint32_t a[4];
        uint32_t ad = ab + (((wm2 * 16 + rowl) * LDA + q) << 2);
        asm volatile(
            "ldmatrix.sync.aligned.m8n8.x4.shared.b16 {%0,%1,%2,%3}, [%4];"
            : "=r"(a[0]), "=r"(a[1]), "=r"(a[2]), "=r"(a[3]) : "r"(ad));
        uint32_t b[2][4];
#pragma unroll
        for (int i2 = 0; i2 < 2; i2++) {
            uint32_t bd = bb + (((wn4 * 32 + i2 * 16 + rowl) * LDA + q) << 2);
            asm volatile(
                "ldmatrix.sync.aligned.m8n8.x4.shared.b16 {%0,%1,%2,%3}, [%4];"
                : "=r"(b[i2][0]), "=r"(b[i2][1]), "=r"(b[i2][2]), "=r"(b[i2][3])
                : "r"(bd));
        }
#pragma unroll
        for (int in_ = 0; in_ < 4; in_++) {
            int i2 = in_ >> 1, p = in_ & 1;
            asm volatile(
                "mma.sync.aligned.m16n8k8.row.col.f32.tf32.tf32.f32 "
                "{%0,%1,%2,%3}, {%4,%5,%6,%7}, {%8,%9}, {%0,%1,%2,%3};\n"
                : "+f"(acc[in_][0]), "+f"(acc[in_][1]),
                  "+f"(acc[in_][2]), "+f"(acc[in_][3])
                : "r"(a[0]), "r"(a[1]), "r"(a[2]), "r"(a[3]),
                  "r"(b[i2][p]), "r"(b[i2][2 + p]));
        }
    }
}

__global__ void __launch_bounds__(256, 1) gemm_bulk(TGArgs g) {
    extern __shared__ char sm[];
    uint32_t sb = smem_u32(sm);
    int tid = threadIdx.x, warp = tid >> 5, lane = tid & 31;
    int wm2 = warp & 1;           // m half within 32-row chunk
    int wn4 = warp >> 1;          // n quarter (32 cols) == B chunk id
    int m0 = blockIdx.x * 128, n0 = blockIdx.y * 128;
    int rowl = lane & 15, khalf = (lane >> 4) * 4;
    int lr = lane >> 2, lc = lane & 3;
    uint32_t myB = sb + 16 + 8 * wn4;

    if (tid == 0) {
        MBAR_INIT(sb + 0, 1);
        MBAR_INIT(sb + 8, 1);
#pragma unroll
        for (int c = 0; c < 4; c++) MBAR_INIT(sb + 16 + 8 * c, 1);
    }
    __syncthreads();

    float acc[4][4][4];           // [chunk][n8-tile][reg]
#pragma unroll
    for (int c = 0; c < 4; c++)
#pragma unroll
        for (int j = 0; j < 4; j++)
#pragma unroll
            for (int k = 0; k < 4; k++) acc[c][j][k] = 0.f;

    // prologue: seg 0 loads
    if (tid == 0) {
        const float* bsrc = g.W + (size_t)n0 * LDA;
        const float* asrc = g.A + (size_t)m0 * LDA;
#pragma unroll
        for (int c = 0; c < 4; c++) {
            MBAR_EXPECT(sb + 16 + 8 * c, CH_BYTES);
            BULK_G2S(sb + SM_B + c * CH_BYTES, bsrc + (size_t)c * CH_ROWS * LDA,
                     CH_BYTES, sb + 16 + 8 * c);
        }
        MBAR_EXPECT(sb + 0, CH_BYTES);
        BULK_G2S(sb + SM_A0, asrc, CH_BYTES, sb + 0);
        MBAR_EXPECT(sb + 8, CH_BYTES);
        BULK_G2S(sb + SM_A1, asrc + CH_ROWS * LDA, CH_BYTES, sb + 8);
    }

    int pB = 0, p0 = 0, p1 = 0;
    for (int seg = 0; seg < g.nseg; seg++) {
        const float* asrc = g.A + (size_t)seg * g.aseg + (size_t)m0 * LDA;
        const float* nasrc = asrc + g.aseg;
        bool more = (seg + 1 < g.nseg);

        mbar_wait(myB, pB);               // own B chunk only
        // chunk 0 (buf0)
        mbar_wait(sb + 0, p0); p0 ^= 1;
        mma_chunk(sb + SM_A0, sb + SM_B, wm2, wn4, rowl, khalf, acc[0]);
        __syncthreads();
        if (tid == 0) {
            MBAR_EXPECT(sb + 0, CH_BYTES);
            BULK_G2S(sb + SM_A0, asrc + 2 * CH_ROWS * LDA, CH_BYTES, sb + 0);
        }
        // chunk 1 (buf1)
        mbar_wait(sb + 8, p1); p1 ^= 1;
        mma_chunk(sb + SM_A1, sb + SM_B, wm2, wn4, rowl, khalf, acc[1]);
        __syncthreads();
        if (tid == 0) {
            MBAR_EXPECT(sb + 8, CH_BYTES);
            BULK_G2S(sb + SM_A1, asrc + 3 * CH_ROWS * LDA, CH_BYTES, sb + 8);
        }
        // chunk 2 (buf0)
        mbar_wait(sb + 0, p0); p0 ^= 1;
        mma_chunk(sb + SM_A0, sb + SM_B, wm2, wn4, rowl, khalf, acc[2]);
        __syncthreads();
        if (more && tid == 0) {           // prefetch next seg A0 during chunk 3
            MBAR_EXPECT(sb + 0, CH_BYTES);
            BULK_G2S(sb + SM_A0, nasrc, CH_BYTES, sb + 0);
        }
        // chunk 3 (buf1)
        mbar_wait(sb + 8, p1); p1 ^= 1;
        mma_chunk(sb + SM_A1, sb + SM_B, wm2, wn4, rowl, khalf, acc[3]);
        __syncthreads();                  // all warps done with this seg's B + buf1
        if (more && tid == 0) {
            const float* nbsrc = g.W + ((size_t)(seg + 1) * 256 + n0) * LDA;
#pragma unroll
            for (int c = 0; c < 4; c++) {
                MBAR_EXPECT(sb + 16 + 8 * c, CH_BYTES);
                BULK_G2S(sb + SM_B + c * CH_BYTES, nbsrc + (size_t)c * CH_ROWS * LDA,
                         CH_BYTES, sb + 16 + 8 * c);
            }
            MBAR_EXPECT(sb + 8, CH_BYTES);
            BULK_G2S(sb + SM_A1, nasrc + CH_ROWS * LDA, CH_BYTES, sb + 8);
        }
        pB ^= 1;
    }

    // ---- epilogue: bias + store (padded C) ----
#pragma unroll
    for (int ci = 0; ci < 4; ci++) {
        int mrow = m0 + ci * 32 + wm2 * 16 + lr;
#pragma unroll
        for (int in_ = 0; in_ < 4; in_++) {
            int col = n0 + wn4 * 32 + in_ * 8 + lc * 2;
            float bia0 = g.bias[col];
            float bia1 = g.bias[col + 1];
            if (mrow < g.M) {
                float2 v = make_float2(acc[ci][in_][0] + bia0,
                                       acc[ci][in_][1] + bia1);
                *(float2*)(g.C + (size_t)mrow * LDA + col) = v;
            }
            if (mrow + 8 < g.M) {
                float2 v = make_float2(acc[ci][in_][2] + bia0,
                                       acc[ci][in_][3] + bia1);
                *(float2*)(g.C + (size_t)(mrow + 8) * LDA + col) = v;
            }
        }
    }
}

// ---------------- SIMT GEMM (final 256x153 only; A padded, W raw) ---------
struct GemmArgs {
    const float* A;   // lda = LDA
    const float* W;   // [256][N] row-major
    int M, N;
    const float* bias;
    float* C;         // [M][N] dense
};

__global__ void gemm_kernel(GemmArgs g) {
    __shared__ float As[16][65];
    __shared__ float Bs[16][64];

    int tid = threadIdx.x;
    int m0 = blockIdx.x * 64;
    int n0 = blockIdx.y * 64;
    int tm = tid >> 4;
    int tn = tid & 15;

    int lrow = tid >> 2;
    int lk4 = (tid & 3) << 2;
    int lkb = tid >> 4;
    int ln4 = (tid & 15) << 2;

    float acc[4][4];
#pragma unroll
    for (int i = 0; i < 4; i++)
#pragma unroll
        for (int j = 0; j < 4; j++) acc[i][j] = 0.f;

    for (int k0 = 0; k0 < H; k0 += 16) {
        float4 av = make_float4(0.f, 0.f, 0.f, 0.f);
        if (m0 + lrow < g.M)
            av = *(const float4*)(g.A + (size_t)(m0 + lrow) * LDA + k0 + lk4);
        As[lk4 + 0][lrow] = av.x;
        As[lk4 + 1][lrow] = av.y;
        As[lk4 + 2][lrow] = av.z;
        As[lk4 + 3][lrow] = av.w;
        const float* wp = g.W + (size_t)(k0 + lkb) * g.N + n0 + ln4;
        float4 bv;
        bv.x = (n0 + ln4 + 0 < g.N) ? wp[0] : 0.f;
        bv.y = (n0 + ln4 + 1 < g.N) ? wp[1] : 0.f;
        bv.z = (n0 + ln4 + 2 < g.N) ? wp[2] : 0.f;
        bv.w = (n0 + ln4 + 3 < g.N) ? wp[3] : 0.f;
        *(float4*)&Bs[lkb][ln4] = bv;
        __syncthreads();
#pragma unroll
        for (int kk = 0; kk < 16; kk++) {
            float a0 = As[kk][tm * 4 + 0];
            float a1 = As[kk][tm * 4 + 1];
            float a2 = As[kk][tm * 4 + 2];
            float a3 = As[kk][tm * 4 + 3];
            float4 b = *(const float4*)&Bs[kk][tn * 4];
            acc[0][0] += a0 * b.x; acc[0][1] += a0 * b.y; acc[0][2] += a0 * b.z; acc[0][3] += a0 * b.w;
            acc[1][0] += a1 * b.x; acc[1][1] += a1 * b.y; acc[1][2] += a1 * b.z; acc[1][3] += a1 * b.w;
            acc[2][0] += a2 * b.x; acc[2][1] += a2 * b.y; acc[2][2] += a2 * b.z; acc[2][3] += a2 * b.w;
            acc[3][0] += a3 * b.x; acc[3][1] += a3 * b.y; acc[3][2] += a3 * b.z; acc[3][3] += a3 * b.w;
        }
        __syncthreads();
    }

#pragma unroll
    for (int i = 0; i < 4; i++) {
        int m = m0 + tm * 4 + i;
        if (m >= g.M) continue;
#pragma unroll
        for (int j = 0; j < 4; j++) {
            int n = n0 + tn * 4 + j;
            if (n < g.N) g.C[(size_t)m * g.N + n] = acc[i][j] + g.bias[n];
        }
    }
}

// ---------------- BN kernels (padded rows) ----------------
__global__ void zero_stats_kernel() {
    g_sum[threadIdx.x] = 0.f;
    g_sumsq[threadIdx.x] = 0.f;
}

__global__ void bn_stats_kernel(const float* __restrict__ h, int M) {
    int col = threadIdx.x;
    int r0 = blockIdx.x * 128;
    int rend = min(r0 + 128, M);
    float s = 0.f, s2 = 0.f;
    for (int r = r0; r < rend; r++) {
        float v = h[(size_t)r * LDA + col];
        s += v;
        s2 += v * v;
    }
    atomicAdd(&g_sum[col], s);
    atomicAdd(&g_sumsq[col], s2);
}

__global__ void bn_finalize_kernel(const float* __restrict__ gamma,
                                   const float* __restrict__ beta, float invM) {
    int col = threadIdx.x;
    float mean = g_sum[col] * invM;
    float var = g_sumsq[col] * invM - mean * mean;
    float sc = gamma[col] * rsqrtf(var + 1e-5f);
    g_scale[col] = sc;
    g_shift[col] = beta[col] - mean * sc;
}

// act 0 = ELU, 1 = ReLU; rnd -> round to tf32 for tensor-GEMM consumers
__global__ void bn_apply_kernel(float* __restrict__ h, int M, int act, int rnd) {
    long i = (long)blockIdx.x * blockDim.x + threadIdx.x;
    if (i >= (long)M * H) return;
    int col = (int)(i & (H - 1));
    long row = i >> 8;
    float v = h[row * LDA + col] * g_scale[col] + g_shift[col];
    if (act == 0)
        v = (v > 0.f) ? v : expm1f(v);
    else
        v = (v > 0.f) ? v : 0.f;
    if (rnd) v = rtf(v);
    h[row * LDA + col] = v;
}

// ---------------- host orchestration ----------------
static inline int cdiv(long a, long b) { return (int)((a + b - 1) / b); }

extern "C" void kernel_launch(void* const* d_in, const int* in_sizes, int n_in,
                              void* d_out, int out_size) {
    const float* x   = (const float*)d_in[0];
    const int* src0  = (const int*)d_in[1];
    const int* dst0  = (const int*)d_in[2];
    const int* et0   = (const int*)d_in[3];
    const int* src1  = (const int*)d_in[4];
    const int* dst1  = (const int*)d_in[5];
    const int* et1   = (const int*)d_in[6];
    const float* W0  = (const float*)d_in[9];
    const float* Wl0 = (const float*)d_in[10];
    const float* b0  = (const float*)d_in[11];
    const float* g0  = (const float*)d_in[12];
    const float* be0 = (const float*)d_in[13];
    const float* W1  = (const float*)d_in[14];
    const float* Wl1 = (const float*)d_in[15];
    const float* b1  = (const float*)d_in[16];
    const float* g1  = (const float*)d_in[17];
    const float* be1 = (const float*)d_in[18];
    const float* Wm1 = (const float*)d_in[19];
    const float* bm1 = (const float*)d_in[20];
    const float* gm  = (const float*)d_in[21];
    const float* bem = (const float*)d_in[22];
    const float* Wm2 = (const float*)d_in[23];
    const float* bm2 = (const float*)d_in[24];
    float* out = (float*)d_out;

    const int E0 = in_sizes[1];
    const int E1 = in_sizes[4];
    const int COUT = 153;
    const int M1 = out_size / COUT;   // 10000
    const int M0 = M0_CONST;          // 50000

    float *A0, *A1, *H0, *H1, *Mh, *Wt;
    int *cnt, *off, *cur, *eidx;
    cudaGetSymbolAddress((void**)&A0, g_A0);
    cudaGetSymbolAddress((void**)&A1, g_A1);
    cudaGetSymbolAddress((void**)&H0, g_H0);
    cudaGetSymbolAddress((void**)&H1, g_H1);
    cudaGetSymbolAddress((void**)&Mh, g_Mh);
    cudaGetSymbolAddress((void**)&Wt, g_Wt);
    cudaGetSymbolAddress((void**)&cnt, g_cnt);
    cudaGetSymbolAddress((void**)&off, g_off);
    cudaGetSymbolAddress((void**)&cur, g_cur);
    cudaGetSymbolAddress((void**)&eidx, g_eidx);

    cudaFuncSetAttribute(gemm_bulk,
                         cudaFuncAttributeMaxDynamicSharedMemorySize, SM_TOTAL);

    // ---- layer 0: CSR + gather (profiled slot 3) + bulk GEMM ----
    hist_kernel<<<cdiv(E0, 256), 256>>>(dst0, E0, cnt);                     // 0
    scan_kernel<<<1, 1024>>>(cnt, off, cur, M0);                            // 1
    scatter_kernel<<<cdiv(E0, 256), 256>>>(src0, dst0, et0, E0, cur, eidx); // 2
    gather_kernel<<<M0, 64>>>(x, eidx, off, cnt, A0, M0, H);                // 3 <- profiled
    transpose_weights<<<dim3(13, 8, 8), dim3(32, 8)>>>(W0, Wl0, W1, Wl1, Wm1);

    TGArgs ga;
    ga.A = A0;  ga.aseg = (long)M0 * LDA;
    ga.W = Wt;  ga.nseg = NSEG;  ga.M = M0;  ga.bias = b0;  ga.C = H0;
    gemm_bulk<<<dim3(cdiv(M0, 128), 2), 256, SM_TOTAL>>>(ga);

    zero_stats_kernel<<<1, H>>>();
    bn_stats_kernel<<<cdiv(M0, 128), H>>>(H0, M0);
    bn_finalize_kernel<<<1, H>>>(g0, be0, 1.0f / M0);
    bn_apply_kernel<<<cdiv((long)M0 * H, 256), 256>>>(H0, M0, 0, 1);

    // ---- layer 1 ----
    hist_kernel<<<cdiv(E1, 256), 256>>>(dst1, E1, cnt);
    scan_kernel<<<1, 1024>>>(cnt, off, cur, M1);
    scatter_kernel<<<cdiv(E1, 256), 256>>>(src1, dst1, et1, E1, cur, eidx);
    gather_kernel<<<M1, 64>>>(H0, eidx, off, cnt, A1, M1, LDA);

    ga.A = A1;  ga.aseg = (long)M1 * LDA;
    ga.W = Wt + (size_t)6 * 256 * LDA;
    ga.nseg = NSEG;  ga.M = M1;  ga.bias = b1;  ga.C = H1;
    gemm_bulk<<<dim3(cdiv(M1, 128), 2), 256, SM_TOTAL>>>(ga);

    zero_stats_kernel<<<1, H>>>();
    bn_stats_kernel<<<cdiv(M1, 128), H>>>(H1, M1);
    bn_finalize_kernel<<<1, H>>>(g1, be1, 1.0f / M1);
    bn_apply_kernel<<<cdiv((long)M1 * H, 256), 256>>>(H1, M1, 0, 1);

    // ---- MLP head ----
    ga.A = H1;  ga.aseg = 0;
    ga.W = Wt + (size_t)12 * 256 * LDA;
    ga.nseg = 1;  ga.M = M1;  ga.bias = bm1;  ga.C = Mh;
    gemm_bulk<<<dim3(cdiv(M1, 128), 2), 256, SM_TOTAL>>>(ga);

    zero_stats_kernel<<<1, H>>>();
    bn_stats_kernel<<<cdiv(M1, 128), H>>>(Mh, M1);
    bn_finalize_kernel<<<1, H>>>(gm, bem, 1.0f / M1);
    bn_apply_kernel<<<cdiv((long)M1 * H, 256), 256>>>(Mh, M1, 1, 0);

    GemmArgs gf;
    gf.A = Mh;  gf.W = Wm2;
    gf.M = M1;  gf.N = COUT;  gf.bias = bm2;  gf.C = out;
    gemm_kernel<<<dim3(cdiv(M1, 64), cdiv(COUT, 64)), 256>>>(gf);
}

// round 11
// speedup vs baseline: 1.9890x; 1.0240x over previous
#include <cuda_runtime.h>
#include <math.h>
#include <stdint.h>

#define H 256
#define RREL 5
#define NSEG 6            // 5 relations + self-loop
#define M0_CONST 50000
#define M1_CONST 10000
#define E0_MAX 800000
#define LDA 260           // padded row stride (floats); 1040B: 16B-aligned, conflict-free ldmatrix

// ---------------- scratch (device globals: allocation-free) ----------------
__device__ float g_A0[((size_t)NSEG * M0_CONST + 128) * LDA];
__device__ float g_A1[((size_t)NSEG * M1_CONST + 128) * LDA];
__device__ float g_H0[((size_t)M0_CONST + 128) * LDA];
__device__ float g_H1[((size_t)M1_CONST + 128) * LDA];
__device__ float g_Mh[((size_t)M1_CONST + 128) * LDA];
__device__ float g_Wt[(size_t)13 * 256 * LDA];   // [mat][n][k] transposed, tf32-rounded
__device__ int   g_cnt[M0_CONST + 4];
__device__ int   g_off[M0_CONST + 4];
__device__ int   g_cur[M0_CONST + 4];
__device__ int   g_eidx[E0_MAX];
__device__ float g_sum[H];
__device__ float g_sumsq[H];
__device__ float g_scale[H];
__device__ float g_shift[H];

// ---------------- helpers ----------------
__device__ __forceinline__ uint32_t f2tf32(float v) {
    uint32_t t;
    asm("cvt.rna.tf32.f32 %0, %1;" : "=r"(t) : "f"(v));
    return t;
}
__device__ __forceinline__ float rtf(float v) { return __uint_as_float(f2tf32(v)); }

__device__ __forceinline__ uint32_t smem_u32(const void* p) {
    uint32_t a;
    asm("{ .reg .u64 t; cvta.to.shared.u64 t, %1; cvt.u32.u64 %0, t; }"
        : "=r"(a) : "l"(p));
    return a;
}

#define MBAR_INIT(addr, cnt)                                                   \
    asm volatile("mbarrier.init.shared.b64 [%0], %1;" :: "r"(addr), "r"(cnt) : "memory")

#define MBAR_EXPECT(addr, bytes)                                               \
    asm volatile("mbarrier.arrive.expect_tx.shared.b64 _, [%0], %1;"           \
                 :: "r"(addr), "r"(bytes) : "memory")

#define BULK_G2S(dst, src, bytes, mbar)                                        \
    asm volatile(                                                              \
        "cp.async.bulk.shared::cluster.global.mbarrier::complete_tx::bytes "   \
        "[%0], [%1], %2, [%3];"                                                \
        :: "r"(dst), "l"(src), "r"(bytes), "r"(mbar) : "memory")

#define NAMED_BAR(id)                                                          \
    asm volatile("bar.sync %0, 128;" :: "r"(id) : "memory")

__device__ __forceinline__ void mbar_wait(uint32_t mbar, uint32_t parity) {
    uint32_t done;
    asm volatile(
        "{\n\t.reg .pred p;\n\t"
        "mbarrier.try_wait.parity.acquire.cta.shared::cta.b64 p, [%1], %2;\n\t"
        "selp.b32 %0, 1, 0, p;\n\t}"
        : "=r"(done) : "r"(mbar), "r"(parity) : "memory");
    if (!done) {
        asm volatile(
            "{\n\t.reg .pred P1;\n\t"
            "W_%=:\n\t"
            "mbarrier.try_wait.parity.acquire.cta.shared::cta.b64 P1, [%0], %1, 0x989680;\n\t"
            "@P1 bra.uni D_%=;\n\t"
            "bra.uni W_%=;\n\t"
            "D_%=:\n\t}"
            :: "r"(mbar), "r"(parity) : "memory");
    }
}

// ---------------- CSR build (dst-keyed, relation packed into eidx) --------
__global__ void hist_kernel(const int* __restrict__ dst, int E, int* __restrict__ cnt) {
    int e = blockIdx.x * 256 + threadIdx.x;
    if (e < E) atomicAdd(&cnt[dst[e]], 1);
}

__global__ void scan_kernel(const int* __restrict__ cnt, int* __restrict__ off,
                            int* __restrict__ cur, int n) {
    __shared__ int part[1024];
    int t = threadIdx.x;
    int chunk = (n + 1023) >> 10;
    int a = t * chunk;
    int b = min(a + chunk, n);
    int s = 0;
#pragma unroll 4
    for (int i = a; i < b; i++) s += cnt[i];
    part[t] = s;
    __syncthreads();
    for (int d = 1; d < 1024; d <<= 1) {
        int v = (t >= d) ? part[t - d] : 0;
        __syncthreads();
        part[t] += v;
        __syncthreads();
    }
    int run = (t == 0) ? 0 : part[t - 1];
    for (int i = a; i < b; i++) { off[i] = run; cur[i] = run; run += cnt[i]; }
    if (b == n) off[n] = run;
}

__global__ void scatter_kernel(const int* __restrict__ src, const int* __restrict__ dst,
                               const int* __restrict__ et, int E,
                               int* __restrict__ cur, int* __restrict__ eidx) {
    int e = blockIdx.x * 256 + threadIdx.x;
    if (e < E) {
        int p = atomicAdd(&cur[dst[e]], 1);
        eidx[p] = (et[e] << 24) | src[e];
    }
}

// One block (64 thr) per dst node; thread t owns channels [4t, 4t+4).
// Edge loop unrolled x2 for memory-level parallelism.
__global__ void gather_kernel(const float* __restrict__ x, const int* __restrict__ eidx,
                              const int* __restrict__ off, int* __restrict__ cnt,
                              float* __restrict__ A, int ndst, int src_lda) {
    int d = blockIdx.x;
    int t = threadIdx.x;          // 0..63
    int c = t * 4;
    int beg = off[d], end = off[d + 1];
    float4 a0 = make_float4(0.f, 0.f, 0.f, 0.f);
    float4 a1 = a0, a2 = a0, a3 = a0, a4 = a0;
#define ACCUM(pk_, v_)                                                         \
    {                                                                          \
        int r_ = (pk_) >> 24;                                                  \
        if (r_ == 0) { a0.x += (v_).x; a0.y += (v_).y; a0.z += (v_).z; a0.w += (v_).w; } \
        if (r_ == 1) { a1.x += (v_).x; a1.y += (v_).y; a1.z += (v_).z; a1.w += (v_).w; } \
        if (r_ == 2) { a2.x += (v_).x; a2.y += (v_).y; a2.z += (v_).z; a2.w += (v_).w; } \
        if (r_ == 3) { a3.x += (v_).x; a3.y += (v_).y; a3.z += (v_).z; a3.w += (v_).w; } \
        if (r_ == 4) { a4.x += (v_).x; a4.y += (v_).y; a4.z += (v_).z; a4.w += (v_).w; } \
    }
    int i = beg;
    for (; i + 1 < end; i += 2) {
        int pk0 = eidx[i];
        int pk1 = eidx[i + 1];
        float4 v0 = *(const float4*)(x + (size_t)(pk0 & 0xFFFFFF) * src_lda + c);
        float4 v1 = *(const float4*)(x + (size_t)(pk1 & 0xFFFFFF) * src_lda + c);
        ACCUM(pk0, v0);
        ACCUM(pk1, v1);
    }
    if (i < end) {
        int pk0 = eidx[i];
        float4 v0 = *(const float4*)(x + (size_t)(pk0 & 0xFFFFFF) * src_lda + c);
        ACCUM(pk0, v0);
    }
    size_t base = (size_t)d * LDA + c;
    size_t seg = (size_t)ndst * LDA;
#define RSTORE(k, av)                                                          \
    {                                                                          \
        float4 o;                                                              \
        o.x = rtf((av).x); o.y = rtf((av).y);                                  \
        o.z = rtf((av).z); o.w = rtf((av).w);                                  \
        *(float4*)(A + base + (size_t)(k) * seg) = o;                          \
    }
    RSTORE(0, a0); RSTORE(1, a1); RSTORE(2, a2); RSTORE(3, a3); RSTORE(4, a4);
    float4 sv = *(const float4*)(x + (size_t)d * src_lda + c);
    RSTORE(5, sv);
    if (t == 0) cnt[d] = 0;
}

// ---------------- weight transpose (one-shot per launch, tf32-rounded) ----
__global__ void transpose_weights(const float* W0, const float* Wl0,
                                  const float* W1, const float* Wl1,
                                  const float* Wm1) {
    __shared__ float t[32][33];
    int m = blockIdx.x;
    const float* src = (m < 5)   ? W0 + (size_t)m * H * H
                     : (m == 5)  ? Wl0
                     : (m < 11)  ? W1 + (size_t)(m - 6) * H * H
                     : (m == 11) ? Wl1 : Wm1;
    float* dst = g_Wt + (size_t)m * 256 * LDA;
    int bx = blockIdx.y * 32, by = blockIdx.z * 32;
    int x = threadIdx.x, y = threadIdx.y;
#pragma unroll
    for (int i = 0; i < 32; i += 8)
        t[y + i][x] = src[(size_t)(by + y + i) * H + bx + x];
    __syncthreads();
#pragma unroll
    for (int i = 0; i < 32; i += 8)
        dst[(size_t)(bx + y + i) * LDA + by + x] = rtf(t[x][y + i]);
}

// ---------------- tf32 tensor GEMM via cp.async.bulk, dual-group ----------
// C[M,256] = sum_s A_s[M,256] @ Wt_s^T + bias.  CTA 128m x 128n; seg-outer.
// Warps 0-3 (group 0) process m-chunks {0,2} in buf0; warps 4-7 (group 1)
// chunks {1,3} in buf1. Warp tile m32 x n32 (acc 64 regs) cuts LDS traffic
// 33% vs m16 x n32. Group-private named barriers allow each group to refill
// its own A buffer mid-seg. B panel: 4 x 32-row chunks, per-chunk mbarriers.
struct TGArgs {
    const float* A; long aseg;   // segment stride in floats
    const float* W;              // base of nseg padded [256][LDA] matrices
    int nseg; int M;
    const float* bias;
    float* C;                    // padded (LDA)
};

#define CH_ROWS 32
#define CH_BYTES (CH_ROWS * LDA * 4)     // 33280
#define SM_A0 1024
#define SM_A1 (1024 + CH_BYTES)
#define SM_B  (1024 + 2 * CH_BYTES)
#define SM_TOTAL (1024 + 2 * CH_BYTES + 128 * LDA * 4)   // 200704
// mbarriers: A-buf g @ sb+8g, B chunk c @ sb+16+8c

// warp computes m32 x n32 of one chunk; acc[im 0..1][in 0..3][4]
__device__ __forceinline__ void mma32(uint32_t ab, uint32_t bb,
                                      int wq, int rowl, int khalf,
                                      float (*acc)[4][4]) {
#pragma unroll 4
    for (int kq = 0; kq < 32; kq++) {
        int q = kq * 8 + khalf;
        uint32_t a[2][4], b[2][4];
#pragma unroll
        for (int im = 0; im < 2; im++) {
            uint32_t ad = ab + (((im * 16 + rowl) * LDA + q) << 2);
            asm volatile(
                "ldmatrix.sync.aligned.m8n8.x4.shared.b16 {%0,%1,%2,%3}, [%4];"
                : "=r"(a[im][0]), "=r"(a[im][1]), "=r"(a[im][2]), "=r"(a[im][3])
                : "r"(ad));
        }
#pragma unroll
        for (int i2 = 0; i2 < 2; i2++) {
            uint32_t bd = bb + (((wq * 32 + i2 * 16 + rowl) * LDA + q) << 2);
            asm volatile(
                "ldmatrix.sync.aligned.m8n8.x4.shared.b16 {%0,%1,%2,%3}, [%4];"
                : "=r"(b[i2][0]), "=r"(b[i2][1]), "=r"(b[i2][2]), "=r"(b[i2][3])
                : "r"(bd));
        }
#pragma unroll
        for (int im = 0; im < 2; im++)
#pragma unroll
            for (int in_ = 0; in_ < 4; in_++) {
                int i2 = in_ >> 1, p = in_ & 1;
                asm volatile(
                    "mma.sync.aligned.m16n8k8.row.col.f32.tf32.tf32.f32 "
                    "{%0,%1,%2,%3}, {%4,%5,%6,%7}, {%8,%9}, {%0,%1,%2,%3};\n"
                    : "+f"(acc[im][in_][0]), "+f"(acc[im][in_][1]),
                      "+f"(acc[im][in_][2]), "+f"(acc[im][in_][3])
                    : "r"(a[im][0]), "r"(a[im][1]), "r"(a[im][2]), "r"(a[im][3]),
                      "r"(b[i2][p]), "r"(b[i2][2 + p]));
            }
    }
}

__global__ void __launch_bounds__(256, 1) gemm_bulk(TGArgs g) {
    extern __shared__ char sm[];
    uint32_t sb = smem_u32(sm);
    int tid = threadIdx.x, warp = tid >> 5, lane = tid & 31;
    int gidx = warp >> 2;         // group 0/1 -> A buf, chunks {g, g+2}
    int wq = warp & 3;            // n quarter == B chunk id
    int m0 = blockIdx.x * 128, n0 = blockIdx.y * 128;
    int rowl = lane & 15, khalf = (lane >> 4) * 4;
    int lr = lane >> 2, lc = lane & 3;
    uint32_t myB = sb + 16 + 8 * wq;
    uint32_t mbarA = sb + 8 * gidx;
    uint32_t bufA = sb + (gidx ? SM_A1 : SM_A0);
    int barid = 1 + gidx;
    bool leader = (tid == gidx * 128);
    uint32_t bb = sb + SM_B;

    if (tid == 0) {
        MBAR_INIT(sb + 0, 1);
        MBAR_INIT(sb + 8, 1);
#pragma unroll
        for (int c = 0; c < 4; c++) MBAR_INIT(sb + 16 + 8 * c, 1);
    }
    __syncthreads();

    float acc[2][2][4][4];        // [ci][im][in][reg]
#pragma unroll
    for (int ci = 0; ci < 2; ci++)
#pragma unroll
        for (int im = 0; im < 2; im++)
#pragma unroll
            for (int j = 0; j < 4; j++)
#pragma unroll
                for (int k = 0; k < 4; k++) acc[ci][im][j][k] = 0.f;

    // prologue: seg 0 loads
    {
        const float* asrc0 = g.A + (size_t)m0 * LDA;
        if (tid == 0) {
            const float* bsrc = g.W + (size_t)n0 * LDA;
#pragma unroll
            for (int c = 0; c < 4; c++) {
                MBAR_EXPECT(sb + 16 + 8 * c, CH_BYTES);
                BULK_G2S(sb + SM_B + c * CH_BYTES, bsrc + (size_t)c * CH_ROWS * LDA,
                         CH_BYTES, sb + 16 + 8 * c);
            }
        }
        if (leader) {
            MBAR_EXPECT(mbarA, CH_BYTES);
            BULK_G2S(bufA, asrc0 + (size_t)gidx * CH_ROWS * LDA, CH_BYTES, mbarA);
        }
    }

    int pA = 0, pB = 0;
    for (int seg = 0; seg < g.nseg; seg++) {
        const float* asrc = g.A + (size_t)seg * g.aseg + (size_t)m0 * LDA;
        const float* nasrc = asrc + g.aseg;
        bool more = (seg + 1 < g.nseg);

        // chunk gidx (ci=0)
        mbar_wait(mbarA, pA); pA ^= 1;
        mbar_wait(myB, pB);
        mma32(bufA, bb, wq, rowl, khalf, acc[0]);
        NAMED_BAR(barid);
        if (leader) {
            MBAR_EXPECT(mbarA, CH_BYTES);
            BULK_G2S(bufA, asrc + (size_t)(2 + gidx) * CH_ROWS * LDA, CH_BYTES, mbarA);
        }
        // chunk gidx+2 (ci=1)
        mbar_wait(mbarA, pA); pA ^= 1;
        mma32(bufA, bb, wq, rowl, khalf, acc[1]);
        NAMED_BAR(barid);
        if (leader && more) {
            MBAR_EXPECT(mbarA, CH_BYTES);
            BULK_G2S(bufA, nasrc + (size_t)gidx * CH_ROWS * LDA, CH_BYTES, mbarA);
        }
        __syncthreads();              // all warps done with this seg's B
        if (tid == 0 && more) {
            const float* nbsrc = g.W + ((size_t)(seg + 1) * 256 + n0) * LDA;
#pragma unroll
            for (int c = 0; c < 4; c++) {
                MBAR_EXPECT(sb + 16 + 8 * c, CH_BYTES);
                BULK_G2S(sb + SM_B + c * CH_BYTES, nbsrc + (size_t)c * CH_ROWS * LDA,
                         CH_BYTES, sb + 16 + 8 * c);
            }
        }
        pB ^= 1;
    }

    // ---- epilogue: bias + store (padded C) ----
#pragma unroll
    for (int ci = 0; ci < 2; ci++) {
        int mbase = m0 + (ci * 2 + gidx) * 32;
#pragma unroll
        for (int im = 0; im < 2; im++) {
            int mrow = mbase + im * 16 + lr;
#pragma unroll
            for (int in_ = 0; in_ < 4; in_++) {
                int col = n0 + wq * 32 + in_ * 8 + lc * 2;
                float bia0 = g.bias[col];
                float bia1 = g.bias[col + 1];
                if (mrow < g.M) {
                    float2 v = make_float2(acc[ci][im][in_][0] + bia0,
                                           acc[ci][im][in_][1] + bia1);
                    *(float2*)(g.C + (size_t)mrow * LDA + col) = v;
                }
                if (mrow + 8 < g.M) {
                    float2 v = make_float2(acc[ci][im][in_][2] + bia0,
                                           acc[ci][im][in_][3] + bia1);
                    *(float2*)(g.C + (size_t)(mrow + 8) * LDA + col) = v;
                }
            }
        }
    }
}

// ---------------- SIMT GEMM (final 256x153 only; A padded, W raw) ---------
struct GemmArgs {
    const float* A;   // lda = LDA
    const float* W;   // [256][N] row-major
    int M, N;
    const float* bias;
    float* C;         // [M][N] dense
};

__global__ void gemm_kernel(GemmArgs g) {
    __shared__ float As[16][65];
    __shared__ float Bs[16][64];

    int tid = threadIdx.x;
    int m0 = blockIdx.x * 64;
    int n0 = blockIdx.y * 64;
    int tm = tid >> 4;
    int tn = tid & 15;

    int lrow = tid >> 2;
    int lk4 = (tid & 3) << 2;
    int lkb = tid >> 4;
    int ln4 = (tid & 15) << 2;

    float acc[4][4];
#pragma unroll
    for (int i = 0; i < 4; i++)
#pragma unroll
        for (int j = 0; j < 4; j++) acc[i][j] = 0.f;

    for (int k0 = 0; k0 < H; k0 += 16) {
        float4 av = make_float4(0.f, 0.f, 0.f, 0.f);
        if (m0 + lrow < g.M)
            av = *(const float4*)(g.A + (size_t)(m0 + lrow) * LDA + k0 + lk4);
        As[lk4 + 0][lrow] = av.x;
        As[lk4 + 1][lrow] = av.y;
        As[lk4 + 2][lrow] = av.z;
        As[lk4 + 3][lrow] = av.w;
        const float* wp = g.W + (size_t)(k0 + lkb) * g.N + n0 + ln4;
        float4 bv;
        bv.x = (n0 + ln4 + 0 < g.N) ? wp[0] : 0.f;
        bv.y = (n0 + ln4 + 1 < g.N) ? wp[1] : 0.f;
        bv.z = (n0 + ln4 + 2 < g.N) ? wp[2] : 0.f;
        bv.w = (n0 + ln4 + 3 < g.N) ? wp[3] : 0.f;
        *(float4*)&Bs[lkb][ln4] = bv;
        __syncthreads();
#pragma unroll
        for (int kk = 0; kk < 16; kk++) {
            float a0 = As[kk][tm * 4 + 0];
            float a1 = As[kk][tm * 4 + 1];
            float a2 = As[kk][tm * 4 + 2];
            float a3 = As[kk][tm * 4 + 3];
            float4 b = *(const float4*)&Bs[kk][tn * 4];
            acc[0][0] += a0 * b.x; acc[0][1] += a0 * b.y; acc[0][2] += a0 * b.z; acc[0][3] += a0 * b.w;
            acc[1][0] += a1 * b.x; acc[1][1] += a1 * b.y; acc[1][2] += a1 * b.z; acc[1][3] += a1 * b.w;
            acc[2][0] += a2 * b.x; acc[2][1] += a2 * b.y; acc[2][2] += a2 * b.z; acc[2][3] += a2 * b.w;
            acc[3][0] += a3 * b.x; acc[3][1] += a3 * b.y; acc[3][2] += a3 * b.z; acc[3][3] += a3 * b.w;
        }
        __syncthreads();
    }

#pragma unroll
    for (int i = 0; i < 4; i++) {
        int m = m0 + tm * 4 + i;
        if (m >= g.M) continue;
#pragma unroll
        for (int j = 0; j < 4; j++) {
            int n = n0 + tn * 4 + j;
            if (n < g.N) g.C[(size_t)m * g.N + n] = acc[i][j] + g.bias[n];
        }
    }
}

// ---------------- BN kernels (padded rows) ----------------
__global__ void zero_stats_kernel() {
    g_sum[threadIdx.x] = 0.f;
    g_sumsq[threadIdx.x] = 0.f;
}

__global__ void bn_stats_kernel(const float* __restrict__ h, int M) {
    int col = threadIdx.x;
    int r0 = blockIdx.x * 128;
    int rend = min(r0 + 128, M);
    float s = 0.f, s2 = 0.f;
    for (int r = r0; r < rend; r++) {
        float v = h[(size_t)r * LDA + col];
        s += v;
        s2 += v * v;
    }
    atomicAdd(&g_sum[col], s);
    atomicAdd(&g_sumsq[col], s2);
}

__global__ void bn_finalize_kernel(const float* __restrict__ gamma,
                                   const float* __restrict__ beta, float invM) {
    int col = threadIdx.x;
    float mean = g_sum[col] * invM;
    float var = g_sumsq[col] * invM - mean * mean;
    float sc = gamma[col] * rsqrtf(var + 1e-5f);
    g_scale[col] = sc;
    g_shift[col] = beta[col] - mean * sc;
}

// act 0 = ELU, 1 = ReLU; rnd -> round to tf32 for tensor-GEMM consumers
__global__ void bn_apply_kernel(float* __restrict__ h, int M, int act, int rnd) {
    long i = (long)blockIdx.x * blockDim.x + threadIdx.x;
    if (i >= (long)M * H) return;
    int col = (int)(i & (H - 1));
    long row = i >> 8;
    float v = h[row * LDA + col] * g_scale[col] + g_shift[col];
    if (act == 0)
        v = (v > 0.f) ? v : expm1f(v);
    else
        v = (v > 0.f) ? v : 0.f;
    if (rnd) v = rtf(v);
    h[row * LDA + col] = v;
}

// ---------------- host orchestration ----------------
static inline int cdiv(long a, long b) { return (int)((a + b - 1) / b); }

extern "C" void kernel_launch(void* const* d_in, const int* in_sizes, int n_in,
                              void* d_out, int out_size) {
    const float* x   = (const float*)d_in[0];
    const int* src0  = (const int*)d_in[1];
    const int* dst0  = (const int*)d_in[2];
    const int* et0   = (const int*)d_in[3];
    const int* src1  = (const int*)d_in[4];
    const int* dst1  = (const int*)d_in[5];
    const int* et1   = (const int*)d_in[6];
    const float* W0  = (const float*)d_in[9];
    const float* Wl0 = (const float*)d_in[10];
    const float* b0  = (const float*)d_in[11];
    const float* g0  = (const float*)d_in[12];
    const float* be0 = (const float*)d_in[13];
    const float* W1  = (const float*)d_in[14];
    const float* Wl1 = (const float*)d_in[15];
    const float* b1  = (const float*)d_in[16];
    const float* g1  = (const float*)d_in[17];
    const float* be1 = (const float*)d_in[18];
    const float* Wm1 = (const float*)d_in[19];
    const float* bm1 = (const float*)d_in[20];
    const float* gm  = (const float*)d_in[21];
    const float* bem = (const float*)d_in[22];
    const float* Wm2 = (const float*)d_in[23];
    const float* bm2 = (const float*)d_in[24];
    float* out = (float*)d_out;

    const int E0 = in_sizes[1];
    const int E1 = in_sizes[4];
    const int COUT = 153;
    const int M1 = out_size / COUT;   // 10000
    const int M0 = M0_CONST;          // 50000

    float *A0, *A1, *H0, *H1, *Mh, *Wt;
    int *cnt, *off, *cur, *eidx;
    cudaGetSymbolAddress((void**)&A0, g_A0);
    cudaGetSymbolAddress((void**)&A1, g_A1);
    cudaGetSymbolAddress((void**)&H0, g_H0);
    cudaGetSymbolAddress((void**)&H1, g_H1);
    cudaGetSymbolAddress((void**)&Mh, g_Mh);
    cudaGetSymbolAddress((void**)&Wt, g_Wt);
    cudaGetSymbolAddress((void**)&cnt, g_cnt);
    cudaGetSymbolAddress((void**)&off, g_off);
    cudaGetSymbolAddress((void**)&cur, g_cur);
    cudaGetSymbolAddress((void**)&eidx, g_eidx);

    cudaFuncSetAttribute(gemm_bulk,
                         cudaFuncAttributeMaxDynamicSharedMemorySize, SM_TOTAL);

    // ---- layer 0: CSR + gather (profiled slot 3) + bulk GEMM ----
    hist_kernel<<<cdiv(E0, 256), 256>>>(dst0, E0, cnt);                     // 0
    scan_kernel<<<1, 1024>>>(cnt, off, cur, M0);                            // 1
    scatter_kernel<<<cdiv(E0, 256), 256>>>(src0, dst0, et0, E0, cur, eidx); // 2
    gather_kernel<<<M0, 64>>>(x, eidx, off, cnt, A0, M0, H);                // 3 <- profiled
    transpose_weights<<<dim3(13, 8, 8), dim3(32, 8)>>>(W0, Wl0, W1, Wl1, Wm1);

    TGArgs ga;
    ga.A = A0;  ga.aseg = (long)M0 * LDA;
    ga.W = Wt;  ga.nseg = NSEG;  ga.M = M0;  ga.bias = b0;  ga.C = H0;
    gemm_bulk<<<dim3(cdiv(M0, 128), 2), 256, SM_TOTAL>>>(ga);

    zero_stats_kernel<<<1, H>>>();
    bn_stats_kernel<<<cdiv(M0, 128), H>>>(H0, M0);
    bn_finalize_kernel<<<1, H>>>(g0, be0, 1.0f / M0);
    bn_apply_kernel<<<cdiv((long)M0 * H, 256), 256>>>(H0, M0, 0, 1);

    // ---- layer 1 ----
    hist_kernel<<<cdiv(E1, 256), 256>>>(dst1, E1, cnt);
    scan_kernel<<<1, 1024>>>(cnt, off, cur, M1);
    scatter_kernel<<<cdiv(E1, 256), 256>>>(src1, dst1, et1, E1, cur, eidx);
    gather_kernel<<<M1, 64>>>(H0, eidx, off, cnt, A1, M1, LDA);

    ga.A = A1;  ga.aseg = (long)M1 * LDA;
    ga.W = Wt + (size_t)6 * 256 * LDA;
    ga.nseg = NSEG;  ga.M = M1;  ga.bias = b1;  ga.C = H1;
    gemm_bulk<<<dim3(cdiv(M1, 128), 2), 256, SM_TOTAL>>>(ga);

    zero_stats_kernel<<<1, H>>>();
    bn_stats_kernel<<<cdiv(M1, 128), H>>>(H1, M1);
    bn_finalize_kernel<<<1, H>>>(g1, be1, 1.0f / M1);
    bn_apply_kernel<<<cdiv((long)M1 * H, 256), 256>>>(H1, M1, 0, 1);

    // ---- MLP head ----
    ga.A = H1;  ga.aseg = 0;
    ga.W = Wt + (size_t)12 * 256 * LDA;
    ga.nseg = 1;  ga.M = M1;  ga.bias = bm1;  ga.C = Mh;
    gemm_bulk<<<dim3(cdiv(M1, 128), 2), 256, SM_TOTAL>>>(ga);

    zero_stats_kernel<<<1, H>>>();
    bn_stats_kernel<<<cdiv(M1, 128), H>>>(Mh, M1);
    bn_finalize_kernel<<<1, H>>>(gm, bem, 1.0f / M1);
    bn_apply_kernel<<<cdiv((long)M1 * H, 256), 256>>>(Mh, M1, 1, 0);

    GemmArgs gf;
    gf.A = Mh;  gf.W = Wm2;
    gf.M = M1;  gf.N = COUT;  gf.bias = bm2;  gf.C = out;
    gemm_kernel<<<dim3(cdiv(M1, 64), cdiv(COUT, 64)), 256>>>(gf);
}

// round 12
// speedup vs baseline: 2.0778x; 1.0447x over previous
#include <cuda_runtime.h>
#include <math.h>
#include <stdint.h>

#define H 256
#define RREL 5
#define NSEG 6            // 5 relations + self-loop
#define M0_CONST 50000
#define M1_CONST 10000
#define M0P 50048         // padded to 128
#define M1P 10112
#define E0_MAX 800000
#define KP 132            // padded half-K row stride (floats); 528B, conflict-free ldmatrix

// ---------------- scratch (device globals: allocation-free) ----------------
// GEMM operand layout: half-K planes [plane][row][KP], plane = seg*2 + kh.
__device__ float g_A0[(size_t)NSEG * 2 * M0P * KP];
__device__ float g_A1[(size_t)NSEG * 2 * M1P * KP];
__device__ float g_H0[(size_t)2 * M0P * KP];
__device__ float g_H1[(size_t)2 * M1P * KP];
__device__ float g_Mh[(size_t)2 * M1P * KP];
__device__ float g_Wt[(size_t)13 * 2 * 256 * KP];  // [mat][kh][n][KP], tf32-rounded
__device__ int   g_cnt[M0_CONST + 4];
__device__ int   g_off[M0_CONST + 4];
__device__ int   g_cur[M0_CONST + 4];
__device__ int   g_eidx[E0_MAX];
__device__ float g_sum[H];
__device__ float g_sumsq[H];
__device__ float g_scale[H];
__device__ float g_shift[H];

// ---------------- helpers ----------------
__device__ __forceinline__ uint32_t f2tf32(float v) {
    uint32_t t;
    asm("cvt.rna.tf32.f32 %0, %1;" : "=r"(t) : "f"(v));
    return t;
}
__device__ __forceinline__ float rtf(float v) { return __uint_as_float(f2tf32(v)); }

__device__ __forceinline__ uint32_t smem_u32(const void* p) {
    uint32_t a;
    asm("{ .reg .u64 t; cvta.to.shared.u64 t, %1; cvt.u32.u64 %0, t; }"
        : "=r"(a) : "l"(p));
    return a;
}

#define MBAR_INIT(addr, cnt)                                                   \
    asm volatile("mbarrier.init.shared.b64 [%0], %1;" :: "r"(addr), "r"(cnt) : "memory")

#define MBAR_EXPECT(addr, bytes)                                               \
    asm volatile("mbarrier.arrive.expect_tx.shared.b64 _, [%0], %1;"           \
                 :: "r"(addr), "r"(bytes) : "memory")

#define BULK_G2S(dst, src, bytes, mbar)                                        \
    asm volatile(                                                              \
        "cp.async.bulk.shared::cluster.global.mbarrier::complete_tx::bytes "   \
        "[%0], [%1], %2, [%3];"                                                \
        :: "r"(dst), "l"(src), "r"(bytes), "r"(mbar) : "memory")

#define NAMED_BAR(id)                                                          \
    asm volatile("bar.sync %0, 128;" :: "r"(id) : "memory")

__device__ __forceinline__ void mbar_wait(uint32_t mbar, uint32_t parity) {
    uint32_t done;
    asm volatile(
        "{\n\t.reg .pred p;\n\t"
        "mbarrier.try_wait.parity.acquire.cta.shared::cta.b64 p, [%1], %2;\n\t"
        "selp.b32 %0, 1, 0, p;\n\t}"
        : "=r"(done) : "r"(mbar), "r"(parity) : "memory");
    if (!done) {
        asm volatile(
            "{\n\t.reg .pred P1;\n\t"
            "W_%=:\n\t"
            "mbarrier.try_wait.parity.acquire.cta.shared::cta.b64 P1, [%0], %1, 0x989680;\n\t"
            "@P1 bra.uni D_%=;\n\t"
            "bra.uni W_%=;\n\t"
            "D_%=:\n\t}"
            :: "r"(mbar), "r"(parity) : "memory");
    }
}

// ---------------- CSR build (dst-keyed, relation packed into eidx) --------
__global__ void hist_kernel(const int* __restrict__ dst, int E, int* __restrict__ cnt) {
    int e = blockIdx.x * 256 + threadIdx.x;
    if (e < E) atomicAdd(&cnt[dst[e]], 1);
}

__global__ void scan_kernel(const int* __restrict__ cnt, int* __restrict__ off,
                            int* __restrict__ cur, int n) {
    __shared__ int part[1024];
    int t = threadIdx.x;
    int chunk = (n + 1023) >> 10;
    int a = t * chunk;
    int b = min(a + chunk, n);
    int s = 0;
#pragma unroll 4
    for (int i = a; i < b; i++) s += cnt[i];
    part[t] = s;
    __syncthreads();
    for (int d = 1; d < 1024; d <<= 1) {
        int v = (t >= d) ? part[t - d] : 0;
        __syncthreads();
        part[t] += v;
        __syncthreads();
    }
    int run = (t == 0) ? 0 : part[t - 1];
    for (int i = a; i < b; i++) { off[i] = run; cur[i] = run; run += cnt[i]; }
    if (b == n) off[n] = run;
}

__global__ void scatter_kernel(const int* __restrict__ src, const int* __restrict__ dst,
                               const int* __restrict__ et, int E,
                               int* __restrict__ cur, int* __restrict__ eidx) {
    int e = blockIdx.x * 256 + threadIdx.x;
    if (e < E) {
        int p = atomicAdd(&cur[dst[e]], 1);
        eidx[p] = (et[e] << 24) | src[e];
    }
}

// One block (64 thr) per dst node; thread t owns channels [4t, 4t+4).
// Source rows addressed via (lda, khstr): dense x -> lda=256, khstr=128;
// plane-layout H -> lda=KP, khstr=MP*KP. Writes A planes [seg*2+kh][d][KP].
__global__ void gather_kernel(const float* __restrict__ x, const int* __restrict__ eidx,
                              const int* __restrict__ off, int* __restrict__ cnt,
                              float* __restrict__ A, long ndstp,
                              long src_lda, long src_khstr) {
    int d = blockIdx.x;
    int t = threadIdx.x;          // 0..63
    int c = t * 4;
    int kh = c >> 7;
    int inner = c & 127;
    long srcoff = (long)kh * src_khstr + inner;
    int beg = off[d], end = off[d + 1];
    float4 a0 = make_float4(0.f, 0.f, 0.f, 0.f);
    float4 a1 = a0, a2 = a0, a3 = a0, a4 = a0;
#define ACCUM(pk_, v_)                                                         \
    {                                                                          \
        int r_ = (pk_) >> 24;                                                  \
        if (r_ == 0) { a0.x += (v_).x; a0.y += (v_).y; a0.z += (v_).z; a0.w += (v_).w; } \
        if (r_ == 1) { a1.x += (v_).x; a1.y += (v_).y; a1.z += (v_).z; a1.w += (v_).w; } \
        if (r_ == 2) { a2.x += (v_).x; a2.y += (v_).y; a2.z += (v_).z; a2.w += (v_).w; } \
        if (r_ == 3) { a3.x += (v_).x; a3.y += (v_).y; a3.z += (v_).z; a3.w += (v_).w; } \
        if (r_ == 4) { a4.x += (v_).x; a4.y += (v_).y; a4.z += (v_).z; a4.w += (v_).w; } \
    }
    int i = beg;
    for (; i + 1 < end; i += 2) {
        int pk0 = eidx[i];
        int pk1 = eidx[i + 1];
        float4 v0 = *(const float4*)(x + (size_t)(pk0 & 0xFFFFFF) * src_lda + srcoff);
        float4 v1 = *(const float4*)(x + (size_t)(pk1 & 0xFFFFFF) * src_lda + srcoff);
        ACCUM(pk0, v0);
        ACCUM(pk1, v1);
    }
    if (i < end) {
        int pk0 = eidx[i];
        float4 v0 = *(const float4*)(x + (size_t)(pk0 & 0xFFFFFF) * src_lda + srcoff);
        ACCUM(pk0, v0);
    }
#define RSTORE(k, av)                                                          \
    {                                                                          \
        float4 o;                                                              \
        o.x = rtf((av).x); o.y = rtf((av).y);                                  \
        o.z = rtf((av).z); o.w = rtf((av).w);                                  \
        *(float4*)(A + ((size_t)((k) * 2 + kh) * ndstp + d) * KP + inner) = o; \
    }
    RSTORE(0, a0); RSTORE(1, a1); RSTORE(2, a2); RSTORE(3, a3); RSTORE(4, a4);
    float4 sv = *(const float4*)(x + (size_t)d * src_lda + srcoff);
    RSTORE(5, sv);
    if (t == 0) cnt[d] = 0;
}

// ---------------- weight transpose (one-shot per launch, tf32-rounded) ----
// Writes Wt[mat][kh][n][KP].
__global__ void transpose_weights(const float* W0, const float* Wl0,
                                  const float* W1, const float* Wl1,
                                  const float* Wm1) {
    __shared__ float t[32][33];
    int m = blockIdx.x;
    const float* src = (m < 5)   ? W0 + (size_t)m * H * H
                     : (m == 5)  ? Wl0
                     : (m < 11)  ? W1 + (size_t)(m - 6) * H * H
                     : (m == 11) ? Wl1 : Wm1;
    float* dst = g_Wt + (size_t)m * 2 * 256 * KP;
    int bx = blockIdx.y * 32, by = blockIdx.z * 32;
    int x = threadIdx.x, y = threadIdx.y;
#pragma unroll
    for (int i = 0; i < 32; i += 8)
        t[y + i][x] = src[(size_t)(by + y + i) * H + bx + x];
    __syncthreads();
#pragma unroll
    for (int i = 0; i < 32; i += 8) {
        int n = bx + y + i;
        int k = by + x;
        dst[((size_t)(k >> 7) * 256 + n) * KP + (k & 127)] = rtf(t[x][y + i]);
    }
}

// ---------------- tf32 tensor GEMM: half-K planes, 2 CTAs/SM --------------
// C[M,256] = sum_s A_s @ Wt_s^T + bias.  CTA 128m x 128n; 12 stages
// (seg x kh). B panel 128n x 128k = 67.6KB single bulk; A chunks 32 rows
// (16.9KB) dual-group. smem 102.4KB -> 2 CTAs/SM for cross-CTA overlap.
struct TGArgs {
    const float* A; long MP;     // plane rows (padded)
    const float* W;              // [nseg][2][256][KP]
    int nseg; int M;
    const float* bias;
    float* C; long CMP;          // C plane rows (padded)
};

#define CH_BYTES (32 * KP * 4)        // 16896
#define B_BYTES  (128 * KP * 4)       // 67584
#define SM_A0 1024
#define SM_A1 (1024 + CH_BYTES)       // 17920
#define SM_B  (1024 + 2 * CH_BYTES)   // 34816
#define SM_TOTAL (SM_B + B_BYTES)     // 102400
// mbarriers: A-buf g @ sb+8g, B @ sb+16

// warp computes m32 x n32 of one chunk over K=128; acc[im][in][4]
__device__ __forceinline__ void mma32(uint32_t ab, uint32_t bb,
                                      int wq, int rowl, int khalf,
                                      float (*acc)[4][4]) {
#pragma unroll 4
    for (int kq = 0; kq < 16; kq++) {
        int q = kq * 8 + khalf;
        uint32_t a[2][4], b[2][4];
#pragma unroll
        for (int im = 0; im < 2; im++) {
            uint32_t ad = ab + (((im * 16 + rowl) * KP + q) << 2);
            asm volatile(
                "ldmatrix.sync.aligned.m8n8.x4.shared.b16 {%0,%1,%2,%3}, [%4];"
                : "=r"(a[im][0]), "=r"(a[im][1]), "=r"(a[im][2]), "=r"(a[im][3])
                : "r"(ad));
        }
#pragma unroll
        for (int i2 = 0; i2 < 2; i2++) {
            uint32_t bd = bb + (((wq * 32 + i2 * 16 + rowl) * KP + q) << 2);
            asm volatile(
                "ldmatrix.sync.aligned.m8n8.x4.shared.b16 {%0,%1,%2,%3}, [%4];"
                : "=r"(b[i2][0]), "=r"(b[i2][1]), "=r"(b[i2][2]), "=r"(b[i2][3])
                : "r"(bd));
        }
#pragma unroll
        for (int im = 0; im < 2; im++)
#pragma unroll
            for (int in_ = 0; in_ < 4; in_++) {
                int i2 = in_ >> 1, p = in_ & 1;
                asm volatile(
                    "mma.sync.aligned.m16n8k8.row.col.f32.tf32.tf32.f32 "
                    "{%0,%1,%2,%3}, {%4,%5,%6,%7}, {%8,%9}, {%0,%1,%2,%3};\n"
                    : "+f"(acc[im][in_][0]), "+f"(acc[im][in_][1]),
                      "+f"(acc[im][in_][2]), "+f"(acc[im][in_][3])
                    : "r"(a[im][0]), "r"(a[im][1]), "r"(a[im][2]), "r"(a[im][3]),
                      "r"(b[i2][p]), "r"(b[i2][2 + p]));
            }
    }
}

__global__ void __launch_bounds__(256, 2) gemm_bulk(TGArgs g) {
    extern __shared__ char sm[];
    uint32_t sb = smem_u32(sm);
    int tid = threadIdx.x, warp = tid >> 5, lane = tid & 31;
    int gidx = warp >> 2;         // group 0/1 -> A buf, chunks {g, g+2}
    int wq = warp & 3;            // n quarter
    int n0 = blockIdx.x * 128;    // n-tile fastest -> same-m CTAs adjacent (L2 A reuse)
    int m0 = blockIdx.y * 128;
    int rowl = lane & 15, khalf = (lane >> 4) * 4;
    int lr = lane >> 2, lc = lane & 3;
    uint32_t mbarA = sb + 8 * gidx;
    uint32_t mbarB = sb + 16;
    uint32_t bufA = sb + (gidx ? SM_A1 : SM_A0);
    uint32_t bb = sb + SM_B;
    int barid = 1 + gidx;
    bool leader = (tid == gidx * 128);
    int nst = g.nseg * 2;

    if (tid == 0) {
        MBAR_INIT(sb + 0, 1);
        MBAR_INIT(sb + 8, 1);
        MBAR_INIT(sb + 16, 1);
    }
    __syncthreads();

    float acc[2][2][4][4];        // [ci][im][in][reg]
#pragma unroll
    for (int ci = 0; ci < 2; ci++)
#pragma unroll
        for (int im = 0; im < 2; im++)
#pragma unroll
            for (int j = 0; j < 4; j++)
#pragma unroll
                for (int k = 0; k < 4; k++) acc[ci][im][j][k] = 0.f;

    // prologue: stage 0
    {
        const float* asrc0 = g.A + (size_t)m0 * KP;
        if (tid == 0) {
            MBAR_EXPECT(mbarB, B_BYTES);
            BULK_G2S(sb + SM_B, g.W + (size_t)n0 * KP, B_BYTES, mbarB);
        }
        if (leader) {
            MBAR_EXPECT(mbarA, CH_BYTES);
            BULK_G2S(bufA, asrc0 + (size_t)gidx * 32 * KP, CH_BYTES, mbarA);
        }
    }

    int pA = 0, pB = 0;
    for (int s = 0; s < nst; s++) {
        const float* asrc = g.A + ((size_t)s * g.MP + m0) * KP;
        const float* nasrc = asrc + (size_t)g.MP * KP;
        bool more = (s + 1 < nst);

        // chunk gidx (ci=0)
        mbar_wait(mbarA, pA); pA ^= 1;
        mbar_wait(mbarB, pB);
        mma32(bufA, bb, wq, rowl, khalf, acc[0]);
        NAMED_BAR(barid);
        if (leader) {
            MBAR_EXPECT(mbarA, CH_BYTES);
            BULK_G2S(bufA, asrc + (size_t)(2 + gidx) * 32 * KP, CH_BYTES, mbarA);
        }
        // chunk gidx+2 (ci=1)
        mbar_wait(mbarA, pA); pA ^= 1;
        mma32(bufA, bb, wq, rowl, khalf, acc[1]);
        NAMED_BAR(barid);
        if (leader && more) {
            MBAR_EXPECT(mbarA, CH_BYTES);
            BULK_G2S(bufA, nasrc + (size_t)gidx * 32 * KP, CH_BYTES, mbarA);
        }
        __syncthreads();              // all warps done with this stage's B
        if (tid == 0 && more) {
            MBAR_EXPECT(mbarB, B_BYTES);
            BULK_G2S(sb + SM_B, g.W + ((size_t)(s + 1) * 256 + n0) * KP,
                     B_BYTES, mbarB);
        }
        pB ^= 1;
    }

    // ---- epilogue: bias + store to C planes ----
#pragma unroll
    for (int ci = 0; ci < 2; ci++) {
        int mbase = m0 + (ci * 2 + gidx) * 32;
#pragma unroll
        for (int im = 0; im < 2; im++) {
            int mrow = mbase + im * 16 + lr;
#pragma unroll
            for (int in_ = 0; in_ < 4; in_++) {
                int col = n0 + wq * 32 + in_ * 8 + lc * 2;
                float* cp = g.C + (size_t)(col >> 7) * g.CMP * KP + (col & 127);
                float bia0 = g.bias[col];
                float bia1 = g.bias[col + 1];
                if (mrow < g.M) {
                    float2 v = make_float2(acc[ci][im][in_][0] + bia0,
                                           acc[ci][im][in_][1] + bia1);
                    *(float2*)(cp + (size_t)mrow * KP) = v;
                }
                if (mrow + 8 < g.M) {
                    float2 v = make_float2(acc[ci][im][in_][2] + bia0,
                                           acc[ci][im][in_][3] + bia1);
                    *(float2*)(cp + (size_t)(mrow + 8) * KP) = v;
                }
            }
        }
    }
}

// ---------------- SIMT GEMM (final 256x153; A in planes, W raw) -----------
struct GemmArgs {
    const float* A;   // planes [2][MP][KP]
    long khstr;       // MP*KP
    const float* W;   // [256][N] row-major
    int M, N;
    const float* bias;
    float* C;         // [M][N] dense
};

__global__ void gemm_kernel(GemmArgs g) {
    __shared__ float As[16][65];
    __shared__ float Bs[16][64];

    int tid = threadIdx.x;
    int m0 = blockIdx.x * 64;
    int n0 = blockIdx.y * 64;
    int tm = tid >> 4;
    int tn = tid & 15;

    int lrow = tid >> 2;
    int lk4 = (tid & 3) << 2;
    int lkb = tid >> 4;
    int ln4 = (tid & 15) << 2;

    float acc[4][4];
#pragma unroll
    for (int i = 0; i < 4; i++)
#pragma unroll
        for (int j = 0; j < 4; j++) acc[i][j] = 0.f;

    for (int k0 = 0; k0 < H; k0 += 16) {
        float4 av = make_float4(0.f, 0.f, 0.f, 0.f);
        if (m0 + lrow < g.M)
            av = *(const float4*)(g.A + (size_t)(k0 >> 7) * g.khstr +
                                  (size_t)(m0 + lrow) * KP + ((k0 + lk4) & 127));
        As[lk4 + 0][lrow] = av.x;
        As[lk4 + 1][lrow] = av.y;
        As[lk4 + 2][lrow] = av.z;
        As[lk4 + 3][lrow] = av.w;
        const float* wp = g.W + (size_t)(k0 + lkb) * g.N + n0 + ln4;
        float4 bv;
        bv.x = (n0 + ln4 + 0 < g.N) ? wp[0] : 0.f;
        bv.y = (n0 + ln4 + 1 < g.N) ? wp[1] : 0.f;
        bv.z = (n0 + ln4 + 2 < g.N) ? wp[2] : 0.f;
        bv.w = (n0 + ln4 + 3 < g.N) ? wp[3] : 0.f;
        *(float4*)&Bs[lkb][ln4] = bv;
        __syncthreads();
#pragma unroll
        for (int kk = 0; kk < 16; kk++) {
            float a0 = As[kk][tm * 4 + 0];
            float a1 = As[kk][tm * 4 + 1];
            float a2 = As[kk][tm * 4 + 2];
            float a3 = As[kk][tm * 4 + 3];
            float4 b = *(const float4*)&Bs[kk][tn * 4];
            acc[0][0] += a0 * b.x; acc[0][1] += a0 * b.y; acc[0][2] += a0 * b.z; acc[0][3] += a0 * b.w;
            acc[1][0] += a1 * b.x; acc[1][1] += a1 * b.y; acc[1][2] += a1 * b.z; acc[1][3] += a1 * b.w;
            acc[2][0] += a2 * b.x; acc[2][1] += a2 * b.y; acc[2][2] += a2 * b.z; acc[2][3] += a2 * b.w;
            acc[3][0] += a3 * b.x; acc[3][1] += a3 * b.y; acc[3][2] += a3 * b.z; acc[3][3] += a3 * b.w;
        }
        __syncthreads();
    }

#pragma unroll
    for (int i = 0; i < 4; i++) {
        int m = m0 + tm * 4 + i;
        if (m >= g.M) continue;
#pragma unroll
        for (int j = 0; j < 4; j++) {
            int n = n0 + tn * 4 + j;
            if (n < g.N) g.C[(size_t)m * g.N + n] = acc[i][j] + g.bias[n];
        }
    }
}

// ---------------- BN kernels (plane layout) ----------------
__global__ void zero_stats_kernel() {
    g_sum[threadIdx.x] = 0.f;
    g_sumsq[threadIdx.x] = 0.f;
}

__global__ void bn_stats_kernel(const float* __restrict__ h, int M, long khstr) {
    int col = threadIdx.x;
    const float* hp = h + (size_t)(col >> 7) * khstr + (col & 127);
    int r0 = blockIdx.x * 128;
    int rend = min(r0 + 128, M);
    float s = 0.f, s2 = 0.f;
    for (int r = r0; r < rend; r++) {
        float v = hp[(size_t)r * KP];
        s += v;
        s2 += v * v;
    }
    atomicAdd(&g_sum[col], s);
    atomicAdd(&g_sumsq[col], s2);
}

__global__ void bn_finalize_kernel(const float* __restrict__ gamma,
                                   const float* __restrict__ beta, float invM) {
    int col = threadIdx.x;
    float mean = g_sum[col] * invM;
    float var = g_sumsq[col] * invM - mean * mean;
    float sc = gamma[col] * rsqrtf(var + 1e-5f);
    g_scale[col] = sc;
    g_shift[col] = beta[col] - mean * sc;
}

// act 0 = ELU, 1 = ReLU; rnd -> round to tf32 for tensor-GEMM consumers
__global__ void bn_apply_kernel(float* __restrict__ h, int M, long khstr,
                                int act, int rnd) {
    long i = (long)blockIdx.x * blockDim.x + threadIdx.x;
    if (i >= (long)M * H) return;
    int col = (int)(i & (H - 1));
    long row = i >> 8;
    float* hp = h + (size_t)(col >> 7) * khstr + row * KP + (col & 127);
    float v = *hp * g_scale[col] + g_shift[col];
    if (act == 0)
        v = (v > 0.f) ? v : expm1f(v);
    else
        v = (v > 0.f) ? v : 0.f;
    if (rnd) v = rtf(v);
    *hp = v;
}

// ---------------- host orchestration ----------------
static inline int cdiv(long a, long b) { return (int)((a + b - 1) / b); }

extern "C" void kernel_launch(void* const* d_in, const int* in_sizes, int n_in,
                              void* d_out, int out_size) {
    const float* x   = (const float*)d_in[0];
    const int* src0  = (const int*)d_in[1];
    const int* dst0  = (const int*)d_in[2];
    const int* et0   = (const int*)d_in[3];
    const int* src1  = (const int*)d_in[4];
    const int* dst1  = (const int*)d_in[5];
    const int* et1   = (const int*)d_in[6];
    const float* W0  = (const float*)d_in[9];
    const float* Wl0 = (const float*)d_in[10];
    const float* b0  = (const float*)d_in[11];
    const float* g0  = (const float*)d_in[12];
    const float* be0 = (const float*)d_in[13];
    const float* W1  = (const float*)d_in[14];
    const float* Wl1 = (const float*)d_in[15];
    const float* b1  = (const float*)d_in[16];
    const float* g1  = (const float*)d_in[17];
    const float* be1 = (const float*)d_in[18];
    const float* Wm1 = (const float*)d_in[19];
    const float* bm1 = (const float*)d_in[20];
    const float* gm  = (const float*)d_in[21];
    const float* bem = (const float*)d_in[22];
    const float* Wm2 = (const float*)d_in[23];
    const float* bm2 = (const float*)d_in[24];
    float* out = (float*)d_out;

    const int E0 = in_sizes[1];
    const int E1 = in_sizes[4];
    const int COUT = 153;
    const int M1 = out_size / COUT;   // 10000
    const int M0 = M0_CONST;          // 50000

    float *A0, *A1, *H0, *H1, *Mh, *Wt;
    int *cnt, *off, *cur, *eidx;
    cudaGetSymbolAddress((void**)&A0, g_A0);
    cudaGetSymbolAddress((void**)&A1, g_A1);
    cudaGetSymbolAddress((void**)&H0, g_H0);
    cudaGetSymbolAddress((void**)&H1, g_H1);
    cudaGetSymbolAddress((void**)&Mh, g_Mh);
    cudaGetSymbolAddress((void**)&Wt, g_Wt);
    cudaGetSymbolAddress((void**)&cnt, g_cnt);
    cudaGetSymbolAddress((void**)&off, g_off);
    cudaGetSymbolAddress((void**)&cur, g_cur);
    cudaGetSymbolAddress((void**)&eidx, g_eidx);

    cudaFuncSetAttribute(gemm_bulk,
                         cudaFuncAttributeMaxDynamicSharedMemorySize, SM_TOTAL);

    // ---- layer 0: CSR + gather (profiled slot 3) + GEMM ----
    hist_kernel<<<cdiv(E0, 256), 256>>>(dst0, E0, cnt);                     // 0
    scan_kernel<<<1, 1024>>>(cnt, off, cur, M0);                            // 1
    scatter_kernel<<<cdiv(E0, 256), 256>>>(src0, dst0, et0, E0, cur, eidx); // 2
    gather_kernel<<<M0, 64>>>(x, eidx, off, cnt, A0, M0P, H, 128);          // 3 <- profiled
    transpose_weights<<<dim3(13, 8, 8), dim3(32, 8)>>>(W0, Wl0, W1, Wl1, Wm1);

    TGArgs ga;
    ga.A = A0;  ga.MP = M0P;
    ga.W = Wt;  ga.nseg = NSEG;  ga.M = M0;  ga.bias = b0;
    ga.C = H0;  ga.CMP = M0P;
    gemm_bulk<<<dim3(2, cdiv(M0, 128)), 256, SM_TOTAL>>>(ga);

    zero_stats_kernel<<<1, H>>>();
    bn_stats_kernel<<<cdiv(M0, 128), H>>>(H0, M0, (long)M0P * KP);
    bn_finalize_kernel<<<1, H>>>(g0, be0, 1.0f / M0);
    bn_apply_kernel<<<cdiv((long)M0 * H, 256), 256>>>(H0, M0, (long)M0P * KP, 0, 1);

    // ---- layer 1 ----
    hist_kernel<<<cdiv(E1, 256), 256>>>(dst1, E1, cnt);
    scan_kernel<<<1, 1024>>>(cnt, off, cur, M1);
    scatter_kernel<<<cdiv(E1, 256), 256>>>(src1, dst1, et1, E1, cur, eidx);
    gather_kernel<<<M1, 64>>>(H0, eidx, off, cnt, A1, M1P, KP, (long)M0P * KP);

    ga.A = A1;  ga.MP = M1P;
    ga.W = Wt + (size_t)6 * 2 * 256 * KP;
    ga.nseg = NSEG;  ga.M = M1;  ga.bias = b1;
    ga.C = H1;  ga.CMP = M1P;
    gemm_bulk<<<dim3(2, cdiv(M1, 128)), 256, SM_TOTAL>>>(ga);

    zero_stats_kernel<<<1, H>>>();
    bn_stats_kernel<<<cdiv(M1, 128), H>>>(H1, M1, (long)M1P * KP);
    bn_finalize_kernel<<<1, H>>>(g1, be1, 1.0f / M1);
    bn_apply_kernel<<<cdiv((long)M1 * H, 256), 256>>>(H1, M1, (long)M1P * KP, 0, 1);

    // ---- MLP head ----
    ga.A = H1;  ga.MP = M1P;
    ga.W = Wt + (size_t)12 * 2 * 256 * KP;
    ga.nseg = 1;  ga.M = M1;  ga.bias = bm1;
    ga.C = Mh;  ga.CMP = M1P;
    gemm_bulk<<<dim3(2, cdiv(M1, 128)), 256, SM_TOTAL>>>(ga);

    zero_stats_kernel<<<1, H>>>();
    bn_stats_kernel<<<cdiv(M1, 128), H>>>(Mh, M1, (long)M1P * KP);
    bn_finalize_kernel<<<1, H>>>(gm, bem, 1.0f / M1);
    bn_apply_kernel<<<cdiv((long)M1 * H, 256), 256>>>(Mh, M1, (long)M1P * KP, 1, 0);

    GemmArgs gf;
    gf.A = Mh;  gf.khstr = (long)M1P * KP;
    gf.W = Wm2;
    gf.M = M1;  gf.N = COUT;  gf.bias = bm2;  gf.C = out;
    gemm_kernel<<<dim3(cdiv(M1, 64), cdiv(COUT, 64)), 256>>>(gf);
}

// round 13
// speedup vs baseline: 2.1547x; 1.0370x over previous
#include <cuda_runtime.h>
#include <math.h>
#include <stdint.h>

#define H 256
#define RREL 5
#define NSEG 6            // 5 relations + self-loop
#define M0_CONST 50000
#define M1_CONST 10000
#define M0P 50048         // padded to 128
#define M1P 10112
#define E0_MAX 800000
#define KP 132            // padded half-K row stride (floats); 528B, conflict-free ldmatrix

// ---------------- scratch (device globals: allocation-free) ----------------
// GEMM operand layout: half-K planes [plane][row][KP], plane = seg*2 + kh.
__device__ float g_A0[(size_t)NSEG * 2 * M0P * KP];
__device__ float g_A1[(size_t)NSEG * 2 * M1P * KP];
__device__ float g_H0[(size_t)2 * M0P * KP];
__device__ float g_H1[(size_t)2 * M1P * KP];
__device__ float g_Mh[(size_t)2 * M1P * KP];
__device__ float g_Wt[(size_t)13 * 2 * 256 * KP];  // [mat][kh][n][KP], tf32-rounded
__device__ int   g_cnt[M0_CONST + 4];
__device__ int   g_off[M0_CONST + 4];
__device__ int   g_cur[M0_CONST + 4];
__device__ int   g_eidx[E0_MAX];
__device__ float g_sum[H];
__device__ float g_sumsq[H];
__device__ float g_scale[H];
__device__ float g_shift[H];

// ---------------- helpers ----------------
__device__ __forceinline__ uint32_t f2tf32(float v) {
    uint32_t t;
    asm("cvt.rna.tf32.f32 %0, %1;" : "=r"(t) : "f"(v));
    return t;
}
__device__ __forceinline__ float rtf(float v) { return __uint_as_float(f2tf32(v)); }

__device__ __forceinline__ uint32_t smem_u32(const void* p) {
    uint32_t a;
    asm("{ .reg .u64 t; cvta.to.shared.u64 t, %1; cvt.u32.u64 %0, t; }"
        : "=r"(a) : "l"(p));
    return a;
}

#define MBAR_INIT(addr, cnt)                                                   \
    asm volatile("mbarrier.init.shared.b64 [%0], %1;" :: "r"(addr), "r"(cnt) : "memory")

#define MBAR_EXPECT(addr, bytes)                                               \
    asm volatile("mbarrier.arrive.expect_tx.shared.b64 _, [%0], %1;"           \
                 :: "r"(addr), "r"(bytes) : "memory")

#define BULK_G2S(dst, src, bytes, mbar)                                        \
    asm volatile(                                                              \
        "cp.async.bulk.shared::cluster.global.mbarrier::complete_tx::bytes "   \
        "[%0], [%1], %2, [%3];"                                                \
        :: "r"(dst), "l"(src), "r"(bytes), "r"(mbar) : "memory")

#define NAMED_BAR(id)                                                          \
    asm volatile("bar.sync %0, 128;" :: "r"(id) : "memory")

__device__ __forceinline__ void mbar_wait(uint32_t mbar, uint32_t parity) {
    uint32_t done;
    asm volatile(
        "{\n\t.reg .pred p;\n\t"
        "mbarrier.try_wait.parity.acquire.cta.shared::cta.b64 p, [%1], %2;\n\t"
        "selp.b32 %0, 1, 0, p;\n\t}"
        : "=r"(done) : "r"(mbar), "r"(parity) : "memory");
    if (!done) {
        asm volatile(
            "{\n\t.reg .pred P1;\n\t"
            "W_%=:\n\t"
            "mbarrier.try_wait.parity.acquire.cta.shared::cta.b64 P1, [%0], %1, 0x989680;\n\t"
            "@P1 bra.uni D_%=;\n\t"
            "bra.uni W_%=;\n\t"
            "D_%=:\n\t}"
            :: "r"(mbar), "r"(parity) : "memory");
    }
}

// ---------------- CSR build (dst-keyed, relation packed into eidx) --------
__global__ void hist_kernel(const int* __restrict__ dst, int E, int* __restrict__ cnt) {
    int e = blockIdx.x * 256 + threadIdx.x;
    if (e < E) atomicAdd(&cnt[dst[e]], 1);
}

__global__ void scan_kernel(const int* __restrict__ cnt, int* __restrict__ off,
                            int* __restrict__ cur, int n) {
    __shared__ int part[1024];
    int t = threadIdx.x;
    int chunk = (n + 1023) >> 10;
    int a = t * chunk;
    int b = min(a + chunk, n);
    int s = 0;
#pragma unroll 4
    for (int i = a; i < b; i++) s += cnt[i];
    part[t] = s;
    __syncthreads();
    for (int d = 1; d < 1024; d <<= 1) {
        int v = (t >= d) ? part[t - d] : 0;
        __syncthreads();
        part[t] += v;
        __syncthreads();
    }
    int run = (t == 0) ? 0 : part[t - 1];
    for (int i = a; i < b; i++) { off[i] = run; cur[i] = run; run += cnt[i]; }
    if (b == n) off[n] = run;
}

__global__ void scatter_kernel(const int* __restrict__ src, const int* __restrict__ dst,
                               const int* __restrict__ et, int E,
                               int* __restrict__ cur, int* __restrict__ eidx) {
    int e = blockIdx.x * 256 + threadIdx.x;
    if (e < E) {
        int p = atomicAdd(&cur[dst[e]], 1);
        eidx[p] = (et[e] << 24) | src[e];
    }
}

// One block (64 thr) per dst node; thread t owns channels [4t, 4t+4).
// int strides + hoisted base pointers keep regs <= 48 (launch_bounds 64,21
// -> ~65% occupancy; R12's long-math version hit 61 regs / 46% occ).
__global__ void __launch_bounds__(64, 21)
gather_kernel(const float* __restrict__ x, const int* __restrict__ eidx,
              const int* __restrict__ off, int* __restrict__ cnt,
              float* __restrict__ A, int ndstp, int src_lda, int src_khstr) {
    int d = blockIdx.x;
    int t = threadIdx.x;          // 0..63
    int c = t * 4;
    int kh = c >> 7;
    int inner = c & 127;
    const float* xb = x + kh * src_khstr + inner;   // row base for this thread
    int beg = off[d], end = off[d + 1];
    float4 a0 = make_float4(0.f, 0.f, 0.f, 0.f);
    float4 a1 = a0, a2 = a0, a3 = a0, a4 = a0;
#define ACCUM(pk_, v_)                                                         \
    {                                                                          \
        int r_ = (pk_) >> 24;                                                  \
        if (r_ == 0) { a0.x += (v_).x; a0.y += (v_).y; a0.z += (v_).z; a0.w += (v_).w; } \
        if (r_ == 1) { a1.x += (v_).x; a1.y += (v_).y; a1.z += (v_).z; a1.w += (v_).w; } \
        if (r_ == 2) { a2.x += (v_).x; a2.y += (v_).y; a2.z += (v_).z; a2.w += (v_).w; } \
        if (r_ == 3) { a3.x += (v_).x; a3.y += (v_).y; a3.z += (v_).z; a3.w += (v_).w; } \
        if (r_ == 4) { a4.x += (v_).x; a4.y += (v_).y; a4.z += (v_).z; a4.w += (v_).w; } \
    }
    int i = beg;
    for (; i + 1 < end; i += 2) {
        int pk0 = eidx[i];
        int pk1 = eidx[i + 1];
        float4 v0 = *(const float4*)(xb + (size_t)(pk0 & 0xFFFFFF) * src_lda);
        float4 v1 = *(const float4*)(xb + (size_t)(pk1 & 0xFFFFFF) * src_lda);
        ACCUM(pk0, v0);
        ACCUM(pk1, v1);
    }
    if (i < end) {
        int pk0 = eidx[i];
        float4 v0 = *(const float4*)(xb + (size_t)(pk0 & 0xFFFFFF) * src_lda);
        ACCUM(pk0, v0);
    }
    // plane stores: base + k*step
    float* ab = A + ((size_t)kh * ndstp + d) * KP + inner;
    size_t step = (size_t)2 * ndstp * KP;
#define RSTORE(k, av)                                                          \
    {                                                                          \
        float4 o;                                                              \
        o.x = rtf((av).x); o.y = rtf((av).y);                                  \
        o.z = rtf((av).z); o.w = rtf((av).w);                                  \
        *(float4*)(ab + (k) * step) = o;                                       \
    }
    RSTORE(0, a0); RSTORE(1, a1); RSTORE(2, a2); RSTORE(3, a3); RSTORE(4, a4);
    float4 sv = *(const float4*)(xb + (size_t)d * src_lda);
    RSTORE(5, sv);
    if (t == 0) cnt[d] = 0;
}

// ---------------- weight transpose (one-shot per launch, tf32-rounded) ----
// Writes Wt[mat][kh][n][KP].
__global__ void transpose_weights(const float* W0, const float* Wl0,
                                  const float* W1, const float* Wl1,
                                  const float* Wm1) {
    __shared__ float t[32][33];
    int m = blockIdx.x;
    const float* src = (m < 5)   ? W0 + (size_t)m * H * H
                     : (m == 5)  ? Wl0
                     : (m < 11)  ? W1 + (size_t)(m - 6) * H * H
                     : (m == 11) ? Wl1 : Wm1;
    float* dst = g_Wt + (size_t)m * 2 * 256 * KP;
    int bx = blockIdx.y * 32, by = blockIdx.z * 32;
    int x = threadIdx.x, y = threadIdx.y;
#pragma unroll
    for (int i = 0; i < 32; i += 8)
        t[y + i][x] = src[(size_t)(by + y + i) * H + bx + x];
    __syncthreads();
#pragma unroll
    for (int i = 0; i < 32; i += 8) {
        int n = bx + y + i;
        int k = by + x;
        dst[((size_t)(k >> 7) * 256 + n) * KP + (k & 127)] = rtf(t[x][y + i]);
    }
}

// ---------------- tf32 tensor GEMM: half-K planes, 2 CTAs/SM --------------
struct TGArgs {
    const float* A; long MP;     // plane rows (padded)
    const float* W;              // [nseg][2][256][KP]
    int nseg; int M;
    const float* bias;
    float* C; long CMP;          // C plane rows (padded)
};

#define CH_BYTES (32 * KP * 4)        // 16896
#define B_BYTES  (128 * KP * 4)       // 67584
#define SM_A0 1024
#define SM_A1 (1024 + CH_BYTES)       // 17920
#define SM_B  (1024 + 2 * CH_BYTES)   // 34816
#define SM_TOTAL (SM_B + B_BYTES)     // 102400
// mbarriers: A-buf g @ sb+8g, B @ sb+16

// warp computes m32 x n32 of one chunk over K=128; acc[im][in][4]
__device__ __forceinline__ void mma32(uint32_t ab, uint32_t bb,
                                      int wq, int rowl, int khalf,
                                      float (*acc)[4][4]) {
#pragma unroll 4
    for (int kq = 0; kq < 16; kq++) {
        int q = kq * 8 + khalf;
        uint32_t a[2][4], b[2][4];
#pragma unroll
        for (int im = 0; im < 2; im++) {
            uint32_t ad = ab + (((im * 16 + rowl) * KP + q) << 2);
            asm volatile(
                "ldmatrix.sync.aligned.m8n8.x4.shared.b16 {%0,%1,%2,%3}, [%4];"
                : "=r"(a[im][0]), "=r"(a[im][1]), "=r"(a[im][2]), "=r"(a[im][3])
                : "r"(ad));
        }
#pragma unroll
        for (int i2 = 0; i2 < 2; i2++) {
            uint32_t bd = bb + (((wq * 32 + i2 * 16 + rowl) * KP + q) << 2);
            asm volatile(
                "ldmatrix.sync.aligned.m8n8.x4.shared.b16 {%0,%1,%2,%3}, [%4];"
                : "=r"(b[i2][0]), "=r"(b[i2][1]), "=r"(b[i2][2]), "=r"(b[i2][3])
                : "r"(bd));
        }
#pragma unroll
        for (int im = 0; im < 2; im++)
#pragma unroll
            for (int in_ = 0; in_ < 4; in_++) {
                int i2 = in_ >> 1, p = in_ & 1;
                asm volatile(
                    "mma.sync.aligned.m16n8k8.row.col.f32.tf32.tf32.f32 "
                    "{%0,%1,%2,%3}, {%4,%5,%6,%7}, {%8,%9}, {%0,%1,%2,%3};\n"
                    : "+f"(acc[im][in_][0]), "+f"(acc[im][in_][1]),
                      "+f"(acc[im][in_][2]), "+f"(acc[im][in_][3])
                    : "r"(a[im][0]), "r"(a[im][1]), "r"(a[im][2]), "r"(a[im][3]),
                      "r"(b[i2][p]), "r"(b[i2][2 + p]));
            }
    }
}

__global__ void __launch_bounds__(256, 2) gemm_bulk(TGArgs g) {
    extern __shared__ char sm[];
    uint32_t sb = smem_u32(sm);
    int tid = threadIdx.x, warp = tid >> 5, lane = tid & 31;
    int gidx = warp >> 2;         // group 0/1 -> A buf, chunks {g, g+2}
    int wq = warp & 3;            // n quarter
    int n0 = blockIdx.x * 128;    // n-tile fastest -> same-m CTAs adjacent (L2 A reuse)
    int m0 = blockIdx.y * 128;
    int rowl = lane & 15, khalf = (lane >> 4) * 4;
    int lr = lane >> 2, lc = lane & 3;
    uint32_t mbarA = sb + 8 * gidx;
    uint32_t mbarB = sb + 16;
    uint32_t bufA = sb + (gidx ? SM_A1 : SM_A0);
    uint32_t bb = sb + SM_B;
    int barid = 1 + gidx;
    bool leader = (tid == gidx * 128);
    int nst = g.nseg * 2;

    if (tid == 0) {
        MBAR_INIT(sb + 0, 1);
        MBAR_INIT(sb + 8, 1);
        MBAR_INIT(sb + 16, 1);
    }
    __syncthreads();

    float acc[2][2][4][4];        // [ci][im][in][reg]
#pragma unroll
    for (int ci = 0; ci < 2; ci++)
#pragma unroll
        for (int im = 0; im < 2; im++)
#pragma unroll
            for (int j = 0; j < 4; j++)
#pragma unroll
                for (int k = 0; k < 4; k++) acc[ci][im][j][k] = 0.f;

    // prologue: stage 0
    {
        const float* asrc0 = g.A + (size_t)m0 * KP;
        if (tid == 0) {
            MBAR_EXPECT(mbarB, B_BYTES);
            BULK_G2S(sb + SM_B, g.W + (size_t)n0 * KP, B_BYTES, mbarB);
        }
        if (leader) {
            MBAR_EXPECT(mbarA, CH_BYTES);
            BULK_G2S(bufA, asrc0 + (size_t)gidx * 32 * KP, CH_BYTES, mbarA);
        }
    }

    int pA = 0, pB = 0;
    for (int s = 0; s < nst; s++) {
        const float* asrc = g.A + ((size_t)s * g.MP + m0) * KP;
        const float* nasrc = asrc + (size_t)g.MP * KP;
        bool more = (s + 1 < nst);

        // chunk gidx (ci=0)
        mbar_wait(mbarA, pA); pA ^= 1;
        mbar_wait(mbarB, pB);
        mma32(bufA, bb, wq, rowl, khalf, acc[0]);
        NAMED_BAR(barid);
        if (leader) {
            MBAR_EXPECT(mbarA, CH_BYTES);
            BULK_G2S(bufA, asrc + (size_t)(2 + gidx) * 32 * KP, CH_BYTES, mbarA);
        }
        // chunk gidx+2 (ci=1)
        mbar_wait(mbarA, pA); pA ^= 1;
        mma32(bufA, bb, wq, rowl, khalf, acc[1]);
        NAMED_BAR(barid);
        if (leader && more) {
            MBAR_EXPECT(mbarA, CH_BYTES);
            BULK_G2S(bufA, nasrc + (size_t)gidx * 32 * KP, CH_BYTES, mbarA);
        }
        __syncthreads();              // all warps done with this stage's B
        if (tid == 0 && more) {
            MBAR_EXPECT(mbarB, B_BYTES);
            BULK_G2S(sb + SM_B, g.W + ((size_t)(s + 1) * 256 + n0) * KP,
                     B_BYTES, mbarB);
        }
        pB ^= 1;
    }

    // ---- epilogue: bias + store to C planes ----
#pragma unroll
    for (int ci = 0; ci < 2; ci++) {
        int mbase = m0 + (ci * 2 + gidx) * 32;
#pragma unroll
        for (int im = 0; im < 2; im++) {
            int mrow = mbase + im * 16 + lr;
#pragma unroll
            for (int in_ = 0; in_ < 4; in_++) {
                int col = n0 + wq * 32 + in_ * 8 + lc * 2;
                float* cp = g.C + (size_t)(col >> 7) * g.CMP * KP + (col & 127);
                float bia0 = g.bias[col];
                float bia1 = g.bias[col + 1];
                if (mrow < g.M) {
                    float2 v = make_float2(acc[ci][im][in_][0] + bia0,
                                           acc[ci][im][in_][1] + bia1);
                    *(float2*)(cp + (size_t)mrow * KP) = v;
                }
                if (mrow + 8 < g.M) {
                    float2 v = make_float2(acc[ci][im][in_][2] + bia0,
                                           acc[ci][im][in_][3] + bia1);
                    *(float2*)(cp + (size_t)(mrow + 8) * KP) = v;
                }
            }
        }
    }
}

// ---------------- SIMT GEMM (final 256x153; A in planes, W raw) -----------
struct GemmArgs {
    const float* A;   // planes [2][MP][KP]
    long khstr;       // MP*KP
    const float* W;   // [256][N] row-major
    int M, N;
    const float* bias;
    float* C;         // [M][N] dense
};

__global__ void gemm_kernel(GemmArgs g) {
    __shared__ float As[16][65];
    __shared__ float Bs[16][64];

    int tid = threadIdx.x;
    int m0 = blockIdx.x * 64;
    int n0 = blockIdx.y * 64;
    int tm = tid >> 4;
    int tn = tid & 15;

    int lrow = tid >> 2;
    int lk4 = (tid & 3) << 2;
    int lkb = tid >> 4;
    int ln4 = (tid & 15) << 2;

    float acc[4][4];
#pragma unroll
    for (int i = 0; i < 4; i++)
#pragma unroll
        for (int j = 0; j < 4; j++) acc[i][j] = 0.f;

    for (int k0 = 0; k0 < H; k0 += 16) {
        float4 av = make_float4(0.f, 0.f, 0.f, 0.f);
        if (m0 + lrow < g.M)
            av = *(const float4*)(g.A + (size_t)(k0 >> 7) * g.khstr +
                                  (size_t)(m0 + lrow) * KP + ((k0 + lk4) & 127));
        As[lk4 + 0][lrow] = av.x;
        As[lk4 + 1][lrow] = av.y;
        As[lk4 + 2][lrow] = av.z;
        As[lk4 + 3][lrow] = av.w;
        const float* wp = g.W + (size_t)(k0 + lkb) * g.N + n0 + ln4;
        float4 bv;
        bv.x = (n0 + ln4 + 0 < g.N) ? wp[0] : 0.f;
        bv.y = (n0 + ln4 + 1 < g.N) ? wp[1] : 0.f;
        bv.z = (n0 + ln4 + 2 < g.N) ? wp[2] : 0.f;
        bv.w = (n0 + ln4 + 3 < g.N) ? wp[3] : 0.f;
        *(float4*)&Bs[lkb][ln4] = bv;
        __syncthreads();
#pragma unroll
        for (int kk = 0; kk < 16; kk++) {
            float a0 = As[kk][tm * 4 + 0];
            float a1 = As[kk][tm * 4 + 1];
            float a2 = As[kk][tm * 4 + 2];
            float a3 = As[kk][tm * 4 + 3];
            float4 b = *(const float4*)&Bs[kk][tn * 4];
            acc[0][0] += a0 * b.x; acc[0][1] += a0 * b.y; acc[0][2] += a0 * b.z; acc[0][3] += a0 * b.w;
            acc[1][0] += a1 * b.x; acc[1][1] += a1 * b.y; acc[1][2] += a1 * b.z; acc[1][3] += a1 * b.w;
            acc[2][0] += a2 * b.x; acc[2][1] += a2 * b.y; acc[2][2] += a2 * b.z; acc[2][3] += a2 * b.w;
            acc[3][0] += a3 * b.x; acc[3][1] += a3 * b.y; acc[3][2] += a3 * b.z; acc[3][3] += a3 * b.w;
        }
        __syncthreads();
    }

#pragma unroll
    for (int i = 0; i < 4; i++) {
        int m = m0 + tm * 4 + i;
        if (m >= g.M) continue;
#pragma unroll
        for (int j = 0; j < 4; j++) {
            int n = n0 + tn * 4 + j;
            if (n < g.N) g.C[(size_t)m * g.N + n] = acc[i][j] + g.bias[n];
        }
    }
}

// ---------------- BN kernels (plane layout) ----------------
__global__ void zero_stats_kernel() {
    g_sum[threadIdx.x] = 0.f;
    g_sumsq[threadIdx.x] = 0.f;
}

__global__ void bn_stats_kernel(const float* __restrict__ h, int M, long khstr) {
    int col = threadIdx.x;
    const float* hp = h + (size_t)(col >> 7) * khstr + (col & 127);
    int r0 = blockIdx.x * 128;
    int rend = min(r0 + 128, M);
    float s = 0.f, s2 = 0.f;
    for (int r = r0; r < rend; r++) {
        float v = hp[(size_t)r * KP];
        s += v;
        s2 += v * v;
    }
    atomicAdd(&g_sum[col], s);
    atomicAdd(&g_sumsq[col], s2);
}

__global__ void bn_finalize_kernel(const float* __restrict__ gamma,
                                   const float* __restrict__ beta, float invM) {
    int col = threadIdx.x;
    float mean = g_sum[col] * invM;
    float var = g_sumsq[col] * invM - mean * mean;
    float sc = gamma[col] * rsqrtf(var + 1e-5f);
    g_scale[col] = sc;
    g_shift[col] = beta[col] - mean * sc;
}

// act 0 = ELU, 1 = ReLU; rnd -> round to tf32 for tensor-GEMM consumers
__global__ void bn_apply_kernel(float* __restrict__ h, int M, long khstr,
                                int act, int rnd) {
    long i = (long)blockIdx.x * blockDim.x + threadIdx.x;
    if (i >= (long)M * H) return;
    int col = (int)(i & (H - 1));
    long row = i >> 8;
    float* hp = h + (size_t)(col >> 7) * khstr + row * KP + (col & 127);
    float v = *hp * g_scale[col] + g_shift[col];
    if (act == 0)
        v = (v > 0.f) ? v : expm1f(v);
    else
        v = (v > 0.f) ? v : 0.f;
    if (rnd) v = rtf(v);
    *hp = v;
}

// ---------------- host orchestration ----------------
static inline int cdiv(long a, long b) { return (int)((a + b - 1) / b); }

extern "C" void kernel_launch(void* const* d_in, const int* in_sizes, int n_in,
                              void* d_out, int out_size) {
    const float* x   = (const float*)d_in[0];
    const int* src0  = (const int*)d_in[1];
    const int* dst0  = (const int*)d_in[2];
    const int* et0   = (const int*)d_in[3];
    const int* src1  = (const int*)d_in[4];
    const int* dst1  = (const int*)d_in[5];
    const int* et1   = (const int*)d_in[6];
    const float* W0  = (const float*)d_in[9];
    const float* Wl0 = (const float*)d_in[10];
    const float* b0  = (const float*)d_in[11];
    const float* g0  = (const float*)d_in[12];
    const float* be0 = (const float*)d_in[13];
    const float* W1  = (const float*)d_in[14];
    const float* Wl1 = (const float*)d_in[15];
    const float* b1  = (const float*)d_in[16];
    const float* g1  = (const float*)d_in[17];
    const float* be1 = (const float*)d_in[18];
    const float* Wm1 = (const float*)d_in[19];
    const float* bm1 = (const float*)d_in[20];
    const float* gm  = (const float*)d_in[21];
    const float* bem = (const float*)d_in[22];
    const float* Wm2 = (const float*)d_in[23];
    const float* bm2 = (const float*)d_in[24];
    float* out = (float*)d_out;

    const int E0 = in_sizes[1];
    const int E1 = in_sizes[4];
    const int COUT = 153;
    const int M1 = out_size / COUT;   // 10000
    const int M0 = M0_CONST;          // 50000

    float *A0, *A1, *H0, *H1, *Mh, *Wt;
    int *cnt, *off, *cur, *eidx;
    cudaGetSymbolAddress((void**)&A0, g_A0);
    cudaGetSymbolAddress((void**)&A1, g_A1);
    cudaGetSymbolAddress((void**)&H0, g_H0);
    cudaGetSymbolAddress((void**)&H1, g_H1);
    cudaGetSymbolAddress((void**)&Mh, g_Mh);
    cudaGetSymbolAddress((void**)&Wt, g_Wt);
    cudaGetSymbolAddress((void**)&cnt, g_cnt);
    cudaGetSymbolAddress((void**)&off, g_off);
    cudaGetSymbolAddress((void**)&cur, g_cur);
    cudaGetSymbolAddress((void**)&eidx, g_eidx);

    cudaFuncSetAttribute(gemm_bulk,
                         cudaFuncAttributeMaxDynamicSharedMemorySize, SM_TOTAL);

    // ---- layer 0: CSR + gather (profiled slot 3) + GEMM ----
    hist_kernel<<<cdiv(E0, 256), 256>>>(dst0, E0, cnt);                     // 0
    scan_kernel<<<1, 1024>>>(cnt, off, cur, M0);                            // 1
    scatter_kernel<<<cdiv(E0, 256), 256>>>(src0, dst0, et0, E0, cur, eidx); // 2
    gather_kernel<<<M0, 64>>>(x, eidx, off, cnt, A0, M0P, H, 128);          // 3 <- profiled
    transpose_weights<<<dim3(13, 8, 8), dim3(32, 8)>>>(W0, Wl0, W1, Wl1, Wm1);

    TGArgs ga;
    ga.A = A0;  ga.MP = M0P;
    ga.W = Wt;  ga.nseg = NSEG;  ga.M = M0;  ga.bias = b0;
    ga.C = H0;  ga.CMP = M0P;
    gemm_bulk<<<dim3(2, cdiv(M0, 128)), 256, SM_TOTAL>>>(ga);

    zero_stats_kernel<<<1, H>>>();
    bn_stats_kernel<<<cdiv(M0, 128), H>>>(H0, M0, (long)M0P * KP);
    bn_finalize_kernel<<<1, H>>>(g0, be0, 1.0f / M0);
    bn_apply_kernel<<<cdiv((long)M0 * H, 256), 256>>>(H0, M0, (long)M0P * KP, 0, 1);

    // ---- layer 1 ----
    hist_kernel<<<cdiv(E1, 256), 256>>>(dst1, E1, cnt);
    scan_kernel<<<1, 1024>>>(cnt, off, cur, M1);
    scatter_kernel<<<cdiv(E1, 256), 256>>>(src1, dst1, et1, E1, cur, eidx);
    gather_kernel<<<M1, 64>>>(H0, eidx, off, cnt, A1, M1P, KP, M0P * KP);

    ga.A = A1;  ga.MP = M1P;
    ga.W = Wt + (size_t)6 * 2 * 256 * KP;
    ga.nseg = NSEG;  ga.M = M1;  ga.bias = b1;
    ga.C = H1;  ga.CMP = M1P;
    gemm_bulk<<<dim3(2, cdiv(M1, 128)), 256, SM_TOTAL>>>(ga);

    zero_stats_kernel<<<1, H>>>();
    bn_stats_kernel<<<cdiv(M1, 128), H>>>(H1, M1, (long)M1P * KP);
    bn_finalize_kernel<<<1, H>>>(g1, be1, 1.0f / M1);
    bn_apply_kernel<<<cdiv((long)M1 * H, 256), 256>>>(H1, M1, (long)M1P * KP, 0, 1);

    // ---- MLP head ----
    ga.A = H1;  ga.MP = M1P;
    ga.W = Wt + (size_t)12 * 2 * 256 * KP;
    ga.nseg = 1;  ga.M = M1;  ga.bias = bm1;
    ga.C = Mh;  ga.CMP = M1P;
    gemm_bulk<<<dim3(2, cdiv(M1, 128)), 256, SM_TOTAL>>>(ga);

    zero_stats_kernel<<<1, H>>>();
    bn_stats_kernel<<<cdiv(M1, 128), H>>>(Mh, M1, (long)M1P * KP);
    bn_finalize_kernel<<<1, H>>>(gm, bem, 1.0f / M1);
    bn_apply_kernel<<<cdiv((long)M1 * H, 256), 256>>>(Mh, M1, (long)M1P * KP, 1, 0);

    GemmArgs gf;
    gf.A = Mh;  gf.khstr = (long)M1P * KP;
    gf.W = Wm2;
    gf.M = M1;  gf.N = COUT;  gf.bias = bm2;  gf.C = out;
    gemm_kernel<<<dim3(cdiv(M1, 64), cdiv(COUT, 64)), 256>>>(gf);
}

// round 14
// speedup vs baseline: 2.2060x; 1.0238x over previous
#include <cuda_runtime.h>
#include <math.h>
#include <stdint.h>

#define H 256
#define RREL 5
#define NSEG 6            // 5 relations + self-loop
#define M0_CONST 50000
#define M1_CONST 10000
#define M0P 50048         // padded to 128
#define M1P 10112
#define E0_MAX 800000
#define KP 132            // padded half-K row stride (floats); 528B, conflict-free ldmatrix

// ---------------- scratch (device globals: allocation-free) ----------------
// GEMM operand layout: half-K planes [plane][row][KP], plane = seg*2 + kh.
__device__ float g_A0[(size_t)NSEG * 2 * M0P * KP];
__device__ float g_A1[(size_t)NSEG * 2 * M1P * KP];
__device__ float g_H0[(size_t)2 * M0P * KP];
__device__ float g_H1[(size_t)2 * M1P * KP];
__device__ float g_Mh[(size_t)2 * M1P * KP];
__device__ float g_Wt[(size_t)13 * 2 * 256 * KP];  // [mat][kh][n][KP], tf32-rounded
__device__ int   g_cnt[M0_CONST + 4];
__device__ int   g_off[M0_CONST + 4];
__device__ int   g_cur[M0_CONST + 4];
__device__ int   g_eidx[E0_MAX];
__device__ float g_sum[H];
__device__ float g_sumsq[H];
__device__ float g_scale[H];
__device__ float g_shift[H];

// ---------------- helpers ----------------
__device__ __forceinline__ uint32_t f2tf32(float v) {
    uint32_t t;
    asm("cvt.rna.tf32.f32 %0, %1;" : "=r"(t) : "f"(v));
    return t;
}
__device__ __forceinline__ float rtf(float v) { return __uint_as_float(f2tf32(v)); }

__device__ __forceinline__ uint32_t smem_u32(const void* p) {
    uint32_t a;
    asm("{ .reg .u64 t; cvta.to.shared.u64 t, %1; cvt.u32.u64 %0, t; }"
        : "=r"(a) : "l"(p));
    return a;
}

#define MBAR_INIT(addr, cnt)                                                   \
    asm volatile("mbarrier.init.shared.b64 [%0], %1;" :: "r"(addr), "r"(cnt) : "memory")

#define MBAR_EXPECT(addr, bytes)                                               \
    asm volatile("mbarrier.arrive.expect_tx.shared.b64 _, [%0], %1;"           \
                 :: "r"(addr), "r"(bytes) : "memory")

#define BULK_G2S(dst, src, bytes, mbar)                                        \
    asm volatile(                                                              \
        "cp.async.bulk.shared::cluster.global.mbarrier::complete_tx::bytes "   \
        "[%0], [%1], %2, [%3];"                                                \
        :: "r"(dst), "l"(src), "r"(bytes), "r"(mbar) : "memory")

#define NAMED_BAR(id)                                                          \
    asm volatile("bar.sync %0, 128;" :: "r"(id) : "memory")

__device__ __forceinline__ void mbar_wait(uint32_t mbar, uint32_t parity) {
    uint32_t done;
    asm volatile(
        "{\n\t.reg .pred p;\n\t"
        "mbarrier.try_wait.parity.acquire.cta.shared::cta.b64 p, [%1], %2;\n\t"
        "selp.b32 %0, 1, 0, p;\n\t}"
        : "=r"(done) : "r"(mbar), "r"(parity) : "memory");
    if (!done) {
        asm volatile(
            "{\n\t.reg .pred P1;\n\t"
            "W_%=:\n\t"
            "mbarrier.try_wait.parity.acquire.cta.shared::cta.b64 P1, [%0], %1, 0x989680;\n\t"
            "@P1 bra.uni D_%=;\n\t"
            "bra.uni W_%=;\n\t"
            "D_%=:\n\t}"
            :: "r"(mbar), "r"(parity) : "memory");
    }
}

// ---------------- CSR build (dst-keyed, relation packed into eidx) --------
__global__ void hist_kernel(const int* __restrict__ dst, int E, int* __restrict__ cnt) {
    int e = blockIdx.x * 256 + threadIdx.x;
    if (e < E) atomicAdd(&cnt[dst[e]], 1);
}

__global__ void scan_kernel(const int* __restrict__ cnt, int* __restrict__ off,
                            int* __restrict__ cur, int n) {
    __shared__ int part[1024];
    int t = threadIdx.x;
    int chunk = (n + 1023) >> 10;
    int a = t * chunk;
    int b = min(a + chunk, n);
    int s = 0;
#pragma unroll 4
    for (int i = a; i < b; i++) s += cnt[i];
    part[t] = s;
    __syncthreads();
    for (int d = 1; d < 1024; d <<= 1) {
        int v = (t >= d) ? part[t - d] : 0;
        __syncthreads();
        part[t] += v;
        __syncthreads();
    }
    int run = (t == 0) ? 0 : part[t - 1];
    for (int i = a; i < b; i++) { off[i] = run; cur[i] = run; run += cnt[i]; }
    if (b == n) off[n] = run;
}

__global__ void scatter_kernel(const int* __restrict__ src, const int* __restrict__ dst,
                               const int* __restrict__ et, int E,
                               int* __restrict__ cur, int* __restrict__ eidx) {
    int e = blockIdx.x * 256 + threadIdx.x;
    if (e < E) {
        int p = atomicAdd(&cur[dst[e]], 1);
        eidx[p] = (et[e] << 24) | src[e];
    }
}

// One block (64 thr) per dst node; thread t owns channels [4t, 4t+4).
__global__ void __launch_bounds__(64, 21)
gather_kernel(const float* __restrict__ x, const int* __restrict__ eidx,
              const int* __restrict__ off, int* __restrict__ cnt,
              float* __restrict__ A, int ndstp, int src_lda, int src_khstr) {
    int d = blockIdx.x;
    int t = threadIdx.x;          // 0..63
    int c = t * 4;
    int kh = c >> 7;
    int inner = c & 127;
    const float* xb = x + kh * src_khstr + inner;   // row base for this thread
    int beg = off[d], end = off[d + 1];
    float4 a0 = make_float4(0.f, 0.f, 0.f, 0.f);
    float4 a1 = a0, a2 = a0, a3 = a0, a4 = a0;
#define ACCUM(pk_, v_)                                                         \
    {                                                                          \
        int r_ = (pk_) >> 24;                                                  \
        if (r_ == 0) { a0.x += (v_).x; a0.y += (v_).y; a0.z += (v_).z; a0.w += (v_).w; } \
        if (r_ == 1) { a1.x += (v_).x; a1.y += (v_).y; a1.z += (v_).z; a1.w += (v_).w; } \
        if (r_ == 2) { a2.x += (v_).x; a2.y += (v_).y; a2.z += (v_).z; a2.w += (v_).w; } \
        if (r_ == 3) { a3.x += (v_).x; a3.y += (v_).y; a3.z += (v_).z; a3.w += (v_).w; } \
        if (r_ == 4) { a4.x += (v_).x; a4.y += (v_).y; a4.z += (v_).z; a4.w += (v_).w; } \
    }
    int i = beg;
    for (; i + 1 < end; i += 2) {
        int pk0 = eidx[i];
        int pk1 = eidx[i + 1];
        float4 v0 = *(const float4*)(xb + (size_t)(pk0 & 0xFFFFFF) * src_lda);
        float4 v1 = *(const float4*)(xb + (size_t)(pk1 & 0xFFFFFF) * src_lda);
        ACCUM(pk0, v0);
        ACCUM(pk1, v1);
    }
    if (i < end) {
        int pk0 = eidx[i];
        float4 v0 = *(const float4*)(xb + (size_t)(pk0 & 0xFFFFFF) * src_lda);
        ACCUM(pk0, v0);
    }
    float* ab = A + ((size_t)kh * ndstp + d) * KP + inner;
    size_t step = (size_t)2 * ndstp * KP;
#define RSTORE(k, av)                                                          \
    {                                                                          \
        float4 o;                                                              \
        o.x = rtf((av).x); o.y = rtf((av).y);                                  \
        o.z = rtf((av).z); o.w = rtf((av).w);                                  \
        *(float4*)(ab + (k) * step) = o;                                       \
    }
    RSTORE(0, a0); RSTORE(1, a1); RSTORE(2, a2); RSTORE(3, a3); RSTORE(4, a4);
    float4 sv = *(const float4*)(xb + (size_t)d * src_lda);
    RSTORE(5, sv);
    if (t == 0) cnt[d] = 0;
}

// ---------------- weight transpose (one-shot per launch, tf32-rounded) ----
__global__ void transpose_weights(const float* W0, const float* Wl0,
                                  const float* W1, const float* Wl1,
                                  const float* Wm1) {
    __shared__ float t[32][33];
    int m = blockIdx.x;
    const float* src = (m < 5)   ? W0 + (size_t)m * H * H
                     : (m == 5)  ? Wl0
                     : (m < 11)  ? W1 + (size_t)(m - 6) * H * H
                     : (m == 11) ? Wl1 : Wm1;
    float* dst = g_Wt + (size_t)m * 2 * 256 * KP;
    int bx = blockIdx.y * 32, by = blockIdx.z * 32;
    int x = threadIdx.x, y = threadIdx.y;
#pragma unroll
    for (int i = 0; i < 32; i += 8)
        t[y + i][x] = src[(size_t)(by + y + i) * H + bx + x];
    __syncthreads();
#pragma unroll
    for (int i = 0; i < 32; i += 8) {
        int n = bx + y + i;
        int k = by + x;
        dst[((size_t)(k >> 7) * 256 + n) * KP + (k & 127)] = rtf(t[x][y + i]);
    }
}

// ---------------- tf32 tensor GEMM: half-K planes, 2 CTAs/SM --------------
// Epilogue optionally accumulates per-column BN stats (sum/sumsq incl bias)
// hierarchically: thread -> shuffle over row-lanes -> smem -> 1 global
// atomicAdd per column per CTA.
struct TGArgs {
    const float* A; long MP;     // plane rows (padded)
    const float* W;              // [nseg][2][256][KP]
    int nseg; int M;
    const float* bias;
    float* C; long CMP;          // C plane rows (padded)
    int do_stats;
};

#define CH_BYTES (32 * KP * 4)        // 16896
#define B_BYTES  (128 * KP * 4)       // 67584
#define SM_A0 1024
#define SM_A1 (1024 + CH_BYTES)       // 17920
#define SM_B  (1024 + 2 * CH_BYTES)   // 34816
#define SM_TOTAL (SM_B + B_BYTES)     // 102400
// mbarriers: A-buf g @ sb+8g, B @ sb+16

__device__ __forceinline__ void mma32(uint32_t ab, uint32_t bb,
                                      int wq, int rowl, int khalf,
                                      float (*acc)[4][4]) {
#pragma unroll 4
    for (int kq = 0; kq < 16; kq++) {
        int q = kq * 8 + khalf;
        uint32_t a[2][4], b[2][4];
#pragma unroll
        for (int im = 0; im < 2; im++) {
            uint32_t ad = ab + (((im * 16 + rowl) * KP + q) << 2);
            asm volatile(
                "ldmatrix.sync.aligned.m8n8.x4.shared.b16 {%0,%1,%2,%3}, [%4];"
                : "=r"(a[im][0]), "=r"(a[im][1]), "=r"(a[im][2]), "=r"(a[im][3])
                : "r"(ad));
        }
#pragma unroll
        for (int i2 = 0; i2 < 2; i2++) {
            uint32_t bd = bb + (((wq * 32 + i2 * 16 + rowl) * KP + q) << 2);
            asm volatile(
                "ldmatrix.sync.aligned.m8n8.x4.shared.b16 {%0,%1,%2,%3}, [%4];"
                : "=r"(b[i2][0]), "=r"(b[i2][1]), "=r"(b[i2][2]), "=r"(b[i2][3])
                : "r"(bd));
        }
#pragma unroll
        for (int im = 0; im < 2; im++)
#pragma unroll
            for (int in_ = 0; in_ < 4; in_++) {
                int i2 = in_ >> 1, p = in_ & 1;
                asm volatile(
                    "mma.sync.aligned.m16n8k8.row.col.f32.tf32.tf32.f32 "
                    "{%0,%1,%2,%3}, {%4,%5,%6,%7}, {%8,%9}, {%0,%1,%2,%3};\n"
                    : "+f"(acc[im][in_][0]), "+f"(acc[im][in_][1]),
                      "+f"(acc[im][in_][2]), "+f"(acc[im][in_][3])
                    : "r"(a[im][0]), "r"(a[im][1]), "r"(a[im][2]), "r"(a[im][3]),
                      "r"(b[i2][p]), "r"(b[i2][2 + p]));
            }
    }
}

__global__ void __launch_bounds__(256, 2) gemm_bulk(TGArgs g) {
    extern __shared__ char sm[];
    uint32_t sb = smem_u32(sm);
    int tid = threadIdx.x, warp = tid >> 5, lane = tid & 31;
    int gidx = warp >> 2;         // group 0/1 -> A buf, chunks {g, g+2}
    int wq = warp & 3;            // n quarter
    int n0 = blockIdx.x * 128;    // n-tile fastest
    int m0 = blockIdx.y * 128;
    int rowl = lane & 15, khalf = (lane >> 4) * 4;
    int lr = lane >> 2, lc = lane & 3;
    uint32_t mbarA = sb + 8 * gidx;
    uint32_t mbarB = sb + 16;
    uint32_t bufA = sb + (gidx ? SM_A1 : SM_A0);
    uint32_t bb = sb + SM_B;
    int barid = 1 + gidx;
    bool leader = (tid == gidx * 128);
    int nst = g.nseg * 2;

    if (tid == 0) {
        MBAR_INIT(sb + 0, 1);
        MBAR_INIT(sb + 8, 1);
        MBAR_INIT(sb + 16, 1);
    }
    __syncthreads();

    float acc[2][2][4][4];        // [ci][im][in][reg]
#pragma unroll
    for (int ci = 0; ci < 2; ci++)
#pragma unroll
        for (int im = 0; im < 2; im++)
#pragma unroll
            for (int j = 0; j < 4; j++)
#pragma unroll
                for (int k = 0; k < 4; k++) acc[ci][im][j][k] = 0.f;

    // prologue: stage 0
    {
        const float* asrc0 = g.A + (size_t)m0 * KP;
        if (tid == 0) {
            MBAR_EXPECT(mbarB, B_BYTES);
            BULK_G2S(sb + SM_B, g.W + (size_t)n0 * KP, B_BYTES, mbarB);
        }
        if (leader) {
            MBAR_EXPECT(mbarA, CH_BYTES);
            BULK_G2S(bufA, asrc0 + (size_t)gidx * 32 * KP, CH_BYTES, mbarA);
        }
    }

    int pA = 0, pB = 0;
    for (int s = 0; s < nst; s++) {
        const float* asrc = g.A + ((size_t)s * g.MP + m0) * KP;
        const float* nasrc = asrc + (size_t)g.MP * KP;
        bool more = (s + 1 < nst);

        mbar_wait(mbarA, pA); pA ^= 1;
        mbar_wait(mbarB, pB);
        mma32(bufA, bb, wq, rowl, khalf, acc[0]);
        NAMED_BAR(barid);
        if (leader) {
            MBAR_EXPECT(mbarA, CH_BYTES);
            BULK_G2S(bufA, asrc + (size_t)(2 + gidx) * 32 * KP, CH_BYTES, mbarA);
        }
        mbar_wait(mbarA, pA); pA ^= 1;
        mma32(bufA, bb, wq, rowl, khalf, acc[1]);
        NAMED_BAR(barid);
        if (leader && more) {
            MBAR_EXPECT(mbarA, CH_BYTES);
            BULK_G2S(bufA, nasrc + (size_t)gidx * 32 * KP, CH_BYTES, mbarA);
        }
        __syncthreads();
        if (tid == 0 && more) {
            MBAR_EXPECT(mbarB, B_BYTES);
            BULK_G2S(sb + SM_B, g.W + ((size_t)(s + 1) * 256 + n0) * KP,
                     B_BYTES, mbarB);
        }
        pB ^= 1;
    }

    // ---- epilogue: bias + store + optional fused BN stats ----
    float* ss = (float*)(sm + SM_A0);   // reuse A buf: [0..127]=sum, [128..255]=sumsq
    if (g.do_stats) {
        ss[tid] = 0.f;
        __syncthreads();
    }
#pragma unroll
    for (int in_ = 0; in_ < 4; in_++) {
        int lcol = wq * 32 + in_ * 8 + lc * 2;   // local column (0..126)
        int col = n0 + lcol;
        float bia0 = g.bias[col];
        float bia1 = g.bias[col + 1];
        float s0 = 0.f, q0 = 0.f, s1 = 0.f, q1 = 0.f;
        float* cp = g.C + (size_t)(col >> 7) * g.CMP * KP + (col & 127);
#pragma unroll
        for (int ci = 0; ci < 2; ci++) {
#pragma unroll
            for (int im = 0; im < 2; im++) {
                int mrow = m0 + (ci * 2 + gidx) * 32 + im * 16 + lr;
                if (mrow < g.M) {
                    float v0 = acc[ci][im][in_][0] + bia0;
                    float v1 = acc[ci][im][in_][1] + bia1;
                    *(float2*)(cp + (size_t)mrow * KP) = make_float2(v0, v1);
                    s0 += v0; q0 += v0 * v0; s1 += v1; q1 += v1 * v1;
                }
                if (mrow + 8 < g.M) {
                    float v2 = acc[ci][im][in_][2] + bia0;
                    float v3 = acc[ci][im][in_][3] + bia1;
                    *(float2*)(cp + (size_t)(mrow + 8) * KP) = make_float2(v2, v3);
                    s0 += v2; q0 += v2 * v2; s1 += v3; q1 += v3 * v3;
                }
            }
        }
        if (g.do_stats) {
            // reduce over the 8 row-lanes (lr = lane bits 2..4)
#pragma unroll
            for (int mk = 4; mk <= 16; mk <<= 1) {
                s0 += __shfl_xor_sync(0xffffffffu, s0, mk);
                q0 += __shfl_xor_sync(0xffffffffu, q0, mk);
                s1 += __shfl_xor_sync(0xffffffffu, s1, mk);
                q1 += __shfl_xor_sync(0xffffffffu, q1, mk);
            }
            if (lr == 0) {
                atomicAdd(&ss[lcol], s0);
                atomicAdd(&ss[128 + lcol], q0);
                atomicAdd(&ss[lcol + 1], s1);
                atomicAdd(&ss[128 + lcol + 1], q1);
            }
        }
    }
    if (g.do_stats) {
        __syncthreads();
        if (tid < 128) {
            atomicAdd(&g_sum[n0 + tid], ss[tid]);
            atomicAdd(&g_sumsq[n0 + tid], ss[128 + tid]);
        }
    }
}

// ---------------- SIMT GEMM (final 256x153; A in planes, W raw) -----------
struct GemmArgs {
    const float* A;   // planes [2][MP][KP]
    long khstr;       // MP*KP
    const float* W;   // [256][N] row-major
    int M, N;
    const float* bias;
    float* C;         // [M][N] dense
};

__global__ void gemm_kernel(GemmArgs g) {
    __shared__ float As[16][65];
    __shared__ float Bs[16][64];

    int tid = threadIdx.x;
    int m0 = blockIdx.x * 64;
    int n0 = blockIdx.y * 64;
    int tm = tid >> 4;
    int tn = tid & 15;

    int lrow = tid >> 2;
    int lk4 = (tid & 3) << 2;
    int lkb = tid >> 4;
    int ln4 = (tid & 15) << 2;

    float acc[4][4];
#pragma unroll
    for (int i = 0; i < 4; i++)
#pragma unroll
        for (int j = 0; j < 4; j++) acc[i][j] = 0.f;

    for (int k0 = 0; k0 < H; k0 += 16) {
        float4 av = make_float4(0.f, 0.f, 0.f, 0.f);
        if (m0 + lrow < g.M)
            av = *(const float4*)(g.A + (size_t)(k0 >> 7) * g.khstr +
                                  (size_t)(m0 + lrow) * KP + ((k0 + lk4) & 127));
        As[lk4 + 0][lrow] = av.x;
        As[lk4 + 1][lrow] = av.y;
        As[lk4 + 2][lrow] = av.z;
        As[lk4 + 3][lrow] = av.w;
        const float* wp = g.W + (size_t)(k0 + lkb) * g.N + n0 + ln4;
        float4 bv;
        bv.x = (n0 + ln4 + 0 < g.N) ? wp[0] : 0.f;
        bv.y = (n0 + ln4 + 1 < g.N) ? wp[1] : 0.f;
        bv.z = (n0 + ln4 + 2 < g.N) ? wp[2] : 0.f;
        bv.w = (n0 + ln4 + 3 < g.N) ? wp[3] : 0.f;
        *(float4*)&Bs[lkb][ln4] = bv;
        __syncthreads();
#pragma unroll
        for (int kk = 0; kk < 16; kk++) {
            float a0 = As[kk][tm * 4 + 0];
            float a1 = As[kk][tm * 4 + 1];
            float a2 = As[kk][tm * 4 + 2];
            float a3 = As[kk][tm * 4 + 3];
            float4 b = *(const float4*)&Bs[kk][tn * 4];
            acc[0][0] += a0 * b.x; acc[0][1] += a0 * b.y; acc[0][2] += a0 * b.z; acc[0][3] += a0 * b.w;
            acc[1][0] += a1 * b.x; acc[1][1] += a1 * b.y; acc[1][2] += a1 * b.z; acc[1][3] += a1 * b.w;
            acc[2][0] += a2 * b.x; acc[2][1] += a2 * b.y; acc[2][2] += a2 * b.z; acc[2][3] += a2 * b.w;
            acc[3][0] += a3 * b.x; acc[3][1] += a3 * b.y; acc[3][2] += a3 * b.z; acc[3][3] += a3 * b.w;
        }
        __syncthreads();
    }

#pragma unroll
    for (int i = 0; i < 4; i++) {
        int m = m0 + tm * 4 + i;
        if (m >= g.M) continue;
#pragma unroll
        for (int j = 0; j < 4; j++) {
            int n = n0 + tn * 4 + j;
            if (n < g.N) g.C[(size_t)m * g.N + n] = acc[i][j] + g.bias[n];
        }
    }
}

// ---------------- BN kernels (plane layout) ----------------
__global__ void zero_stats_kernel() {
    g_sum[threadIdx.x] = 0.f;
    g_sumsq[threadIdx.x] = 0.f;
}

// computes scale/shift, then re-zeroes the stats accumulators for the next use
__global__ void bn_finalize_kernel(const float* __restrict__ gamma,
                                   const float* __restrict__ beta, float invM) {
    int col = threadIdx.x;
    float mean = g_sum[col] * invM;
    float var = g_sumsq[col] * invM - mean * mean;
    float sc = gamma[col] * rsqrtf(var + 1e-5f);
    g_scale[col] = sc;
    g_shift[col] = beta[col] - mean * sc;
    g_sum[col] = 0.f;
    g_sumsq[col] = 0.f;
}

// act 0 = ELU, 1 = ReLU; rnd -> round to tf32 for tensor-GEMM consumers
__global__ void bn_apply_kernel(float* __restrict__ h, int M, long khstr,
                                int act, int rnd) {
    long i = (long)blockIdx.x * blockDim.x + threadIdx.x;
    if (i >= (long)M * H) return;
    int col = (int)(i & (H - 1));
    long row = i >> 8;
    float* hp = h + (size_t)(col >> 7) * khstr + row * KP + (col & 127);
    float v = *hp * g_scale[col] + g_shift[col];
    if (act == 0)
        v = (v > 0.f) ? v : expm1f(v);
    else
        v = (v > 0.f) ? v : 0.f;
    if (rnd) v = rtf(v);
    *hp = v;
}

// ---------------- host orchestration ----------------
static inline int cdiv(long a, long b) { return (int)((a + b - 1) / b); }

extern "C" void kernel_launch(void* const* d_in, const int* in_sizes, int n_in,
                              void* d_out, int out_size) {
    const float* x   = (const float*)d_in[0];
    const int* src0  = (const int*)d_in[1];
    const int* dst0  = (const int*)d_in[2];
    const int* et0   = (const int*)d_in[3];
    const int* src1  = (const int*)d_in[4];
    const int* dst1  = (const int*)d_in[5];
    const int* et1   = (const int*)d_in[6];
    const float* W0  = (const float*)d_in[9];
    const float* Wl0 = (const float*)d_in[10];
    const float* b0  = (const float*)d_in[11];
    const float* g0  = (const float*)d_in[12];
    const float* be0 = (const float*)d_in[13];
    const float* W1  = (const float*)d_in[14];
    const float* Wl1 = (const float*)d_in[15];
    const float* b1  = (const float*)d_in[16];
    const float* g1  = (const float*)d_in[17];
    const float* be1 = (const float*)d_in[18];
    const float* Wm1 = (const float*)d_in[19];
    const float* bm1 = (const float*)d_in[20];
    const float* gm  = (const float*)d_in[21];
    const float* bem = (const float*)d_in[22];
    const float* Wm2 = (const float*)d_in[23];
    const float* bm2 = (const float*)d_in[24];
    float* out = (float*)d_out;

    const int E0 = in_sizes[1];
    const int E1 = in_sizes[4];
    const int COUT = 153;
    const int M1 = out_size / COUT;   // 10000
    const int M0 = M0_CONST;          // 50000

    float *A0, *A1, *H0, *H1, *Mh, *Wt;
    int *cnt, *off, *cur, *eidx;
    cudaGetSymbolAddress((void**)&A0, g_A0);
    cudaGetSymbolAddress((void**)&A1, g_A1);
    cudaGetSymbolAddress((void**)&H0, g_H0);
    cudaGetSymbolAddress((void**)&H1, g_H1);
    cudaGetSymbolAddress((void**)&Mh, g_Mh);
    cudaGetSymbolAddress((void**)&Wt, g_Wt);
    cudaGetSymbolAddress((void**)&cnt, g_cnt);
    cudaGetSymbolAddress((void**)&off, g_off);
    cudaGetSymbolAddress((void**)&cur, g_cur);
    cudaGetSymbolAddress((void**)&eidx, g_eidx);

    cudaFuncSetAttribute(gemm_bulk,
                         cudaFuncAttributeMaxDynamicSharedMemorySize, SM_TOTAL);

    // ---- layer 0: CSR + gather (profiled slot 3) + GEMM(fused stats) ----
    hist_kernel<<<cdiv(E0, 256), 256>>>(dst0, E0, cnt);                     // 0
    scan_kernel<<<1, 1024>>>(cnt, off, cur, M0);                            // 1
    scatter_kernel<<<cdiv(E0, 256), 256>>>(src0, dst0, et0, E0, cur, eidx); // 2
    gather_kernel<<<M0, 64>>>(x, eidx, off, cnt, A0, M0P, H, 128);          // 3 <- profiled
    transpose_weights<<<dim3(13, 8, 8), dim3(32, 8)>>>(W0, Wl0, W1, Wl1, Wm1);
    zero_stats_kernel<<<1, H>>>();    // safety: establish zeroed accumulators

    TGArgs ga;
    ga.A = A0;  ga.MP = M0P;
    ga.W = Wt;  ga.nseg = NSEG;  ga.M = M0;  ga.bias = b0;
    ga.C = H0;  ga.CMP = M0P;  ga.do_stats = 1;
    gemm_bulk<<<dim3(2, cdiv(M0, 128)), 256, SM_TOTAL>>>(ga);

    bn_finalize_kernel<<<1, H>>>(g0, be0, 1.0f / M0);
    bn_apply_kernel<<<cdiv((long)M0 * H, 256), 256>>>(H0, M0, (long)M0P * KP, 0, 1);

    // ---- layer 1 ----
    hist_kernel<<<cdiv(E1, 256), 256>>>(dst1, E1, cnt);
    scan_kernel<<<1, 1024>>>(cnt, off, cur, M1);
    scatter_kernel<<<cdiv(E1, 256), 256>>>(src1, dst1, et1, E1, cur, eidx);
    gather_kernel<<<M1, 64>>>(H0, eidx, off, cnt, A1, M1P, KP, M0P * KP);

    ga.A = A1;  ga.MP = M1P;
    ga.W = Wt + (size_t)6 * 2 * 256 * KP;
    ga.nseg = NSEG;  ga.M = M1;  ga.bias = b1;
    ga.C = H1;  ga.CMP = M1P;  ga.do_stats = 1;
    gemm_bulk<<<dim3(2, cdiv(M1, 128)), 256, SM_TOTAL>>>(ga);

    bn_finalize_kernel<<<1, H>>>(g1, be1, 1.0f / M1);
    bn_apply_kernel<<<cdiv((long)M1 * H, 256), 256>>>(H1, M1, (long)M1P * KP, 0, 1);

    // ---- MLP head ----
    ga.A = H1;  ga.MP = M1P;
    ga.W = Wt + (size_t)12 * 2 * 256 * KP;
    ga.nseg = 1;  ga.M = M1;  ga.bias = bm1;
    ga.C = Mh;  ga.CMP = M1P;  ga.do_stats = 1;
    gemm_bulk<<<dim3(2, cdiv(M1, 128)), 256, SM_TOTAL>>>(ga);

    bn_finalize_kernel<<<1, H>>>(gm, bem, 1.0f / M1);
    bn_apply_kernel<<<cdiv((long)M1 * H, 256), 256>>>(Mh, M1, (long)M1P * KP, 1, 0);

    GemmArgs gf;
    gf.A = Mh;  gf.khstr = (long)M1P * KP;
    gf.W = Wm2;
    gf.M = M1;  gf.N = COUT;  gf.bias = bm2;  gf.C = out;
    gemm_kernel<<<dim3(cdiv(M1, 64), cdiv(COUT, 64)), 256>>>(gf);
}

// round 15
// speedup vs baseline: 2.2131x; 1.0032x over previous
#include <cuda_runtime.h>
#include <math.h>
#include <stdint.h>

#define H 256
#define RREL 5
#define NSEG 6            // 5 relations + self-loop
#define M0_CONST 50000
#define M1_CONST 10000
#define M0P 50048         // padded to 128
#define M1P 10112
#define E0_MAX 800000
#define KP 132            // padded half-K row stride (floats); 528B, conflict-free ldmatrix

// ---------------- scratch (device globals: allocation-free) ----------------
// GEMM operand layout: half-K planes [plane][row][KP], plane = seg*2 + kh.
__device__ float g_A0[(size_t)NSEG * 2 * M0P * KP];
__device__ float g_A1[(size_t)NSEG * 2 * M1P * KP];
__device__ float g_H0[(size_t)2 * M0P * KP];
__device__ float g_H1[(size_t)2 * M1P * KP];
__device__ float g_Mh[(size_t)2 * M1P * KP];
__device__ float g_Wt[(size_t)13 * 2 * 256 * KP];  // [mat][kh][n][KP], tf32-rounded
__device__ int   g_cnt[M0_CONST + 4];
__device__ int   g_off[M0_CONST + 4];
__device__ int   g_cur[M0_CONST + 4];
__device__ int   g_eidx[E0_MAX];
__device__ float g_sum[3][H];      // per-layer BN stats (zeroed once per replay)
__device__ float g_sumsq[3][H];

// ---------------- helpers ----------------
__device__ __forceinline__ uint32_t f2tf32(float v) {
    uint32_t t;
    asm("cvt.rna.tf32.f32 %0, %1;" : "=r"(t) : "f"(v));
    return t;
}
__device__ __forceinline__ float rtf(float v) { return __uint_as_float(f2tf32(v)); }

__device__ __forceinline__ uint32_t smem_u32(const void* p) {
    uint32_t a;
    asm("{ .reg .u64 t; cvta.to.shared.u64 t, %1; cvt.u32.u64 %0, t; }"
        : "=r"(a) : "l"(p));
    return a;
}

#define MBAR_INIT(addr, cnt)                                                   \
    asm volatile("mbarrier.init.shared.b64 [%0], %1;" :: "r"(addr), "r"(cnt) : "memory")

#define MBAR_EXPECT(addr, bytes)                                               \
    asm volatile("mbarrier.arrive.expect_tx.shared.b64 _, [%0], %1;"           \
                 :: "r"(addr), "r"(bytes) : "memory")

#define BULK_G2S(dst, src, bytes, mbar)                                        \
    asm volatile(                                                              \
        "cp.async.bulk.shared::cluster.global.mbarrier::complete_tx::bytes "   \
        "[%0], [%1], %2, [%3];"                                                \
        :: "r"(dst), "l"(src), "r"(bytes), "r"(mbar) : "memory")

#define NAMED_BAR(id)                                                          \
    asm volatile("bar.sync %0, 128;" :: "r"(id) : "memory")

__device__ __forceinline__ void mbar_wait(uint32_t mbar, uint32_t parity) {
    uint32_t done;
    asm volatile(
        "{\n\t.reg .pred p;\n\t"
        "mbarrier.try_wait.parity.acquire.cta.shared::cta.b64 p, [%1], %2;\n\t"
        "selp.b32 %0, 1, 0, p;\n\t}"
        : "=r"(done) : "r"(mbar), "r"(parity) : "memory");
    if (!done) {
        asm volatile(
            "{\n\t.reg .pred P1;\n\t"
            "W_%=:\n\t"
            "mbarrier.try_wait.parity.acquire.cta.shared::cta.b64 P1, [%0], %1, 0x989680;\n\t"
            "@P1 bra.uni D_%=;\n\t"
            "bra.uni W_%=;\n\t"
            "D_%=:\n\t}"
            :: "r"(mbar), "r"(parity) : "memory");
    }
}

// ---------------- CSR build (dst-keyed, relation packed into eidx) --------
__global__ void hist_kernel(const int* __restrict__ dst, int E, int* __restrict__ cnt) {
    int e = blockIdx.x * 256 + threadIdx.x;
    if (e < E) atomicAdd(&cnt[dst[e]], 1);
}

__global__ void scan_kernel(const int* __restrict__ cnt, int* __restrict__ off,
                            int* __restrict__ cur, int n) {
    __shared__ int part[1024];
    int t = threadIdx.x;
    int chunk = (n + 1023) >> 10;
    int a = t * chunk;
    int b = min(a + chunk, n);
    int s = 0;
#pragma unroll 4
    for (int i = a; i < b; i++) s += cnt[i];
    part[t] = s;
    __syncthreads();
    for (int d = 1; d < 1024; d <<= 1) {
        int v = (t >= d) ? part[t - d] : 0;
        __syncthreads();
        part[t] += v;
        __syncthreads();
    }
    int run = (t == 0) ? 0 : part[t - 1];
    for (int i = a; i < b; i++) { off[i] = run; cur[i] = run; run += cnt[i]; }
    if (b == n) off[n] = run;
}

__global__ void scatter_kernel(const int* __restrict__ src, const int* __restrict__ dst,
                               const int* __restrict__ et, int E,
                               int* __restrict__ cur, int* __restrict__ eidx) {
    int e = blockIdx.x * 256 + threadIdx.x;
    if (e < E) {
        int p = atomicAdd(&cur[dst[e]], 1);
        eidx[p] = (et[e] << 24) | src[e];
    }
}

// One block (64 thr) per dst node; thread t owns channels [4t, 4t+4).
__global__ void __launch_bounds__(64, 21)
gather_kernel(const float* __restrict__ x, const int* __restrict__ eidx,
              const int* __restrict__ off, int* __restrict__ cnt,
              float* __restrict__ A, int ndstp, int src_lda, int src_khstr) {
    int d = blockIdx.x;
    int t = threadIdx.x;          // 0..63
    int c = t * 4;
    int kh = c >> 7;
    int inner = c & 127;
    const float* xb = x + kh * src_khstr + inner;   // row base for this thread
    int beg = off[d], end = off[d + 1];
    float4 a0 = make_float4(0.f, 0.f, 0.f, 0.f);
    float4 a1 = a0, a2 = a0, a3 = a0, a4 = a0;
#define ACCUM(pk_, v_)                                                         \
    {                                                                          \
        int r_ = (pk_) >> 24;                                                  \
        if (r_ == 0) { a0.x += (v_).x; a0.y += (v_).y; a0.z += (v_).z; a0.w += (v_).w; } \
        if (r_ == 1) { a1.x += (v_).x; a1.y += (v_).y; a1.z += (v_).z; a1.w += (v_).w; } \
        if (r_ == 2) { a2.x += (v_).x; a2.y += (v_).y; a2.z += (v_).z; a2.w += (v_).w; } \
        if (r_ == 3) { a3.x += (v_).x; a3.y += (v_).y; a3.z += (v_).z; a3.w += (v_).w; } \
        if (r_ == 4) { a4.x += (v_).x; a4.y += (v_).y; a4.z += (v_).z; a4.w += (v_).w; } \
    }
    int i = beg;
    for (; i + 1 < end; i += 2) {
        int pk0 = eidx[i];
        int pk1 = eidx[i + 1];
        float4 v0 = *(const float4*)(xb + (size_t)(pk0 & 0xFFFFFF) * src_lda);
        float4 v1 = *(const float4*)(xb + (size_t)(pk1 & 0xFFFFFF) * src_lda);
        ACCUM(pk0, v0);
        ACCUM(pk1, v1);
    }
    if (i < end) {
        int pk0 = eidx[i];
        float4 v0 = *(const float4*)(xb + (size_t)(pk0 & 0xFFFFFF) * src_lda);
        ACCUM(pk0, v0);
    }
    float* ab = A + ((size_t)kh * ndstp + d) * KP + inner;
    size_t step = (size_t)2 * ndstp * KP;
#define RSTORE(k, av)                                                          \
    {                                                                          \
        float4 o;                                                              \
        o.x = rtf((av).x); o.y = rtf((av).y);                                  \
        o.z = rtf((av).z); o.w = rtf((av).w);                                  \
        *(float4*)(ab + (k) * step) = o;                                       \
    }
    RSTORE(0, a0); RSTORE(1, a1); RSTORE(2, a2); RSTORE(3, a3); RSTORE(4, a4);
    float4 sv = *(const float4*)(xb + (size_t)d * src_lda);
    RSTORE(5, sv);
    if (t == 0) cnt[d] = 0;
}

// ---------------- weight transpose (one-shot per launch, tf32-rounded) ----
__global__ void transpose_weights(const float* W0, const float* Wl0,
                                  const float* W1, const float* Wl1,
                                  const float* Wm1) {
    __shared__ float t[32][33];
    int m = blockIdx.x;
    const float* src = (m < 5)   ? W0 + (size_t)m * H * H
                     : (m == 5)  ? Wl0
                     : (m < 11)  ? W1 + (size_t)(m - 6) * H * H
                     : (m == 11) ? Wl1 : Wm1;
    float* dst = g_Wt + (size_t)m * 2 * 256 * KP;
    int bx = blockIdx.y * 32, by = blockIdx.z * 32;
    int x = threadIdx.x, y = threadIdx.y;
#pragma unroll
    for (int i = 0; i < 32; i += 8)
        t[y + i][x] = src[(size_t)(by + y + i) * H + bx + x];
    __syncthreads();
#pragma unroll
    for (int i = 0; i < 32; i += 8) {
        int n = bx + y + i;
        int k = by + x;
        dst[((size_t)(k >> 7) * 256 + n) * KP + (k & 127)] = rtf(t[x][y + i]);
    }
}

// ---------------- tf32 tensor GEMM: half-K planes, 2 CTAs/SM --------------
// Epilogue accumulates per-column BN stats (sum/sumsq incl bias) into
// g_sum[layer]/g_sumsq[layer] hierarchically (thread->shfl->smem->1 atomic).
struct TGArgs {
    const float* A; long MP;     // plane rows (padded)
    const float* W;              // [nseg][2][256][KP]
    int nseg; int M;
    const float* bias;
    float* C; long CMP;          // C plane rows (padded)
    int layer;                   // stats slot
};

#define CH_BYTES (32 * KP * 4)        // 16896
#define B_BYTES  (128 * KP * 4)       // 67584
#define SM_A0 1024
#define SM_A1 (1024 + CH_BYTES)       // 17920
#define SM_B  (1024 + 2 * CH_BYTES)   // 34816
#define SM_TOTAL (SM_B + B_BYTES)     // 102400
// mbarriers: A-buf g @ sb+8g, B @ sb+16

__device__ __forceinline__ void mma32(uint32_t ab, uint32_t bb,
                                      int wq, int rowl, int khalf,
                                      float (*acc)[4][4]) {
#pragma unroll 4
    for (int kq = 0; kq < 16; kq++) {
        int q = kq * 8 + khalf;
        uint32_t a[2][4], b[2][4];
#pragma unroll
        for (int im = 0; im < 2; im++) {
            uint32_t ad = ab + (((im * 16 + rowl) * KP + q) << 2);
            asm volatile(
                "ldmatrix.sync.aligned.m8n8.x4.shared.b16 {%0,%1,%2,%3}, [%4];"
                : "=r"(a[im][0]), "=r"(a[im][1]), "=r"(a[im][2]), "=r"(a[im][3])
                : "r"(ad));
        }
#pragma unroll
        for (int i2 = 0; i2 < 2; i2++) {
            uint32_t bd = bb + (((wq * 32 + i2 * 16 + rowl) * KP + q) << 2);
            asm volatile(
                "ldmatrix.sync.aligned.m8n8.x4.shared.b16 {%0,%1,%2,%3}, [%4];"
                : "=r"(b[i2][0]), "=r"(b[i2][1]), "=r"(b[i2][2]), "=r"(b[i2][3])
                : "r"(bd));
        }
#pragma unroll
        for (int im = 0; im < 2; im++)
#pragma unroll
            for (int in_ = 0; in_ < 4; in_++) {
                int i2 = in_ >> 1, p = in_ & 1;
                asm volatile(
                    "mma.sync.aligned.m16n8k8.row.col.f32.tf32.tf32.f32 "
                    "{%0,%1,%2,%3}, {%4,%5,%6,%7}, {%8,%9}, {%0,%1,%2,%3};\n"
                    : "+f"(acc[im][in_][0]), "+f"(acc[im][in_][1]),
                      "+f"(acc[im][in_][2]), "+f"(acc[im][in_][3])
                    : "r"(a[im][0]), "r"(a[im][1]), "r"(a[im][2]), "r"(a[im][3]),
                      "r"(b[i2][p]), "r"(b[i2][2 + p]));
            }
    }
}

__global__ void __launch_bounds__(256, 2) gemm_bulk(TGArgs g) {
    extern __shared__ char sm[];
    uint32_t sb = smem_u32(sm);
    int tid = threadIdx.x, warp = tid >> 5, lane = tid & 31;
    int gidx = warp >> 2;         // group 0/1 -> A buf, chunks {g, g+2}
    int wq = warp & 3;            // n quarter
    int n0 = blockIdx.x * 128;    // n-tile fastest
    int m0 = blockIdx.y * 128;
    int rowl = lane & 15, khalf = (lane >> 4) * 4;
    int lr = lane >> 2, lc = lane & 3;
    uint32_t mbarA = sb + 8 * gidx;
    uint32_t mbarB = sb + 16;
    uint32_t bufA = sb + (gidx ? SM_A1 : SM_A0);
    uint32_t bb = sb + SM_B;
    int barid = 1 + gidx;
    bool leader = (tid == gidx * 128);
    int nst = g.nseg * 2;

    if (tid == 0) {
        MBAR_INIT(sb + 0, 1);
        MBAR_INIT(sb + 8, 1);
        MBAR_INIT(sb + 16, 1);
    }
    __syncthreads();

    float acc[2][2][4][4];        // [ci][im][in][reg]
#pragma unroll
    for (int ci = 0; ci < 2; ci++)
#pragma unroll
        for (int im = 0; im < 2; im++)
#pragma unroll
            for (int j = 0; j < 4; j++)
#pragma unroll
                for (int k = 0; k < 4; k++) acc[ci][im][j][k] = 0.f;

    // prologue: stage 0
    {
        const float* asrc0 = g.A + (size_t)m0 * KP;
        if (tid == 0) {
            MBAR_EXPECT(mbarB, B_BYTES);
            BULK_G2S(sb + SM_B, g.W + (size_t)n0 * KP, B_BYTES, mbarB);
        }
        if (leader) {
            MBAR_EXPECT(mbarA, CH_BYTES);
            BULK_G2S(bufA, asrc0 + (size_t)gidx * 32 * KP, CH_BYTES, mbarA);
        }
    }

    int pA = 0, pB = 0;
    for (int s = 0; s < nst; s++) {
        const float* asrc = g.A + ((size_t)s * g.MP + m0) * KP;
        const float* nasrc = asrc + (size_t)g.MP * KP;
        bool more = (s + 1 < nst);

        mbar_wait(mbarA, pA); pA ^= 1;
        mbar_wait(mbarB, pB);
        mma32(bufA, bb, wq, rowl, khalf, acc[0]);
        NAMED_BAR(barid);
        if (leader) {
            MBAR_EXPECT(mbarA, CH_BYTES);
            BULK_G2S(bufA, asrc + (size_t)(2 + gidx) * 32 * KP, CH_BYTES, mbarA);
        }
        mbar_wait(mbarA, pA); pA ^= 1;
        mma32(bufA, bb, wq, rowl, khalf, acc[1]);
        NAMED_BAR(barid);
        if (leader && more) {
            MBAR_EXPECT(mbarA, CH_BYTES);
            BULK_G2S(bufA, nasrc + (size_t)gidx * 32 * KP, CH_BYTES, mbarA);
        }
        __syncthreads();
        if (tid == 0 && more) {
            MBAR_EXPECT(mbarB, B_BYTES);
            BULK_G2S(sb + SM_B, g.W + ((size_t)(s + 1) * 256 + n0) * KP,
                     B_BYTES, mbarB);
        }
        pB ^= 1;
    }

    // ---- epilogue: bias + store + fused BN stats ----
    float* ss = (float*)(sm + SM_A0);   // reuse A buf: [0..127]=sum, [128..255]=sumsq
    ss[tid] = 0.f;
    __syncthreads();
#pragma unroll
    for (int in_ = 0; in_ < 4; in_++) {
        int lcol = wq * 32 + in_ * 8 + lc * 2;   // local column (0..126)
        int col = n0 + lcol;
        float bia0 = g.bias[col];
        float bia1 = g.bias[col + 1];
        float s0 = 0.f, q0 = 0.f, s1 = 0.f, q1 = 0.f;
        float* cp = g.C + (size_t)(col >> 7) * g.CMP * KP + (col & 127);
#pragma unroll
        for (int ci = 0; ci < 2; ci++) {
#pragma unroll
            for (int im = 0; im < 2; im++) {
                int mrow = m0 + (ci * 2 + gidx) * 32 + im * 16 + lr;
                if (mrow < g.M) {
                    float v0 = acc[ci][im][in_][0] + bia0;
                    float v1 = acc[ci][im][in_][1] + bia1;
                    *(float2*)(cp + (size_t)mrow * KP) = make_float2(v0, v1);
                    s0 += v0; q0 += v0 * v0; s1 += v1; q1 += v1 * v1;
                }
                if (mrow + 8 < g.M) {
                    float v2 = acc[ci][im][in_][2] + bia0;
                    float v3 = acc[ci][im][in_][3] + bia1;
                    *(float2*)(cp + (size_t)(mrow + 8) * KP) = make_float2(v2, v3);
                    s0 += v2; q0 += v2 * v2; s1 += v3; q1 += v3 * v3;
                }
            }
        }
        // reduce over the 8 row-lanes (lr = lane bits 2..4)
#pragma unroll
        for (int mk = 4; mk <= 16; mk <<= 1) {
            s0 += __shfl_xor_sync(0xffffffffu, s0, mk);
            q0 += __shfl_xor_sync(0xffffffffu, q0, mk);
            s1 += __shfl_xor_sync(0xffffffffu, s1, mk);
            q1 += __shfl_xor_sync(0xffffffffu, q1, mk);
        }
        if (lr == 0) {
            atomicAdd(&ss[lcol], s0);
            atomicAdd(&ss[128 + lcol], q0);
            atomicAdd(&ss[lcol + 1], s1);
            atomicAdd(&ss[128 + lcol + 1], q1);
        }
    }
    __syncthreads();
    if (tid < 128) {
        atomicAdd(&g_sum[g.layer][n0 + tid], ss[tid]);
        atomicAdd(&g_sumsq[g.layer][n0 + tid], ss[128 + tid]);
    }
}

// ---------------- SIMT GEMM (final 256x153; A in planes, W raw) -----------
struct GemmArgs {
    const float* A;   // planes [2][MP][KP]
    long khstr;       // MP*KP
    const float* W;   // [256][N] row-major
    int M, N;
    const float* bias;
    float* C;         // [M][N] dense
};

__global__ void gemm_kernel(GemmArgs g) {
    __shared__ float As[16][65];
    __shared__ float Bs[16][64];

    int tid = threadIdx.x;
    int m0 = blockIdx.x * 64;
    int n0 = blockIdx.y * 64;
    int tm = tid >> 4;
    int tn = tid & 15;

    int lrow = tid >> 2;
    int lk4 = (tid & 3) << 2;
    int lkb = tid >> 4;
    int ln4 = (tid & 15) << 2;

    float acc[4][4];
#pragma unroll
    for (int i = 0; i < 4; i++)
#pragma unroll
        for (int j = 0; j < 4; j++) acc[i][j] = 0.f;

    for (int k0 = 0; k0 < H; k0 += 16) {
        float4 av = make_float4(0.f, 0.f, 0.f, 0.f);
        if (m0 + lrow < g.M)
            av = *(const float4*)(g.A + (size_t)(k0 >> 7) * g.khstr +
                                  (size_t)(m0 + lrow) * KP + ((k0 + lk4) & 127));
        As[lk4 + 0][lrow] = av.x;
        As[lk4 + 1][lrow] = av.y;
        As[lk4 + 2][lrow] = av.z;
        As[lk4 + 3][lrow] = av.w;
        const float* wp = g.W + (size_t)(k0 + lkb) * g.N + n0 + ln4;
        float4 bv;
        bv.x = (n0 + ln4 + 0 < g.N) ? wp[0] : 0.f;
        bv.y = (n0 + ln4 + 1 < g.N) ? wp[1] : 0.f;
        bv.z = (n0 + ln4 + 2 < g.N) ? wp[2] : 0.f;
        bv.w = (n0 + ln4 + 3 < g.N) ? wp[3] : 0.f;
        *(float4*)&Bs[lkb][ln4] = bv;
        __syncthreads();
#pragma unroll
        for (int kk = 0; kk < 16; kk++) {
            float a0 = As[kk][tm * 4 + 0];
            float a1 = As[kk][tm * 4 + 1];
            float a2 = As[kk][tm * 4 + 2];
            float a3 = As[kk][tm * 4 + 3];
            float4 b = *(const float4*)&Bs[kk][tn * 4];
            acc[0][0] += a0 * b.x; acc[0][1] += a0 * b.y; acc[0][2] += a0 * b.z; acc[0][3] += a0 * b.w;
            acc[1][0] += a1 * b.x; acc[1][1] += a1 * b.y; acc[1][2] += a1 * b.z; acc[1][3] += a1 * b.w;
            acc[2][0] += a2 * b.x; acc[2][1] += a2 * b.y; acc[2][2] += a2 * b.z; acc[2][3] += a2 * b.w;
            acc[3][0] += a3 * b.x; acc[3][1] += a3 * b.y; acc[3][2] += a3 * b.z; acc[3][3] += a3 * b.w;
        }
        __syncthreads();
    }

#pragma unroll
    for (int i = 0; i < 4; i++) {
        int m = m0 + tm * 4 + i;
        if (m >= g.M) continue;
#pragma unroll
        for (int j = 0; j < 4; j++) {
            int n = n0 + tn * 4 + j;
            if (n < g.N) g.C[(size_t)m * g.N + n] = acc[i][j] + g.bias[n];
        }
    }
}

// ---------------- BN kernels (plane layout) ----------------
// zero all 3 layers' stats once per replay
__global__ void zero_stats3_kernel() {
    int t = threadIdx.x;
#pragma unroll
    for (int l = 0; l < 3; l++) {
        g_sum[l][t] = 0.f;
        g_sumsq[l][t] = 0.f;
    }
}

// fused finalize + apply: each thread computes scale/shift for its column
// from the (L2-hot) stats, then processes 8 rows. act 0=ELU, 1=ReLU;
// rnd -> tf32-round output.
__global__ void bn_apply_kernel(float* __restrict__ h, int M, long khstr,
                                const float* __restrict__ gamma,
                                const float* __restrict__ beta,
                                float invM, int layer, int act, int rnd) {
    int col = threadIdx.x;
    float mean = g_sum[layer][col] * invM;
    float var = g_sumsq[layer][col] * invM - mean * mean;
    float sc = gamma[col] * rsqrtf(var + 1e-5f);
    float sh = beta[col] - mean * sc;
    float* hp = h + (size_t)(col >> 7) * khstr + (col & 127);
    int r0 = blockIdx.x * 8;
    int rend = min(r0 + 8, M);
#pragma unroll 8
    for (int r = r0; r < rend; r++) {
        float v = hp[(size_t)r * KP] * sc + sh;
        if (act == 0)
            v = (v > 0.f) ? v : expm1f(v);
        else
            v = (v > 0.f) ? v : 0.f;
        if (rnd) v = rtf(v);
        hp[(size_t)r * KP] = v;
    }
}

// ---------------- host orchestration ----------------
static inline int cdiv(long a, long b) { return (int)((a + b - 1) / b); }

extern "C" void kernel_launch(void* const* d_in, const int* in_sizes, int n_in,
                              void* d_out, int out_size) {
    const float* x   = (const float*)d_in[0];
    const int* src0  = (const int*)d_in[1];
    const int* dst0  = (const int*)d_in[2];
    const int* et0   = (const int*)d_in[3];
    const int* src1  = (const int*)d_in[4];
    const int* dst1  = (const int*)d_in[5];
    const int* et1   = (const int*)d_in[6];
    const float* W0  = (const float*)d_in[9];
    const float* Wl0 = (const float*)d_in[10];
    const float* b0  = (const float*)d_in[11];
    const float* g0  = (const float*)d_in[12];
    const float* be0 = (const float*)d_in[13];
    const float* W1  = (const float*)d_in[14];
    const float* Wl1 = (const float*)d_in[15];
    const float* b1  = (const float*)d_in[16];
    const float* g1  = (const float*)d_in[17];
    const float* be1 = (const float*)d_in[18];
    const float* Wm1 = (const float*)d_in[19];
    const float* bm1 = (const float*)d_in[20];
    const float* gm  = (const float*)d_in[21];
    const float* bem = (const float*)d_in[22];
    const float* Wm2 = (const float*)d_in[23];
    const float* bm2 = (const float*)d_in[24];
    float* out = (float*)d_out;

    const int E0 = in_sizes[1];
    const int E1 = in_sizes[4];
    const int COUT = 153;
    const int M1 = out_size / COUT;   // 10000
    const int M0 = M0_CONST;          // 50000

    float *A0, *A1, *H0, *H1, *Mh, *Wt;
    int *cnt, *off, *cur, *eidx;
    cudaGetSymbolAddress((void**)&A0, g_A0);
    cudaGetSymbolAddress((void**)&A1, g_A1);
    cudaGetSymbolAddress((void**)&H0, g_H0);
    cudaGetSymbolAddress((void**)&H1, g_H1);
    cudaGetSymbolAddress((void**)&Mh, g_Mh);
    cudaGetSymbolAddress((void**)&Wt, g_Wt);
    cudaGetSymbolAddress((void**)&cnt, g_cnt);
    cudaGetSymbolAddress((void**)&off, g_off);
    cudaGetSymbolAddress((void**)&cur, g_cur);
    cudaGetSymbolAddress((void**)&eidx, g_eidx);

    cudaFuncSetAttribute(gemm_bulk,
                         cudaFuncAttributeMaxDynamicSharedMemorySize, SM_TOTAL);

    // ---- layer 0: CSR + gather (profiled slot 3) + GEMM(fused stats) ----
    hist_kernel<<<cdiv(E0, 256), 256>>>(dst0, E0, cnt);                     // 0
    scan_kernel<<<1, 1024>>>(cnt, off, cur, M0);                            // 1
    scatter_kernel<<<cdiv(E0, 256), 256>>>(src0, dst0, et0, E0, cur, eidx); // 2
    gather_kernel<<<M0, 64>>>(x, eidx, off, cnt, A0, M0P, H, 128);          // 3 <- profiled
    transpose_weights<<<dim3(13, 8, 8), dim3(32, 8)>>>(W0, Wl0, W1, Wl1, Wm1);
    zero_stats3_kernel<<<1, H>>>();

    TGArgs ga;
    ga.A = A0;  ga.MP = M0P;
    ga.W = Wt;  ga.nseg = NSEG;  ga.M = M0;  ga.bias = b0;
    ga.C = H0;  ga.CMP = M0P;  ga.layer = 0;
    gemm_bulk<<<dim3(2, cdiv(M0, 128)), 256, SM_TOTAL>>>(ga);

    bn_apply_kernel<<<cdiv(M0, 8), H>>>(H0, M0, (long)M0P * KP,
                                        g0, be0, 1.0f / M0, 0, 0, 1);

    // ---- layer 1 ----
    hist_kernel<<<cdiv(E1, 256), 256>>>(dst1, E1, cnt);
    scan_kernel<<<1, 1024>>>(cnt, off, cur, M1);
    scatter_kernel<<<cdiv(E1, 256), 256>>>(src1, dst1, et1, E1, cur, eidx);
    gather_kernel<<<M1, 64>>>(H0, eidx, off, cnt, A1, M1P, KP, M0P * KP);

    ga.A = A1;  ga.MP = M1P;
    ga.W = Wt + (size_t)6 * 2 * 256 * KP;
    ga.nseg = NSEG;  ga.M = M1;  ga.bias = b1;
    ga.C = H1;  ga.CMP = M1P;  ga.layer = 1;
    gemm_bulk<<<dim3(2, cdiv(M1, 128)), 256, SM_TOTAL>>>(ga);

    bn_apply_kernel<<<cdiv(M1, 8), H>>>(H1, M1, (long)M1P * KP,
                                        g1, be1, 1.0f / M1, 1, 0, 1);

    // ---- MLP head ----
    ga.A = H1;  ga.MP = M1P;
    ga.W = Wt + (size_t)12 * 2 * 256 * KP;
    ga.nseg = 1;  ga.M = M1;  ga.bias = bm1;
    ga.C = Mh;  ga.CMP = M1P;  ga.layer = 2;
    gemm_bulk<<<dim3(2, cdiv(M1, 128)), 256, SM_TOTAL>>>(ga);

    bn_apply_kernel<<<cdiv(M1, 8), H>>>(Mh, M1, (long)M1P * KP,
                                        gm, bem, 1.0f / M1, 2, 1, 0);

    GemmArgs gf;
    gf.A = Mh;  gf.khstr = (long)M1P * KP;
    gf.W = Wm2;
    gf.M = M1;  gf.N = COUT;  gf.bias = bm2;  gf.C = out;
    gemm_kernel<<<dim3(cdiv(M1, 64), cdiv(COUT, 64)), 256>>>(gf);
}

// round 16
// speedup vs baseline: 2.9964x; 1.3540x over previous
#include <cuda_runtime.h>
#include <cuda_fp16.h>
#include <math.h>
#include <stdint.h>

#define H 256
#define RREL 5
#define NSEG 6            // 5 relations + self-loop
#define M0_CONST 50000
#define M1_CONST 10000
#define M0P 50048         // padded to 128
#define M1P 10112
#define E0_MAX 800000
#define KH 264            // halves per row (528B): 16B-aligned, conflict-free ldmatrix
#define KHB 528           // row stride bytes

// ---------------- scratch (device globals: allocation-free) ----------------
// GEMM operands in fp16: A[seg][row][KH], Wt[mat][n][KH], H/Mh [row][KH].
__device__ __half g_A0[(size_t)NSEG * M0P * KH];
__device__ __half g_A1[(size_t)NSEG * M1P * KH];
__device__ __half g_H0[(size_t)M0P * KH];
__device__ __half g_H1[(size_t)M1P * KH];
__device__ __half g_Mh[(size_t)M1P * KH];
__device__ __half g_Wt[(size_t)13 * 256 * KH];
__device__ int    g_cnt[M0_CONST + 4];
__device__ int    g_off[M0_CONST + 4];
__device__ int    g_cur[M0_CONST + 4];
__device__ int    g_eidx[E0_MAX];
__device__ float  g_sum[3][H];     // per-layer BN stats (zeroed once per replay)
__device__ float  g_sumsq[3][H];

// ---------------- helpers ----------------
__device__ __forceinline__ uint32_t smem_u32(const void* p) {
    uint32_t a;
    asm("{ .reg .u64 t; cvta.to.shared.u64 t, %1; cvt.u32.u64 %0, t; }"
        : "=r"(a) : "l"(p));
    return a;
}

#define MBAR_INIT(addr, cnt)                                                   \
    asm volatile("mbarrier.init.shared.b64 [%0], %1;" :: "r"(addr), "r"(cnt) : "memory")

#define MBAR_EXPECT(addr, bytes)                                               \
    asm volatile("mbarrier.arrive.expect_tx.shared.b64 _, [%0], %1;"           \
                 :: "r"(addr), "r"(bytes) : "memory")

#define BULK_G2S(dst, src, bytes, mbar)                                        \
    asm volatile(                                                              \
        "cp.async.bulk.shared::cluster.global.mbarrier::complete_tx::bytes "   \
        "[%0], [%1], %2, [%3];"                                                \
        :: "r"(dst), "l"(src), "r"(bytes), "r"(mbar) : "memory")

#define NAMED_BAR(id)                                                          \
    asm volatile("bar.sync %0, 128;" :: "r"(id) : "memory")

__device__ __forceinline__ void mbar_wait(uint32_t mbar, uint32_t parity) {
    uint32_t done;
    asm volatile(
        "{\n\t.reg .pred p;\n\t"
        "mbarrier.try_wait.parity.acquire.cta.shared::cta.b64 p, [%1], %2;\n\t"
        "selp.b32 %0, 1, 0, p;\n\t}"
        : "=r"(done) : "r"(mbar), "r"(parity) : "memory");
    if (!done) {
        asm volatile(
            "{\n\t.reg .pred P1;\n\t"
            "W_%=:\n\t"
            "mbarrier.try_wait.parity.acquire.cta.shared::cta.b64 P1, [%0], %1, 0x989680;\n\t"
            "@P1 bra.uni D_%=;\n\t"
            "bra.uni W_%=;\n\t"
            "D_%=:\n\t}"
            :: "r"(mbar), "r"(parity) : "memory");
    }
}

__device__ __forceinline__ float4 ld4h(const __half* p) {
    uint2 u = *(const uint2*)p;
    __half2 h0 = *(__half2*)&u.x;
    __half2 h1 = *(__half2*)&u.y;
    float2 f0 = __half22float2(h0);
    float2 f1 = __half22float2(h1);
    return make_float4(f0.x, f0.y, f1.x, f1.y);
}

__device__ __forceinline__ void st4h(__half* p, float4 v) {
    __half2 h0 = __floats2half2_rn(v.x, v.y);
    __half2 h1 = __floats2half2_rn(v.z, v.w);
    uint2 u;
    u.x = *(uint32_t*)&h0;
    u.y = *(uint32_t*)&h1;
    *(uint2*)p = u;
}

// ---------------- CSR build (dst-keyed, relation packed into eidx) --------
__global__ void hist_kernel(const int* __restrict__ dst, int E, int* __restrict__ cnt) {
    int e = blockIdx.x * 256 + threadIdx.x;
    if (e < E) atomicAdd(&cnt[dst[e]], 1);
}

__global__ void scan_kernel(const int* __restrict__ cnt, int* __restrict__ off,
                            int* __restrict__ cur, int n) {
    __shared__ int part[1024];
    int t = threadIdx.x;
    int chunk = (n + 1023) >> 10;
    int a = t * chunk;
    int b = min(a + chunk, n);
    int s = 0;
#pragma unroll 4
    for (int i = a; i < b; i++) s += cnt[i];
    part[t] = s;
    __syncthreads();
    for (int d = 1; d < 1024; d <<= 1) {
        int v = (t >= d) ? part[t - d] : 0;
        __syncthreads();
        part[t] += v;
        __syncthreads();
    }
    int run = (t == 0) ? 0 : part[t - 1];
    for (int i = a; i < b; i++) { off[i] = run; cur[i] = run; run += cnt[i]; }
    if (b == n) off[n] = run;
}

__global__ void scatter_kernel(const int* __restrict__ src, const int* __restrict__ dst,
                               const int* __restrict__ et, int E,
                               int* __restrict__ cur, int* __restrict__ eidx) {
    int e = blockIdx.x * 256 + threadIdx.x;
    if (e < E) {
        int p = atomicAdd(&cur[dst[e]], 1);
        eidx[p] = (et[e] << 24) | src[e];
    }
}

// gather body: accumulate 5 relations in fp32, store fp16 rows.
#define GATHER_BODY(LOADV)                                                     \
    int d = blockIdx.x;                                                        \
    int t = threadIdx.x;                                                       \
    int c = t * 4;                                                             \
    int beg = off[d], end = off[d + 1];                                        \
    float4 a0 = make_float4(0.f, 0.f, 0.f, 0.f);                               \
    float4 a1 = a0, a2 = a0, a3 = a0, a4 = a0;                                 \
    int i = beg;                                                               \
    for (; i + 1 < end; i += 2) {                                              \
        int pk0 = eidx[i];                                                     \
        int pk1 = eidx[i + 1];                                                 \
        float4 v0 = LOADV(pk0 & 0xFFFFFF);                                     \
        float4 v1 = LOADV(pk1 & 0xFFFFFF);                                     \
        ACCUM(pk0, v0);                                                        \
        ACCUM(pk1, v1);                                                        \
    }                                                                          \
    if (i < end) {                                                             \
        int pk0 = eidx[i];                                                     \
        float4 v0 = LOADV(pk0 & 0xFFFFFF);                                     \
        ACCUM(pk0, v0);                                                        \
    }                                                                          \
    __half* ab = A + (size_t)d * KH + c;                                       \
    size_t step = (size_t)ndstp * KH;                                          \
    st4h(ab + 0 * step, a0);                                                   \
    st4h(ab + 1 * step, a1);                                                   \
    st4h(ab + 2 * step, a2);                                                   \
    st4h(ab + 3 * step, a3);                                                   \
    st4h(ab + 4 * step, a4);                                                   \
    st4h(ab + 5 * step, LOADV(d));                                             \
    if (t == 0) cnt[d] = 0;

#define ACCUM(pk_, v_)                                                         \
    {                                                                          \
        int r_ = (pk_) >> 24;                                                  \
        if (r_ == 0) { a0.x += (v_).x; a0.y += (v_).y; a0.z += (v_).z; a0.w += (v_).w; } \
        if (r_ == 1) { a1.x += (v_).x; a1.y += (v_).y; a1.z += (v_).z; a1.w += (v_).w; } \
        if (r_ == 2) { a2.x += (v_).x; a2.y += (v_).y; a2.z += (v_).z; a2.w += (v_).w; } \
        if (r_ == 3) { a3.x += (v_).x; a3.y += (v_).y; a3.z += (v_).z; a3.w += (v_).w; } \
        if (r_ == 4) { a4.x += (v_).x; a4.y += (v_).y; a4.z += (v_).z; a4.w += (v_).w; } \
    }

// layer 0: dense fp32 input, row stride 256
__global__ void __launch_bounds__(64, 21)
gather_f32(const float* __restrict__ x, const int* __restrict__ eidx,
           const int* __restrict__ off, int* __restrict__ cnt,
           __half* __restrict__ A, int ndstp) {
    const float* xb = x + threadIdx.x * 4;
#define LOADF(row_) (*(const float4*)(xb + (size_t)(row_) * H))
    GATHER_BODY(LOADF)
#undef LOADF
}

// layer 1: fp16 input, row stride KH
__global__ void __launch_bounds__(64, 21)
gather_f16(const __half* __restrict__ x, const int* __restrict__ eidx,
           const int* __restrict__ off, int* __restrict__ cnt,
           __half* __restrict__ A, int ndstp) {
    const __half* xb = x + threadIdx.x * 4;
#define LOADH(row_) ld4h(xb + (size_t)(row_) * KH)
    GATHER_BODY(LOADH)
#undef LOADH
}

// ---------------- weight transpose (one-shot per launch, fp16) ----------
__global__ void transpose_weights(const float* W0, const float* Wl0,
                                  const float* W1, const float* Wl1,
                                  const float* Wm1) {
    __shared__ float t[32][33];
    int m = blockIdx.x;
    const float* src = (m < 5)   ? W0 + (size_t)m * H * H
                     : (m == 5)  ? Wl0
                     : (m < 11)  ? W1 + (size_t)(m - 6) * H * H
                     : (m == 11) ? Wl1 : Wm1;
    __half* dst = g_Wt + (size_t)m * 256 * KH;
    int bx = blockIdx.y * 32, by = blockIdx.z * 32;
    int x = threadIdx.x, y = threadIdx.y;
#pragma unroll
    for (int i = 0; i < 32; i += 8)
        t[y + i][x] = src[(size_t)(by + y + i) * H + bx + x];
    __syncthreads();
#pragma unroll
    for (int i = 0; i < 32; i += 8) {
        int n = bx + y + i;
        int k = by + x;
        dst[(size_t)n * KH + k] = __float2half_rn(t[x][y + i]);
    }
}

// ---------------- fp16 tensor GEMM: full-K rows, 2 CTAs/SM ---------------
// C[M,256] = sum_s A_s @ Wt_s^T + bias (fp32 accum).  CTA 128m x 128n;
// nseg stages (K=256 each). B panel 128 x 528B = 67.6KB one bulk; A chunks
// 32 rows (16.9KB) dual-group double-buffered. Epilogue: fp16 store + fused
// BN stats (thread -> shfl -> smem -> 1 atomic/col/CTA).
struct TGArgs {
    const __half* A; long MP;    // rows (padded)
    const __half* W;             // [nseg][256][KH]
    int nseg; int M;
    const float* bias;
    __half* C;                   // [M][KH]
    int layer;                   // stats slot
};

#define CH_BYTES (32 * KHB)           // 16896
#define B_BYTES  (128 * KHB)          // 67584
#define SM_A0 1024
#define SM_A1 (1024 + CH_BYTES)       // 17920
#define SM_B  (1024 + 2 * CH_BYTES)   // 34816
#define SM_TOTAL (SM_B + B_BYTES)     // 102400
// mbarriers: A-buf g @ sb+8g, B @ sb+16

// warp computes m32 x n32 over K=256 with mma.m16n8k16.f16
__device__ __forceinline__ void mma16(uint32_t ab, uint32_t bb,
                                      int wq, int rowl, int k16,
                                      float (*acc)[4][4]) {
#pragma unroll 4
    for (int kq = 0; kq < 16; kq++) {
        int kb = kq * 32 + k16;      // byte offset within row
        uint32_t a[2][4], b[2][4];
#pragma unroll
        for (int im = 0; im < 2; im++) {
            uint32_t ad = ab + (im * 16 + rowl) * KHB + kb;
            asm volatile(
                "ldmatrix.sync.aligned.m8n8.x4.shared.b16 {%0,%1,%2,%3}, [%4];"
                : "=r"(a[im][0]), "=r"(a[im][1]), "=r"(a[im][2]), "=r"(a[im][3])
                : "r"(ad));
        }
#pragma unroll
        for (int i2 = 0; i2 < 2; i2++) {
            uint32_t bd = bb + (wq * 32 + i2 * 16 + rowl) * KHB + kb;
            asm volatile(
                "ldmatrix.sync.aligned.m8n8.x4.shared.b16 {%0,%1,%2,%3}, [%4];"
                : "=r"(b[i2][0]), "=r"(b[i2][1]), "=r"(b[i2][2]), "=r"(b[i2][3])
                : "r"(bd));
        }
#pragma unroll
        for (int im = 0; im < 2; im++)
#pragma unroll
            for (int in_ = 0; in_ < 4; in_++) {
                int i2 = in_ >> 1, j = in_ & 1;
                asm volatile(
                    "mma.sync.aligned.m16n8k16.row.col.f32.f16.f16.f32 "
                    "{%0,%1,%2,%3}, {%4,%5,%6,%7}, {%8,%9}, {%0,%1,%2,%3};\n"
                    : "+f"(acc[im][in_][0]), "+f"(acc[im][in_][1]),
                      "+f"(acc[im][in_][2]), "+f"(acc[im][in_][3])
                    : "r"(a[im][0]), "r"(a[im][1]), "r"(a[im][2]), "r"(a[im][3]),
                      "r"(b[i2][j]), "r"(b[i2][2 + j]));
            }
    }
}

__global__ void __launch_bounds__(256, 2) gemm_bulk(TGArgs g) {
    extern __shared__ char sm[];
    uint32_t sb = smem_u32(sm);
    int tid = threadIdx.x, warp = tid >> 5, lane = tid & 31;
    int gidx = warp >> 2;         // group 0/1 -> A buf, chunks {g, g+2}
    int wq = warp & 3;            // n quarter
    int n0 = blockIdx.x * 128;    // n-tile fastest (same-m CTAs adjacent)
    int m0 = blockIdx.y * 128;
    int rowl = lane & 15;
    int k16 = (lane >> 4) * 16;   // 16B half-select for ldmatrix
    int lr = lane >> 2, lc = lane & 3;
    uint32_t mbarA = sb + 8 * gidx;
    uint32_t mbarB = sb + 16;
    uint32_t bufA = sb + (gidx ? SM_A1 : SM_A0);
    uint32_t bb = sb + SM_B;
    int barid = 1 + gidx;
    bool leader = (tid == gidx * 128);
    int nst = g.nseg;

    if (tid == 0) {
        MBAR_INIT(sb + 0, 1);
        MBAR_INIT(sb + 8, 1);
        MBAR_INIT(sb + 16, 1);
    }
    __syncthreads();

    float acc[2][2][4][4];        // [ci][im][in][reg]
#pragma unroll
    for (int ci = 0; ci < 2; ci++)
#pragma unroll
        for (int im = 0; im < 2; im++)
#pragma unroll
            for (int j = 0; j < 4; j++)
#pragma unroll
                for (int k = 0; k < 4; k++) acc[ci][im][j][k] = 0.f;

    // prologue: stage 0
    {
        const __half* asrc0 = g.A + (size_t)m0 * KH;
        if (tid == 0) {
            MBAR_EXPECT(mbarB, B_BYTES);
            BULK_G2S(sb + SM_B, g.W + (size_t)n0 * KH, B_BYTES, mbarB);
        }
        if (leader) {
            MBAR_EXPECT(mbarA, CH_BYTES);
            BULK_G2S(bufA, asrc0 + (size_t)gidx * 32 * KH, CH_BYTES, mbarA);
        }
    }

    int pA = 0, pB = 0;
    for (int s = 0; s < nst; s++) {
        const __half* asrc = g.A + ((size_t)s * g.MP + m0) * KH;
        const __half* nasrc = asrc + (size_t)g.MP * KH;
        bool more = (s + 1 < nst);

        mbar_wait(mbarA, pA); pA ^= 1;
        mbar_wait(mbarB, pB);
        mma16(bufA, bb, wq, rowl, k16, acc[0]);
        NAMED_BAR(barid);
        if (leader) {
            MBAR_EXPECT(mbarA, CH_BYTES);
            BULK_G2S(bufA, asrc + (size_t)(2 + gidx) * 32 * KH, CH_BYTES, mbarA);
        }
        mbar_wait(mbarA, pA); pA ^= 1;
        mma16(bufA, bb, wq, rowl, k16, acc[1]);
        NAMED_BAR(barid);
        if (leader && more) {
            MBAR_EXPECT(mbarA, CH_BYTES);
            BULK_G2S(bufA, nasrc + (size_t)gidx * 32 * KH, CH_BYTES, mbarA);
        }
        __syncthreads();
        if (tid == 0 && more) {
            MBAR_EXPECT(mbarB, B_BYTES);
            BULK_G2S(sb + SM_B, g.W + ((size_t)(s + 1) * 256 + n0) * KH,
                     B_BYTES, mbarB);
        }
        pB ^= 1;
    }

    // ---- epilogue: bias + fp16 store + fused BN stats ----
    float* ss = (float*)(sm + SM_A0);   // [0..127]=sum, [128..255]=sumsq
    ss[tid] = 0.f;
    __syncthreads();
#pragma unroll
    for (int in_ = 0; in_ < 4; in_++) {
        int lcol = wq * 32 + in_ * 8 + lc * 2;   // local column (0..126)
        int col = n0 + lcol;
        float bia0 = g.bias[col];
        float bia1 = g.bias[col + 1];
        float s0 = 0.f, q0 = 0.f, s1 = 0.f, q1 = 0.f;
        __half* cp = g.C + col;
#pragma unroll
        for (int ci = 0; ci < 2; ci++) {
#pragma unroll
            for (int im = 0; im < 2; im++) {
                int mrow = m0 + (ci * 2 + gidx) * 32 + im * 16 + lr;
                if (mrow < g.M) {
                    float v0 = acc[ci][im][in_][0] + bia0;
                    float v1 = acc[ci][im][in_][1] + bia1;
                    *(__half2*)(cp + (size_t)mrow * KH) = __floats2half2_rn(v0, v1);
                    s0 += v0; q0 += v0 * v0; s1 += v1; q1 += v1 * v1;
                }
                if (mrow + 8 < g.M) {
                    float v2 = acc[ci][im][in_][2] + bia0;
                    float v3 = acc[ci][im][in_][3] + bia1;
                    *(__half2*)(cp + (size_t)(mrow + 8) * KH) = __floats2half2_rn(v2, v3);
                    s0 += v2; q0 += v2 * v2; s1 += v3; q1 += v3 * v3;
                }
            }
        }
#pragma unroll
        for (int mk = 4; mk <= 16; mk <<= 1) {
            s0 += __shfl_xor_sync(0xffffffffu, s0, mk);
            q0 += __shfl_xor_sync(0xffffffffu, q0, mk);
            s1 += __shfl_xor_sync(0xffffffffu, s1, mk);
            q1 += __shfl_xor_sync(0xffffffffu, q1, mk);
        }
        if (lr == 0) {
            atomicAdd(&ss[lcol], s0);
            atomicAdd(&ss[128 + lcol], q0);
            atomicAdd(&ss[lcol + 1], s1);
            atomicAdd(&ss[128 + lcol + 1], q1);
        }
    }
    __syncthreads();
    if (tid < 128) {
        atomicAdd(&g_sum[g.layer][n0 + tid], ss[tid]);
        atomicAdd(&g_sumsq[g.layer][n0 + tid], ss[128 + tid]);
    }
}

// ---------------- SIMT GEMM (final 256x153; A fp16, W fp32) ---------------
struct GemmArgs {
    const __half* A;  // [M][KH]
    const float* W;   // [256][N] row-major
    int M, N;
    const float* bias;
    float* C;         // [M][N] dense fp32
};

__global__ void gemm_kernel(GemmArgs g) {
    __shared__ float As[16][65];
    __shared__ float Bs[16][64];

    int tid = threadIdx.x;
    int m0 = blockIdx.x * 64;
    int n0 = blockIdx.y * 64;
    int tm = tid >> 4;
    int tn = tid & 15;

    int lrow = tid >> 2;
    int lk4 = (tid & 3) << 2;
    int lkb = tid >> 4;
    int ln4 = (tid & 15) << 2;

    float acc[4][4];
#pragma unroll
    for (int i = 0; i < 4; i++)
#pragma unroll
        for (int j = 0; j < 4; j++) acc[i][j] = 0.f;

    for (int k0 = 0; k0 < H; k0 += 16) {
        float4 av = make_float4(0.f, 0.f, 0.f, 0.f);
        if (m0 + lrow < g.M)
            av = ld4h(g.A + (size_t)(m0 + lrow) * KH + k0 + lk4);
        As[lk4 + 0][lrow] = av.x;
        As[lk4 + 1][lrow] = av.y;
        As[lk4 + 2][lrow] = av.z;
        As[lk4 + 3][lrow] = av.w;
        const float* wp = g.W + (size_t)(k0 + lkb) * g.N + n0 + ln4;
        float4 bv;
        bv.x = (n0 + ln4 + 0 < g.N) ? wp[0] : 0.f;
        bv.y = (n0 + ln4 + 1 < g.N) ? wp[1] : 0.f;
        bv.z = (n0 + ln4 + 2 < g.N) ? wp[2] : 0.f;
        bv.w = (n0 + ln4 + 3 < g.N) ? wp[3] : 0.f;
        *(float4*)&Bs[lkb][ln4] = bv;
        __syncthreads();
#pragma unroll
        for (int kk = 0; kk < 16; kk++) {
            float a0 = As[kk][tm * 4 + 0];
            float a1 = As[kk][tm * 4 + 1];
            float a2 = As[kk][tm * 4 + 2];
            float a3 = As[kk][tm * 4 + 3];
            float4 b = *(const float4*)&Bs[kk][tn * 4];
            acc[0][0] += a0 * b.x; acc[0][1] += a0 * b.y; acc[0][2] += a0 * b.z; acc[0][3] += a0 * b.w;
            acc[1][0] += a1 * b.x; acc[1][1] += a1 * b.y; acc[1][2] += a1 * b.z; acc[1][3] += a1 * b.w;
            acc[2][0] += a2 * b.x; acc[2][1] += a2 * b.y; acc[2][2] += a2 * b.z; acc[2][3] += a2 * b.w;
            acc[3][0] += a3 * b.x; acc[3][1] += a3 * b.y; acc[3][2] += a3 * b.z; acc[3][3] += a3 * b.w;
        }
        __syncthreads();
    }

#pragma unroll
    for (int i = 0; i < 4; i++) {
        int m = m0 + tm * 4 + i;
        if (m >= g.M) continue;
#pragma unroll
        for (int j = 0; j < 4; j++) {
            int n = n0 + tn * 4 + j;
            if (n < g.N) g.C[(size_t)m * g.N + n] = acc[i][j] + g.bias[n];
        }
    }
}

// ---------------- BN kernels ----------------
__global__ void zero_stats3_kernel() {
    int t = threadIdx.x;
#pragma unroll
    for (int l = 0; l < 3; l++) {
        g_sum[l][t] = 0.f;
        g_sumsq[l][t] = 0.f;
    }
}

// fused finalize + apply on fp16 rows. act 0=ELU, 1=ReLU.
__global__ void bn_apply_kernel(__half* __restrict__ h, int M,
                                const float* __restrict__ gamma,
                                const float* __restrict__ beta,
                                float invM, int layer, int act) {
    int col = threadIdx.x;
    float mean = g_sum[layer][col] * invM;
    float var = g_sumsq[layer][col] * invM - mean * mean;
    float sc = gamma[col] * rsqrtf(var + 1e-5f);
    float sh = beta[col] - mean * sc;
    __half* hp = h + col;
    int r0 = blockIdx.x * 8;
    int rend = min(r0 + 8, M);
#pragma unroll 8
    for (int r = r0; r < rend; r++) {
        float v = __half2float(hp[(size_t)r * KH]) * sc + sh;
        if (act == 0)
            v = (v > 0.f) ? v : expm1f(v);
        else
            v = (v > 0.f) ? v : 0.f;
        hp[(size_t)r * KH] = __float2half_rn(v);
    }
}

// ---------------- host orchestration ----------------
static inline int cdiv(long a, long b) { return (int)((a + b - 1) / b); }

extern "C" void kernel_launch(void* const* d_in, const int* in_sizes, int n_in,
                              void* d_out, int out_size) {
    const float* x   = (const float*)d_in[0];
    const int* src0  = (const int*)d_in[1];
    const int* dst0  = (const int*)d_in[2];
    const int* et0   = (const int*)d_in[3];
    const int* src1  = (const int*)d_in[4];
    const int* dst1  = (const int*)d_in[5];
    const int* et1   = (const int*)d_in[6];
    const float* W0  = (const float*)d_in[9];
    const float* Wl0 = (const float*)d_in[10];
    const float* b0  = (const float*)d_in[11];
    const float* g0  = (const float*)d_in[12];
    const float* be0 = (const float*)d_in[13];
    const float* W1  = (const float*)d_in[14];
    const float* Wl1 = (const float*)d_in[15];
    const float* b1  = (const float*)d_in[16];
    const float* g1  = (const float*)d_in[17];
    const float* be1 = (const float*)d_in[18];
    const float* Wm1 = (const float*)d_in[19];
    const float* bm1 = (const float*)d_in[20];
    const float* gm  = (const float*)d_in[21];
    const float* bem = (const float*)d_in[22];
    const float* Wm2 = (const float*)d_in[23];
    const float* bm2 = (const float*)d_in[24];
    float* out = (float*)d_out;

    const int E0 = in_sizes[1];
    const int E1 = in_sizes[4];
    const int COUT = 153;
    const int M1 = out_size / COUT;   // 10000
    const int M0 = M0_CONST;          // 50000

    __half *A0, *A1, *H0, *H1, *Mh, *Wt;
    int *cnt, *off, *cur, *eidx;
    cudaGetSymbolAddress((void**)&A0, g_A0);
    cudaGetSymbolAddress((void**)&A1, g_A1);
    cudaGetSymbolAddress((void**)&H0, g_H0);
    cudaGetSymbolAddress((void**)&H1, g_H1);
    cudaGetSymbolAddress((void**)&Mh, g_Mh);
    cudaGetSymbolAddress((void**)&Wt, g_Wt);
    cudaGetSymbolAddress((void**)&cnt, g_cnt);
    cudaGetSymbolAddress((void**)&off, g_off);
    cudaGetSymbolAddress((void**)&cur, g_cur);
    cudaGetSymbolAddress((void**)&eidx, g_eidx);

    cudaFuncSetAttribute(gemm_bulk,
                         cudaFuncAttributeMaxDynamicSharedMemorySize, SM_TOTAL);

    // ---- layer 0: CSR + gather (profiled slot 3) + GEMM(fused stats) ----
    hist_kernel<<<cdiv(E0, 256), 256>>>(dst0, E0, cnt);                     // 0
    scan_kernel<<<1, 1024>>>(cnt, off, cur, M0);                            // 1
    scatter_kernel<<<cdiv(E0, 256), 256>>>(src0, dst0, et0, E0, cur, eidx); // 2
    gather_f32<<<M0, 64>>>(x, eidx, off, cnt, A0, M0P);                     // 3 <- profiled
    transpose_weights<<<dim3(13, 8, 8), dim3(32, 8)>>>(W0, Wl0, W1, Wl1, Wm1);
    zero_stats3_kernel<<<1, H>>>();

    TGArgs ga;
    ga.A = A0;  ga.MP = M0P;
    ga.W = Wt;  ga.nseg = NSEG;  ga.M = M0;  ga.bias = b0;
    ga.C = H0;  ga.layer = 0;
    gemm_bulk<<<dim3(2, cdiv(M0, 128)), 256, SM_TOTAL>>>(ga);

    bn_apply_kernel<<<cdiv(M0, 8), H>>>(H0, M0, g0, be0, 1.0f / M0, 0, 0);

    // ---- layer 1 ----
    hist_kernel<<<cdiv(E1, 256), 256>>>(dst1, E1, cnt);
    scan_kernel<<<1, 1024>>>(cnt, off, cur, M1);
    scatter_kernel<<<cdiv(E1, 256), 256>>>(src1, dst1, et1, E1, cur, eidx);
    gather_f16<<<M1, 64>>>(H0, eidx, off, cnt, A1, M1P);

    ga.A = A1;  ga.MP = M1P;
    ga.W = Wt + (size_t)6 * 256 * KH;
    ga.nseg = NSEG;  ga.M = M1;  ga.bias = b1;
    ga.C = H1;  ga.layer = 1;
    gemm_bulk<<<dim3(2, cdiv(M1, 128)), 256, SM_TOTAL>>>(ga);

    bn_apply_kernel<<<cdiv(M1, 8), H>>>(H1, M1, g1, be1, 1.0f / M1, 1, 0);

    // ---- MLP head ----
    ga.A = H1;  ga.MP = M1P;
    ga.W = Wt + (size_t)12 * 256 * KH;
    ga.nseg = 1;  ga.M = M1;  ga.bias = bm1;
    ga.C = Mh;  ga.layer = 2;
    gemm_bulk<<<dim3(2, cdiv(M1, 128)), 256, SM_TOTAL>>>(ga);

    bn_apply_kernel<<<cdiv(M1, 8), H>>>(Mh, M1, gm, bem, 1.0f / M1, 2, 1);

    GemmArgs gf;
    gf.A = Mh;  gf.W = Wm2;
    gf.M = M1;  gf.N = COUT;  gf.bias = bm2;  gf.C = out;
    gemm_kernel<<<dim3(cdiv(M1, 64), cdiv(COUT, 64)), 256>>>(gf);
}

// round 17
// speedup vs baseline: 3.0392x; 1.0143x over previous
#include <cuda_runtime.h>
#include <cuda_fp16.h>
#include <math.h>
#include <stdint.h>

#define H 256
#define RREL 5
#define NSEG 6            // 5 relations + self-loop
#define M0_CONST 50000
#define M1_CONST 10000
#define M0P 50048         // padded to 128
#define M1P 10112
#define E0_MAX 800000
#define E1_MAX 200000
#define NSRC 200000
#define KH 264            // halves per row (528B): 16B-aligned, conflict-free ldmatrix
#define KHB 528           // row stride bytes

// ---------------- scratch (device globals: allocation-free) ----------------
__device__ __half g_X16[(size_t)NSRC * H];          // fp16 copy of x (L2-resident)
__device__ __half g_A0[(size_t)NSEG * M0P * KH];
__device__ __half g_A1[(size_t)NSEG * M1P * KH];
__device__ __half g_H0[(size_t)M0P * KH];
__device__ __half g_H1[(size_t)M1P * KH];
__device__ __half g_Mh[(size_t)M1P * KH];
__device__ __half g_Wt[(size_t)13 * 256 * KH];
__device__ int    g_cnt0[M0_CONST + 4];
__device__ int    g_off0[M0_CONST + 4];
__device__ int    g_cur0[M0_CONST + 4];
__device__ int    g_cnt1[M1_CONST + 4];
__device__ int    g_off1[M1_CONST + 4];
__device__ int    g_cur1[M1_CONST + 4];
__device__ int    g_eidx0[E0_MAX];
__device__ int    g_eidx1[E1_MAX];
__device__ float  g_sum[3][H];
__device__ float  g_sumsq[3][H];

// ---------------- helpers ----------------
__device__ __forceinline__ uint32_t smem_u32(const void* p) {
    uint32_t a;
    asm("{ .reg .u64 t; cvta.to.shared.u64 t, %1; cvt.u32.u64 %0, t; }"
        : "=r"(a) : "l"(p));
    return a;
}

#define MBAR_INIT(addr, cnt)                                                   \
    asm volatile("mbarrier.init.shared.b64 [%0], %1;" :: "r"(addr), "r"(cnt) : "memory")

#define MBAR_EXPECT(addr, bytes)                                               \
    asm volatile("mbarrier.arrive.expect_tx.shared.b64 _, [%0], %1;"           \
                 :: "r"(addr), "r"(bytes) : "memory")

#define BULK_G2S(dst, src, bytes, mbar)                                        \
    asm volatile(                                                              \
        "cp.async.bulk.shared::cluster.global.mbarrier::complete_tx::bytes "   \
        "[%0], [%1], %2, [%3];"                                                \
        :: "r"(dst), "l"(src), "r"(bytes), "r"(mbar) : "memory")

#define NAMED_BAR(id)                                                          \
    asm volatile("bar.sync %0, 128;" :: "r"(id) : "memory")

__device__ __forceinline__ void mbar_wait(uint32_t mbar, uint32_t parity) {
    uint32_t done;
    asm volatile(
        "{\n\t.reg .pred p;\n\t"
        "mbarrier.try_wait.parity.acquire.cta.shared::cta.b64 p, [%1], %2;\n\t"
        "selp.b32 %0, 1, 0, p;\n\t}"
        : "=r"(done) : "r"(mbar), "r"(parity) : "memory");
    if (!done) {
        asm volatile(
            "{\n\t.reg .pred P1;\n\t"
            "W_%=:\n\t"
            "mbarrier.try_wait.parity.acquire.cta.shared::cta.b64 P1, [%0], %1, 0x989680;\n\t"
            "@P1 bra.uni D_%=;\n\t"
            "bra.uni W_%=;\n\t"
            "D_%=:\n\t}"
            :: "r"(mbar), "r"(parity) : "memory");
    }
}

__device__ __forceinline__ float4 ld4h(const __half* p) {
    uint2 u = *(const uint2*)p;
    __half2 h0 = *(__half2*)&u.x;
    __half2 h1 = *(__half2*)&u.y;
    float2 f0 = __half22float2(h0);
    float2 f1 = __half22float2(h1);
    return make_float4(f0.x, f0.y, f1.x, f1.y);
}

__device__ __forceinline__ void st4h(__half* p, float4 v) {
    __half2 h0 = __floats2half2_rn(v.x, v.y);
    __half2 h1 = __floats2half2_rn(v.z, v.w);
    uint2 u;
    u.x = *(uint32_t*)&h0;
    u.y = *(uint32_t*)&h1;
    *(uint2*)p = u;
}

// ---------------- prep: x -> fp16 copy + both layers' histograms ----------
#define NCONV_BLK 50000     // 50000*256 threads * 4 elems = 51.2M = NSRC*H
__global__ void prep_kernel(const float* __restrict__ x,
                            const int* __restrict__ dst0, int E0,
                            const int* __restrict__ dst1, int E1) {
    int b = blockIdx.x;
    int t = threadIdx.x;
    if (b < NCONV_BLK) {
        size_t i = ((size_t)b * 256 + t) * 4;
        float4 v = *(const float4*)(x + i);
        st4h(g_X16 + i, v);
    } else {
        int e = (b - NCONV_BLK) * 256 + t;
        if (e < E0) atomicAdd(&g_cnt0[dst0[e]], 1);
        int e1 = e - E0;
        if (e1 >= 0 && e1 < E1) atomicAdd(&g_cnt1[dst1[e1]], 1);
    }
}

// scan both layers: block 0 -> layer 0, block 1 -> layer 1
__global__ void scan_both_kernel(int M0v, int M1v) {
    __shared__ int part[1024];
    const int* cnt = blockIdx.x ? g_cnt1 : g_cnt0;
    int* off = blockIdx.x ? g_off1 : g_off0;
    int* cur = blockIdx.x ? g_cur1 : g_cur0;
    int n = blockIdx.x ? M1v : M0v;
    int t = threadIdx.x;
    int chunk = (n + 1023) >> 10;
    int a = t * chunk;
    int bq = min(a + chunk, n);
    int s = 0;
#pragma unroll 4
    for (int i = a; i < bq; i++) s += cnt[i];
    part[t] = s;
    __syncthreads();
    for (int d = 1; d < 1024; d <<= 1) {
        int v = (t >= d) ? part[t - d] : 0;
        __syncthreads();
        part[t] += v;
        __syncthreads();
    }
    int run = (t == 0) ? 0 : part[t - 1];
    for (int i = a; i < bq; i++) { off[i] = run; cur[i] = run; run += cnt[i]; }
    if (bq == n) off[n] = run;
}

__global__ void scatter_both_kernel(const int* __restrict__ src0,
                                    const int* __restrict__ dst0,
                                    const int* __restrict__ et0, int E0,
                                    const int* __restrict__ src1,
                                    const int* __restrict__ dst1,
                                    const int* __restrict__ et1, int E1) {
    int e = blockIdx.x * 256 + threadIdx.x;
    if (e < E0) {
        int p = atomicAdd(&g_cur0[dst0[e]], 1);
        g_eidx0[p] = (et0[e] << 24) | src0[e];
    } else {
        int e1 = e - E0;
        if (e1 < E1) {
            int p = atomicAdd(&g_cur1[dst1[e1]], 1);
            g_eidx1[p] = (et1[e1] << 24) | src1[e1];
        }
    }
}

// ---------------- gather: fp16 source rows (stride in halves) -------------
__global__ void __launch_bounds__(64, 21)
gather_h(const __half* __restrict__ x, int xstride,
         const int* __restrict__ eidx, const int* __restrict__ off,
         int* __restrict__ cnt, __half* __restrict__ A, int ndstp) {
    int d = blockIdx.x;
    int t = threadIdx.x;
    int c = t * 4;
    const __half* xb = x + c;
    int beg = off[d], end = off[d + 1];
    float4 a0 = make_float4(0.f, 0.f, 0.f, 0.f);
    float4 a1 = a0, a2 = a0, a3 = a0, a4 = a0;
#define ACCUM(pk_, v_)                                                         \
    {                                                                          \
        int r_ = (pk_) >> 24;                                                  \
        if (r_ == 0) { a0.x += (v_).x; a0.y += (v_).y; a0.z += (v_).z; a0.w += (v_).w; } \
        if (r_ == 1) { a1.x += (v_).x; a1.y += (v_).y; a1.z += (v_).z; a1.w += (v_).w; } \
        if (r_ == 2) { a2.x += (v_).x; a2.y += (v_).y; a2.z += (v_).z; a2.w += (v_).w; } \
        if (r_ == 3) { a3.x += (v_).x; a3.y += (v_).y; a3.z += (v_).z; a3.w += (v_).w; } \
        if (r_ == 4) { a4.x += (v_).x; a4.y += (v_).y; a4.z += (v_).z; a4.w += (v_).w; } \
    }
    int i = beg;
    for (; i + 1 < end; i += 2) {
        int pk0 = eidx[i];
        int pk1 = eidx[i + 1];
        float4 v0 = ld4h(xb + (size_t)(pk0 & 0xFFFFFF) * xstride);
        float4 v1 = ld4h(xb + (size_t)(pk1 & 0xFFFFFF) * xstride);
        ACCUM(pk0, v0);
        ACCUM(pk1, v1);
    }
    if (i < end) {
        int pk0 = eidx[i];
        float4 v0 = ld4h(xb + (size_t)(pk0 & 0xFFFFFF) * xstride);
        ACCUM(pk0, v0);
    }
    __half* ab = A + (size_t)d * KH + c;
    size_t step = (size_t)ndstp * KH;
    st4h(ab + 0 * step, a0);
    st4h(ab + 1 * step, a1);
    st4h(ab + 2 * step, a2);
    st4h(ab + 3 * step, a3);
    st4h(ab + 4 * step, a4);
    st4h(ab + 5 * step, ld4h(xb + (size_t)d * xstride));
    if (t == 0) cnt[d] = 0;
}

// ---------------- weight transpose (one-shot per launch, fp16) ----------
__global__ void transpose_weights(const float* W0, const float* Wl0,
                                  const float* W1, const float* Wl1,
                                  const float* Wm1) {
    __shared__ float t[32][33];
    int m = blockIdx.x;
    const float* src = (m < 5)   ? W0 + (size_t)m * H * H
                     : (m == 5)  ? Wl0
                     : (m < 11)  ? W1 + (size_t)(m - 6) * H * H
                     : (m == 11) ? Wl1 : Wm1;
    __half* dst = g_Wt + (size_t)m * 256 * KH;
    int bx = blockIdx.y * 32, by = blockIdx.z * 32;
    int x = threadIdx.x, y = threadIdx.y;
#pragma unroll
    for (int i = 0; i < 32; i += 8)
        t[y + i][x] = src[(size_t)(by + y + i) * H + bx + x];
    __syncthreads();
#pragma unroll
    for (int i = 0; i < 32; i += 8) {
        int n = bx + y + i;
        int k = by + x;
        dst[(size_t)n * KH + k] = __float2half_rn(t[x][y + i]);
    }
}

// ---------------- fp16 tensor GEMM (unchanged from R16) ------------------
struct TGArgs {
    const __half* A; long MP;
    const __half* W;
    int nseg; int M;
    const float* bias;
    __half* C;
    int layer;
};

#define CH_BYTES (32 * KHB)
#define B_BYTES  (128 * KHB)
#define SM_A0 1024
#define SM_A1 (1024 + CH_BYTES)
#define SM_B  (1024 + 2 * CH_BYTES)
#define SM_TOTAL (SM_B + B_BYTES)     // 102400

__device__ __forceinline__ void mma16(uint32_t ab, uint32_t bb,
                                      int wq, int rowl, int k16,
                                      float (*acc)[4][4]) {
#pragma unroll 4
    for (int kq = 0; kq < 16; kq++) {
        int kb = kq * 32 + k16;
        uint32_t a[2][4], b[2][4];
#pragma unroll
        for (int im = 0; im < 2; im++) {
            uint32_t ad = ab + (im * 16 + rowl) * KHB + kb;
            asm volatile(
                "ldmatrix.sync.aligned.m8n8.x4.shared.b16 {%0,%1,%2,%3}, [%4];"
                : "=r"(a[im][0]), "=r"(a[im][1]), "=r"(a[im][2]), "=r"(a[im][3])
                : "r"(ad));
        }
#pragma unroll
        for (int i2 = 0; i2 < 2; i2++) {
            uint32_t bd = bb + (wq * 32 + i2 * 16 + rowl) * KHB + kb;
            asm volatile(
                "ldmatrix.sync.aligned.m8n8.x4.shared.b16 {%0,%1,%2,%3}, [%4];"
                : "=r"(b[i2][0]), "=r"(b[i2][1]), "=r"(b[i2][2]), "=r"(b[i2][3])
                : "r"(bd));
        }
#pragma unroll
        for (int im = 0; im < 2; im++)
#pragma unroll
            for (int in_ = 0; in_ < 4; in_++) {
                int i2 = in_ >> 1, j = in_ & 1;
                asm volatile(
                    "mma.sync.aligned.m16n8k16.row.col.f32.f16.f16.f32 "
                    "{%0,%1,%2,%3}, {%4,%5,%6,%7}, {%8,%9}, {%0,%1,%2,%3};\n"
                    : "+f"(acc[im][in_][0]), "+f"(acc[im][in_][1]),
                      "+f"(acc[im][in_][2]), "+f"(acc[im][in_][3])
                    : "r"(a[im][0]), "r"(a[im][1]), "r"(a[im][2]), "r"(a[im][3]),
                      "r"(b[i2][j]), "r"(b[i2][2 + j]));
            }
    }
}

__global__ void __launch_bounds__(256, 2) gemm_bulk(TGArgs g) {
    extern __shared__ char sm[];
    uint32_t sb = smem_u32(sm);
    int tid = threadIdx.x, warp = tid >> 5, lane = tid & 31;
    int gidx = warp >> 2;
    int wq = warp & 3;
    int n0 = blockIdx.x * 128;
    int m0 = blockIdx.y * 128;
    int rowl = lane & 15;
    int k16 = (lane >> 4) * 16;
    int lr = lane >> 2, lc = lane & 3;
    uint32_t mbarA = sb + 8 * gidx;
    uint32_t mbarB = sb + 16;
    uint32_t bufA = sb + (gidx ? SM_A1 : SM_A0);
    uint32_t bb = sb + SM_B;
    int barid = 1 + gidx;
    bool leader = (tid == gidx * 128);
    int nst = g.nseg;

    if (tid == 0) {
        MBAR_INIT(sb + 0, 1);
        MBAR_INIT(sb + 8, 1);
        MBAR_INIT(sb + 16, 1);
    }
    __syncthreads();

    float acc[2][2][4][4];
#pragma unroll
    for (int ci = 0; ci < 2; ci++)
#pragma unroll
        for (int im = 0; im < 2; im++)
#pragma unroll
            for (int j = 0; j < 4; j++)
#pragma unroll
                for (int k = 0; k < 4; k++) acc[ci][im][j][k] = 0.f;

    {
        const __half* asrc0 = g.A + (size_t)m0 * KH;
        if (tid == 0) {
            MBAR_EXPECT(mbarB, B_BYTES);
            BULK_G2S(sb + SM_B, g.W + (size_t)n0 * KH, B_BYTES, mbarB);
        }
        if (leader) {
            MBAR_EXPECT(mbarA, CH_BYTES);
            BULK_G2S(bufA, asrc0 + (size_t)gidx * 32 * KH, CH_BYTES, mbarA);
        }
    }

    int pA = 0, pB = 0;
    for (int s = 0; s < nst; s++) {
        const __half* asrc = g.A + ((size_t)s * g.MP + m0) * KH;
        const __half* nasrc = asrc + (size_t)g.MP * KH;
        bool more = (s + 1 < nst);

        mbar_wait(mbarA, pA); pA ^= 1;
        mbar_wait(mbarB, pB);
        mma16(bufA, bb, wq, rowl, k16, acc[0]);
        NAMED_BAR(barid);
        if (leader) {
            MBAR_EXPECT(mbarA, CH_BYTES);
            BULK_G2S(bufA, asrc + (size_t)(2 + gidx) * 32 * KH, CH_BYTES, mbarA);
        }
        mbar_wait(mbarA, pA); pA ^= 1;
        mma16(bufA, bb, wq, rowl, k16, acc[1]);
        NAMED_BAR(barid);
        if (leader && more) {
            MBAR_EXPECT(mbarA, CH_BYTES);
            BULK_G2S(bufA, nasrc + (size_t)gidx * 32 * KH, CH_BYTES, mbarA);
        }
        __syncthreads();
        if (tid == 0 && more) {
            MBAR_EXPECT(mbarB, B_BYTES);
            BULK_G2S(sb + SM_B, g.W + ((size_t)(s + 1) * 256 + n0) * KH,
                     B_BYTES, mbarB);
        }
        pB ^= 1;
    }

    float* ss = (float*)(sm + SM_A0);
    ss[tid] = 0.f;
    __syncthreads();
#pragma unroll
    for (int in_ = 0; in_ < 4; in_++) {
        int lcol = wq * 32 + in_ * 8 + lc * 2;
        int col = n0 + lcol;
        float bia0 = g.bias[col];
        float bia1 = g.bias[col + 1];
        float s0 = 0.f, q0 = 0.f, s1 = 0.f, q1 = 0.f;
        __half* cp = g.C + col;
#pragma unroll
        for (int ci = 0; ci < 2; ci++) {
#pragma unroll
            for (int im = 0; im < 2; im++) {
                int mrow = m0 + (ci * 2 + gidx) * 32 + im * 16 + lr;
                if (mrow < g.M) {
                    float v0 = acc[ci][im][in_][0] + bia0;
                    float v1 = acc[ci][im][in_][1] + bia1;
                    *(__half2*)(cp + (size_t)mrow * KH) = __floats2half2_rn(v0, v1);
                    s0 += v0; q0 += v0 * v0; s1 += v1; q1 += v1 * v1;
                }
                if (mrow + 8 < g.M) {
                    float v2 = acc[ci][im][in_][2] + bia0;
                    float v3 = acc[ci][im][in_][3] + bia1;
                    *(__half2*)(cp + (size_t)(mrow + 8) * KH) = __floats2half2_rn(v2, v3);
                    s0 += v2; q0 += v2 * v2; s1 += v3; q1 += v3 * v3;
                }
            }
        }
#pragma unroll
        for (int mk = 4; mk <= 16; mk <<= 1) {
            s0 += __shfl_xor_sync(0xffffffffu, s0, mk);
            q0 += __shfl_xor_sync(0xffffffffu, q0, mk);
            s1 += __shfl_xor_sync(0xffffffffu, s1, mk);
            q1 += __shfl_xor_sync(0xffffffffu, q1, mk);
        }
        if (lr == 0) {
            atomicAdd(&ss[lcol], s0);
            atomicAdd(&ss[128 + lcol], q0);
            atomicAdd(&ss[lcol + 1], s1);
            atomicAdd(&ss[128 + lcol + 1], q1);
        }
    }
    __syncthreads();
    if (tid < 128) {
        atomicAdd(&g_sum[g.layer][n0 + tid], ss[tid]);
        atomicAdd(&g_sumsq[g.layer][n0 + tid], ss[128 + tid]);
    }
}

// ---------------- SIMT GEMM (final 256x153; A fp16, W fp32) ---------------
struct GemmArgs {
    const __half* A;
    const float* W;
    int M, N;
    const float* bias;
    float* C;
};

__global__ void gemm_kernel(GemmArgs g) {
    __shared__ float As[16][65];
    __shared__ float Bs[16][64];

    int tid = threadIdx.x;
    int m0 = blockIdx.x * 64;
    int n0 = blockIdx.y * 64;
    int tm = tid >> 4;
    int tn = tid & 15;

    int lrow = tid >> 2;
    int lk4 = (tid & 3) << 2;
    int lkb = tid >> 4;
    int ln4 = (tid & 15) << 2;

    float acc[4][4];
#pragma unroll
    for (int i = 0; i < 4; i++)
#pragma unroll
        for (int j = 0; j < 4; j++) acc[i][j] = 0.f;

    for (int k0 = 0; k0 < H; k0 += 16) {
        float4 av = make_float4(0.f, 0.f, 0.f, 0.f);
        if (m0 + lrow < g.M)
            av = ld4h(g.A + (size_t)(m0 + lrow) * KH + k0 + lk4);
        As[lk4 + 0][lrow] = av.x;
        As[lk4 + 1][lrow] = av.y;
        As[lk4 + 2][lrow] = av.z;
        As[lk4 + 3][lrow] = av.w;
        const float* wp = g.W + (size_t)(k0 + lkb) * g.N + n0 + ln4;
        float4 bv;
        bv.x = (n0 + ln4 + 0 < g.N) ? wp[0] : 0.f;
        bv.y = (n0 + ln4 + 1 < g.N) ? wp[1] : 0.f;
        bv.z = (n0 + ln4 + 2 < g.N) ? wp[2] : 0.f;
        bv.w = (n0 + ln4 + 3 < g.N) ? wp[3] : 0.f;
        *(float4*)&Bs[lkb][ln4] = bv;
        __syncthreads();
#pragma unroll
        for (int kk = 0; kk < 16; kk++) {
            float a0 = As[kk][tm * 4 + 0];
            float a1 = As[kk][tm * 4 + 1];
            float a2 = As[kk][tm * 4 + 2];
            float a3 = As[kk][tm * 4 + 3];
            float4 b = *(const float4*)&Bs[kk][tn * 4];
            acc[0][0] += a0 * b.x; acc[0][1] += a0 * b.y; acc[0][2] += a0 * b.z; acc[0][3] += a0 * b.w;
            acc[1][0] += a1 * b.x; acc[1][1] += a1 * b.y; acc[1][2] += a1 * b.z; acc[1][3] += a1 * b.w;
            acc[2][0] += a2 * b.x; acc[2][1] += a2 * b.y; acc[2][2] += a2 * b.z; acc[2][3] += a2 * b.w;
            acc[3][0] += a3 * b.x; acc[3][1] += a3 * b.y; acc[3][2] += a3 * b.z; acc[3][3] += a3 * b.w;
        }
        __syncthreads();
    }

#pragma unroll
    for (int i = 0; i < 4; i++) {
        int m = m0 + tm * 4 + i;
        if (m >= g.M) continue;
#pragma unroll
        for (int j = 0; j < 4; j++) {
            int n = n0 + tn * 4 + j;
            if (n < g.N) g.C[(size_t)m * g.N + n] = acc[i][j] + g.bias[n];
        }
    }
}

// ---------------- BN kernels ----------------
__global__ void zero_stats3_kernel() {
    int t = threadIdx.x;
#pragma unroll
    for (int l = 0; l < 3; l++) {
        g_sum[l][t] = 0.f;
        g_sumsq[l][t] = 0.f;
    }
}

__global__ void bn_apply_kernel(__half* __restrict__ h, int M,
                                const float* __restrict__ gamma,
                                const float* __restrict__ beta,
                                float invM, int layer, int act) {
    int col = threadIdx.x;
    float mean = g_sum[layer][col] * invM;
    float var = g_sumsq[layer][col] * invM - mean * mean;
    float sc = gamma[col] * rsqrtf(var + 1e-5f);
    float sh = beta[col] - mean * sc;
    __half* hp = h + col;
    int r0 = blockIdx.x * 8;
    int rend = min(r0 + 8, M);
#pragma unroll 8
    for (int r = r0; r < rend; r++) {
        float v = __half2float(hp[(size_t)r * KH]) * sc + sh;
        if (act == 0)
            v = (v > 0.f) ? v : expm1f(v);
        else
            v = (v > 0.f) ? v : 0.f;
        hp[(size_t)r * KH] = __float2half_rn(v);
    }
}

// ---------------- host orchestration ----------------
static inline int cdiv(long a, long b) { return (int)((a + b - 1) / b); }

extern "C" void kernel_launch(void* const* d_in, const int* in_sizes, int n_in,
                              void* d_out, int out_size) {
    const float* x   = (const float*)d_in[0];
    const int* src0  = (const int*)d_in[1];
    const int* dst0  = (const int*)d_in[2];
    const int* et0   = (const int*)d_in[3];
    const int* src1  = (const int*)d_in[4];
    const int* dst1  = (const int*)d_in[5];
    const int* et1   = (const int*)d_in[6];
    const float* W0  = (const float*)d_in[9];
    const float* Wl0 = (const float*)d_in[10];
    const float* b0  = (const float*)d_in[11];
    const float* g0  = (const float*)d_in[12];
    const float* be0 = (const float*)d_in[13];
    const float* W1  = (const float*)d_in[14];
    const float* Wl1 = (const float*)d_in[15];
    const float* b1  = (const float*)d_in[16];
    const float* g1  = (const float*)d_in[17];
    const float* be1 = (const float*)d_in[18];
    const float* Wm1 = (const float*)d_in[19];
    const float* bm1 = (const float*)d_in[20];
    const float* gm  = (const float*)d_in[21];
    const float* bem = (const float*)d_in[22];
    const float* Wm2 = (const float*)d_in[23];
    const float* bm2 = (const float*)d_in[24];
    float* out = (float*)d_out;

    const int E0 = in_sizes[1];
    const int E1 = in_sizes[4];
    const int COUT = 153;
    const int M1 = out_size / COUT;   // 10000
    const int M0 = M0_CONST;          // 50000

    __half *A0, *A1, *H0, *H1, *Mh, *Wt, *X16;
    int *cnt0, *off0, *cnt1, *off1, *eidx0, *eidx1;
    cudaGetSymbolAddress((void**)&A0, g_A0);
    cudaGetSymbolAddress((void**)&A1, g_A1);
    cudaGetSymbolAddress((void**)&H0, g_H0);
    cudaGetSymbolAddress((void**)&H1, g_H1);
    cudaGetSymbolAddress((void**)&Mh, g_Mh);
    cudaGetSymbolAddress((void**)&Wt, g_Wt);
    cudaGetSymbolAddress((void**)&X16, g_X16);
    cudaGetSymbolAddress((void**)&cnt0, g_cnt0);
    cudaGetSymbolAddress((void**)&off0, g_off0);
    cudaGetSymbolAddress((void**)&cnt1, g_cnt1);
    cudaGetSymbolAddress((void**)&off1, g_off1);
    cudaGetSymbolAddress((void**)&eidx0, g_eidx0);
    cudaGetSymbolAddress((void**)&eidx1, g_eidx1);

    cudaFuncSetAttribute(gemm_bulk,
                         cudaFuncAttributeMaxDynamicSharedMemorySize, SM_TOTAL);

    // 0: convert x -> fp16 (L2-resident) + both histograms
    prep_kernel<<<NCONV_BLK + cdiv(E0 + E1, 256), 256>>>(x, dst0, E0, dst1, E1);
    // 1: scan both layers
    scan_both_kernel<<<2, 1024>>>(M0, M1);
    // 2: scatter both layers
    scatter_both_kernel<<<cdiv(E0 + E1, 256), 256>>>(src0, dst0, et0, E0,
                                                     src1, dst1, et1, E1);
    // 3: layer-0 gather (profiled slot)
    gather_h<<<M0, 64>>>(X16, H, eidx0, off0, cnt0, A0, M0P);
    transpose_weights<<<dim3(13, 8, 8), dim3(32, 8)>>>(W0, Wl0, W1, Wl1, Wm1);
    zero_stats3_kernel<<<1, H>>>();

    TGArgs ga;
    ga.A = A0;  ga.MP = M0P;
    ga.W = Wt;  ga.nseg = NSEG;  ga.M = M0;  ga.bias = b0;
    ga.C = H0;  ga.layer = 0;
    gemm_bulk<<<dim3(2, cdiv(M0, 128)), 256, SM_TOTAL>>>(ga);

    bn_apply_kernel<<<cdiv(M0, 8), H>>>(H0, M0, g0, be0, 1.0f / M0, 0, 0);

    // ---- layer 1 ----
    gather_h<<<M1, 64>>>(H0, KH, eidx1, off1, cnt1, A1, M1P);

    ga.A = A1;  ga.MP = M1P;
    ga.W = Wt + (size_t)6 * 256 * KH;
    ga.nseg = NSEG;  ga.M = M1;  ga.bias = b1;
    ga.C = H1;  ga.layer = 1;
    gemm_bulk<<<dim3(2, cdiv(M1, 128)), 256, SM_TOTAL>>>(ga);

    bn_apply_kernel<<<cdiv(M1, 8), H>>>(H1, M1, g1, be1, 1.0f / M1, 1, 0);

    // ---- MLP head ----
    ga.A = H1;  ga.MP = M1P;
    ga.W = Wt + (size_t)12 * 256 * KH;
    ga.nseg = 1;  ga.M = M1;  ga.bias = bm1;
    ga.C = Mh;  ga.layer = 2;
    gemm_bulk<<<dim3(2, cdiv(M1, 128)), 256, SM_TOTAL>>>(ga);

    bn_apply_kernel<<<cdiv(M1, 8), H>>>(Mh, M1, gm, bem, 1.0f / M1, 2, 1);

    GemmArgs gf;
    gf.A = Mh;  gf.W = Wm2;
    gf.M = M1;  gf.N = COUT;  gf.bias = bm2;  gf.C = out;
    gemm_kernel<<<dim3(cdiv(M1, 64), cdiv(COUT, 64)), 256>>>(gf);
}